// round 4
// baseline (speedup 1.0000x reference)
#include <cuda_runtime.h>
#include <cuda_bf16.h>
#include <math.h>

#define N_ 32768
#define E_ 262144
#define C_ 128
#define H_ 8
#define R_ 8
#define T_ 8
#define CAPR 36864   // per-relation edge bucket capacity (expected 32768 +/- 165)
#define CAPN 4608    // per-type node bucket capacity (expected 4096 +/- 62)
#define KSTEP 8

// ---------------- f32x2 helpers ----------------
__device__ __forceinline__ unsigned long long dup2(float v) {
    unsigned long long r;
    asm("mov.b64 %0, {%1, %1};" : "=l"(r) : "f"(v));
    return r;
}
__device__ __forceinline__ void fma2(unsigned long long& acc, unsigned long long a,
                                     unsigned long long b) {
    asm("fma.rn.f32x2 %0, %1, %2, %0;" : "+l"(acc) : "l"(a), "l"(b));
}
__device__ __forceinline__ void unpack2(unsigned long long p, float& lo, float& hi) {
    asm("mov.b64 {%0, %1}, %2;" : "=f"(lo), "=f"(hi) : "l"(p));
}

// ---------------- scratch (device globals; no runtime alloc) ----------------
__device__ float d_Wall[R_][C_ * 384];   // fused weights: cols [0,128)=kt, [128,256)=vt, [256,384)=q
__device__ float d_ball[R_][384];        // fused biases
__device__ int   d_cursor8[R_];          // per-relation cursors (= counts after setup)
__device__ int   d_ssrc[R_ * CAPR];      // padded per-relation buckets
__device__ int   d_sdst[R_ * CAPR];

__device__ float d_att[E_ * H_];         // compact slot indexed
__device__ float d_vt[E_ * C_];          // compact slot indexed

__device__ int   d_cnt[N_];
__device__ int   d_rowPtr[N_ + 1];
__device__ int   d_cursor[N_];
__device__ int   d_bydst[E_];            // compact slots grouped by dst
__device__ float d_x0[N_ * C_];

__device__ int   d_cursorN8[T_];
__device__ int   d_snid[T_ * CAPN];

// ---------------- 0: zero init ----------------
__global__ void k_zero() {
    int i = blockIdx.x * blockDim.x + threadIdx.x;
    if (i < N_) { d_cnt[i] = 0; d_cursor[i] = 0; }
    if (i < R_) { d_cursor8[i] = 0; d_cursorN8[i] = 0; }
}

// ---------------- 1: fused setup: weight-fuse + edge scatter + node scatter ----------------
__global__ void __launch_bounds__(384) k_setup(
        const float* __restrict__ Wk, const float* __restrict__ bk,
        const float* __restrict__ Wq, const float* __restrict__ bq,
        const float* __restrict__ Wv, const float* __restrict__ bv,
        const float* __restrict__ pri, const float* __restrict__ Aatt,
        const float* __restrict__ Amsg,
        const int* __restrict__ ei, const int* __restrict__ ea,
        const int* __restrict__ tid_) {
    int b = blockIdx.x;
    int j = threadIdx.x;
    if (b < 64) {
        int r = b & 7, kc = b >> 3;
        int k0 = kc * 16;
        float* Wdst = d_Wall[r];
        if (j < 256) {
            bool isK = j < 128;
            int c = j & 127;
            int h = c >> 4, d2 = c & 15;
            const float* M  = (isK ? Aatt : Amsg) + ((r * 8 + h) * 256) + d2; // stride 16 over d
            const float* Ws = (isK ? Wk : Wv) + r * 16384 + h * 16;
            for (int k = k0; k < k0 + 16; k++) {
                float s = 0.f;
                #pragma unroll
                for (int d = 0; d < 16; d++) s = fmaf(Ws[k * 128 + d], M[d * 16], s);
                Wdst[k * 384 + j] = s;
            }
            if (kc == 0) {
                const float* bs = (isK ? bk : bv) + r * 128 + h * 16;
                float s = 0.f;
                #pragma unroll
                for (int d = 0; d < 16; d++) s = fmaf(bs[d], M[d * 16], s);
                d_ball[r][j] = s;
            }
        } else {
            int c = j - 256;
            int h = c >> 4;
            float sc = pri[r * 8 + h] * 0.25f;
            for (int k = k0; k < k0 + 16; k++)
                Wdst[k * 384 + j] = Wq[r * 16384 + k * 128 + c] * sc;
            if (kc == 0) d_ball[r][j] = bq[r * 128 + c] * sc;
        }
    } else if (b < 747) {
        int e = (b - 64) * 384 + j;
        if (e < E_) {
            int r = ea[e];
            int dst = ei[E_ + e];
            int pos = atomicAdd(&d_cursor8[r], 1);
            if (pos < CAPR) {
                d_ssrc[r * CAPR + pos] = ei[e];
                d_sdst[r * CAPR + pos] = dst;
            }
            atomicAdd(&d_cnt[dst], 1);
        }
    } else {
        int n = (b - 747) * 384 + j;
        if (n < N_) {
            int pos = atomicAdd(&d_cursorN8[tid_[n]], 1);
            if (pos < CAPN) d_snid[tid_[n] * CAPN + pos] = n;
        }
    }
}

// ---------------- 2: prefix scan of d_cnt -> d_rowPtr (single block) ----------------
__global__ void k_scan() {
    __shared__ int sums[1024];
    int tid = threadIdx.x;
    int base = tid * 32;
    int tot = 0;
    for (int i = 0; i < 32; i++) tot += d_cnt[base + i];
    sums[tid] = tot;
    __syncthreads();
    for (int off = 1; off < 1024; off <<= 1) {
        int v = (tid >= off) ? sums[tid - off] : 0;
        __syncthreads();
        sums[tid] += v;
        __syncthreads();
    }
    int run = sums[tid] - tot;   // exclusive prefix of this chunk
    for (int i = 0; i < 32; i++) {
        d_rowPtr[base + i] = run;
        run += d_cnt[base + i];
    }
    if (tid == 1023) d_rowPtr[N_] = run;
}

// ---------------- 3: edge GEMM (PROFILED): software-pipelined, double-buffered ----------------
// 64-edge tile, single relation. kt|vt from x[src], q from x[dst].
// 16 pipeline iterations of KSTEP=8 k-slices; LDG for iter i+1 issued before
// compute of iter i; STS into alternate buffer after compute; 1 barrier/iter.
__global__ void __launch_bounds__(256, 1) k_edge_gemm(const float* __restrict__ x) {
    int r = blockIdx.y;
    int i = blockIdx.x;

    __shared__ int s_cnt, s_gbase;
    if (threadIdx.x == 0) {
        int cnt = min(d_cursor8[r], CAPR);
        int gb = 0;
        #pragma unroll
        for (int q = 0; q < R_; q++) {
            int c = min(d_cursor8[q], CAPR);
            if (q < r) gb += c;
        }
        s_cnt = cnt;
        s_gbase = gb;
    }
    __syncthreads();
    int cnt = s_cnt;
    if (i * 64 >= cnt) return;
    int count = min(64, cnt - i * 64);
    int gstart = s_gbase + i * 64;          // compact output base for this tile
    int pstart = r * CAPR + i * 64;         // padded input base

    const float* __restrict__ W = d_Wall[r];

    __shared__ __align__(16) float sA[2][2][KSTEP][68];  // [buf][side][kk][row]
    __shared__ __align__(16) float sB[2][KSTEP][388];    // [buf][kk][col]

    int tid = threadIdx.x;
    int ty = tid >> 4, tx = tid & 15;
    int rowL = tid >> 2, q4 = tid & 3;
    int side = q4 >> 1, half = q4 & 1;      // gather role: side 0=src,1=dst; half=which float4 of 8-k slice

    int src = 0, dst = 0;
    if (rowL < count) { src = d_ssrc[pstart + rowL]; dst = d_sdst[pstart + rowL]; }
    const float* xg = x + (size_t)(side == 0 ? src : dst) * C_;

    // W-load decomposition: idx = tid + 256*a (a<3) -> kk = idx/96, c4 = idx%96
    int wkk[3], wc4[3];
    #pragma unroll
    for (int a = 0; a < 3; a++) {
        int idx = tid + 256 * a;
        wkk[a] = idx / 96;
        wc4[a] = idx % 96;
    }

    unsigned long long acc2[4][12];
    #pragma unroll
    for (int a = 0; a < 4; a++)
        #pragma unroll
        for (int p = 0; p < 12; p++) acc2[a][p] = 0ull;

    // ---- prologue: load slice 0 ----
    float4 av = *(const float4*)(xg + half * 4);
    float4 wv0 = *(const float4*)(W + wkk[0] * 384 + wc4[0] * 4);
    float4 wv1 = *(const float4*)(W + wkk[1] * 384 + wc4[1] * 4);
    float4 wv2 = *(const float4*)(W + wkk[2] * 384 + wc4[2] * 4);
    {
        int kb = half * 4;
        sA[0][side][kb + 0][rowL] = av.x; sA[0][side][kb + 1][rowL] = av.y;
        sA[0][side][kb + 2][rowL] = av.z; sA[0][side][kb + 3][rowL] = av.w;
        *(float4*)&sB[0][wkk[0]][wc4[0] * 4] = wv0;
        *(float4*)&sB[0][wkk[1]][wc4[1] * 4] = wv1;
        *(float4*)&sB[0][wkk[2]][wc4[2] * 4] = wv2;
    }
    __syncthreads();

    #pragma unroll
    for (int it = 0; it < 16; it++) {
        int cur = it & 1;
        // prefetch slice it+1
        if (it < 15) {
            int kbase = (it + 1) * KSTEP;
            av  = *(const float4*)(xg + kbase + half * 4);
            wv0 = *(const float4*)(W + (kbase + wkk[0]) * 384 + wc4[0] * 4);
            wv1 = *(const float4*)(W + (kbase + wkk[1]) * 384 + wc4[1] * 4);
            wv2 = *(const float4*)(W + (kbase + wkk[2]) * 384 + wc4[2] * 4);
        }
        // compute on buf cur
        #pragma unroll
        for (int kk = 0; kk < KSTEP; kk++) {
            float4 as4 = *(const float4*)&sA[cur][0][kk][ty * 4];
            float4 ad4 = *(const float4*)&sA[cur][1][kk][ty * 4];
            unsigned long long a0p[4], a1p[4];
            a0p[0] = dup2(as4.x); a0p[1] = dup2(as4.y);
            a0p[2] = dup2(as4.z); a0p[3] = dup2(as4.w);
            a1p[0] = dup2(ad4.x); a1p[1] = dup2(ad4.y);
            a1p[2] = dup2(ad4.z); a1p[3] = dup2(ad4.w);
            #pragma unroll
            for (int g = 0; g < 6; g++) {
                ulonglong2 b2 = *(const ulonglong2*)&sB[cur][kk][tx * 4 + 64 * g];
                #pragma unroll
                for (int a = 0; a < 4; a++) {
                    unsigned long long avp = (g < 4) ? a0p[a] : a1p[a];
                    fma2(acc2[a][g * 2 + 0], avp, b2.x);
                    fma2(acc2[a][g * 2 + 1], avp, b2.y);
                }
            }
        }
        // store prefetched slice into alternate buffer
        if (it < 15) {
            int nxt = cur ^ 1;
            int kb = half * 4;
            sA[nxt][side][kb + 0][rowL] = av.x; sA[nxt][side][kb + 1][rowL] = av.y;
            sA[nxt][side][kb + 2][rowL] = av.z; sA[nxt][side][kb + 3][rowL] = av.w;
            *(float4*)&sB[nxt][wkk[0]][wc4[0] * 4] = wv0;
            *(float4*)&sB[nxt][wkk[1]][wc4[1] * 4] = wv1;
            *(float4*)&sB[nxt][wkk[2]][wc4[2] * 4] = wv2;
        }
        __syncthreads();
    }

    const float* __restrict__ bb = d_ball[r];

    float acc[4][24];
    #pragma unroll
    for (int a = 0; a < 4; a++)
        #pragma unroll
        for (int p = 0; p < 12; p++)
            unpack2(acc2[a][p], acc[a][2 * p], acc[a][2 * p + 1]);

    // att: per head, dot(kt, q); 16 dims split across the 4-thread tx quad
    #pragma unroll
    for (int a = 0; a < 4; a++) {
        int row = ty * 4 + a;
        float p0 = 0.f, p1 = 0.f;
        #pragma unroll
        for (int l = 0; l < 4; l++) {
            int c0 = 4 * tx + l;
            float kt0 = acc[a][0 * 4 + l] + bb[c0];
            float q0  = acc[a][4 * 4 + l] + bb[256 + c0];
            p0 = fmaf(kt0, q0, p0);
            int c1 = 64 + 4 * tx + l;
            float kt1 = acc[a][1 * 4 + l] + bb[c1];
            float q1  = acc[a][5 * 4 + l] + bb[256 + c1];
            p1 = fmaf(kt1, q1, p1);
        }
        p0 += __shfl_xor_sync(0xffffffffu, p0, 1);
        p0 += __shfl_xor_sync(0xffffffffu, p0, 2);
        p1 += __shfl_xor_sync(0xffffffffu, p1, 1);
        p1 += __shfl_xor_sync(0xffffffffu, p1, 2);
        if (row < count && (tx & 3) == 0) {
            int slot = gstart + row;
            int h = tx >> 2;
            d_att[slot * 8 + h] = p0;
            d_att[slot * 8 + 4 + h] = p1;
        }
    }
    // vt writes (compact, coalesced)
    #pragma unroll
    for (int a = 0; a < 4; a++) {
        int row = ty * 4 + a;
        if (row < count) {
            int slot = gstart + row;
            #pragma unroll
            for (int g = 2; g < 4; g++) {
                int cb = 64 * (g - 2) + 4 * tx;
                float4 o;
                o.x = acc[a][g * 4 + 0] + bb[128 + cb + 0];
                o.y = acc[a][g * 4 + 1] + bb[128 + cb + 1];
                o.z = acc[a][g * 4 + 2] + bb[128 + cb + 2];
                o.w = acc[a][g * 4 + 3] + bb[128 + cb + 3];
                *(float4*)&d_vt[(size_t)slot * C_ + cb] = o;
            }
        }
    }
}

// ---------------- 4: scatter compact slots by dst ----------------
__global__ void k_scatterD() {
    __shared__ int sb[R_ + 1];
    if (threadIdx.x < R_) sb[threadIdx.x + 1] = min(d_cursor8[threadIdx.x], CAPR);
    if (threadIdx.x == 0) sb[0] = 0;
    __syncthreads();
    if (threadIdx.x == 0) {
        #pragma unroll
        for (int q = 1; q <= R_; q++) sb[q] += sb[q - 1];
    }
    __syncthreads();
    int c = blockIdx.x * blockDim.x + threadIdx.x;
    if (c >= sb[R_]) return;
    int r = 0;
    #pragma unroll
    for (int q = 1; q < R_; q++) r += (c >= sb[q]);
    int padded = r * CAPR + (c - sb[r]);
    int dst = d_sdst[padded];
    int pos = d_rowPtr[dst] + atomicAdd(&d_cursor[dst], 1);
    d_bydst[pos] = c;
}

// ---------------- 5: per-node softmax + weighted mean (warp per node) ----------------
__global__ void k_aggregate() {
    int warp = threadIdx.x >> 5;
    int lane = threadIdx.x & 31;
    int n = blockIdx.x * (blockDim.x >> 5) + warp;
    if (n >= N_) return;
    int s = d_rowPtr[n], eEnd = d_rowPtr[n + 1];
    int deg = eEnd - s;
    if (deg == 0) {
        #pragma unroll
        for (int j = 0; j < 4; j++) d_x0[n * C_ + lane + 32 * j] = 0.f;
        return;
    }
    int slot = lane >> 3, h = lane & 7;
    float m = -1e30f;
    for (int b = s; b < eEnd; b += 4) {
        int idx = b + slot;
        if (idx < eEnd) {
            int e = d_bydst[idx];
            m = fmaxf(m, d_att[e * 8 + h]);
        }
    }
    m = fmaxf(m, __shfl_xor_sync(0xffffffffu, m, 8));
    m = fmaxf(m, __shfl_xor_sync(0xffffffffu, m, 16));
    float den = 0.f;
    for (int b = s; b < eEnd; b += 4) {
        int idx = b + slot;
        if (idx < eEnd) {
            int e = d_bydst[idx];
            den += expf(d_att[e * 8 + h] - m);
        }
    }
    den += __shfl_xor_sync(0xffffffffu, den, 8);
    den += __shfl_xor_sync(0xffffffffu, den, 16);

    int hb = lane >> 4; // channel c = lane + 32j -> head hb + 2j
    float mj[4], rj[4];
    #pragma unroll
    for (int j = 0; j < 4; j++) {
        int hh = hb + 2 * j;
        mj[j] = __shfl_sync(0xffffffffu, m, hh);
        rj[j] = 1.f / __shfl_sync(0xffffffffu, den, hh);
    }
    float acc[4] = {0.f, 0.f, 0.f, 0.f};
    for (int idx = s; idx < eEnd; idx++) {
        int e = d_bydst[idx];
        const float* ar = &d_att[e * 8];
        const float* vr = &d_vt[(size_t)e * C_];
        #pragma unroll
        for (int j = 0; j < 4; j++) {
            float w = expf(ar[hb + 2 * j] - mj[j]) * rj[j];
            acc[j] = fmaf(w, vr[lane + 32 * j], acc[j]);
        }
    }
    float inv = 1.f / (float)deg;
    #pragma unroll
    for (int j = 0; j < 4; j++) d_x0[n * C_ + lane + 32 * j] = acc[j] * inv;
}

// ---------------- 6: output: typed GEMM + gated residual + LayerNorm ----------------
__global__ void __launch_bounds__(256) k_out(const float* __restrict__ x,
                                             const float* __restrict__ Wa,
                                             const float* __restrict__ ba,
                                             const float* __restrict__ skipv,
                                             const float* __restrict__ gamma,
                                             const float* __restrict__ beta,
                                             float* __restrict__ out) {
    int t = blockIdx.y;
    int jt = blockIdx.x;
    int cntT = min(d_cursorN8[t], CAPN);
    if (jt * 64 >= cntT) return;
    int count = min(64, cntT - jt * 64);
    int start = t * CAPN + jt * 64;

    __shared__ __align__(16) float sA[16][68];
    __shared__ __align__(16) float sB[16][132];

    int tid = threadIdx.x;
    int ty = tid >> 4, tx = tid & 15;
    int rowL = tid >> 2, q4 = tid & 3;

    int nidL = (rowL < count) ? d_snid[start + rowL] : 0;
    const float* a_src = d_x0 + (size_t)nidL * C_;
    const float* W = Wa + t * 16384;

    unsigned long long acc2[4][4];
    #pragma unroll
    for (int a = 0; a < 4; a++)
        #pragma unroll
        for (int p = 0; p < 4; p++) acc2[a][p] = 0ull;

    for (int k0 = 0; k0 < 128; k0 += 16) {
        __syncthreads();
        float4 v = *(const float4*)(a_src + k0 + q4 * 4);
        sA[q4 * 4 + 0][rowL] = v.x; sA[q4 * 4 + 1][rowL] = v.y;
        sA[q4 * 4 + 2][rowL] = v.z; sA[q4 * 4 + 3][rowL] = v.w;
        #pragma unroll
        for (int a = 0; a < 2; a++) {
            int idx = tid + 256 * a;
            int kk = idx >> 5, c4 = idx & 31;
            *(float4*)&sB[kk][c4 * 4] = *(const float4*)(W + (k0 + kk) * 128 + c4 * 4);
        }
        __syncthreads();
        #pragma unroll
        for (int kk = 0; kk < 16; kk++) {
            float4 a4 = *(const float4*)&sA[kk][ty * 4];
            unsigned long long ap[4];
            ap[0] = dup2(a4.x); ap[1] = dup2(a4.y);
            ap[2] = dup2(a4.z); ap[3] = dup2(a4.w);
            #pragma unroll
            for (int g = 0; g < 2; g++) {
                ulonglong2 b2 = *(const ulonglong2*)&sB[kk][tx * 4 + 64 * g];
                #pragma unroll
                for (int a = 0; a < 4; a++) {
                    fma2(acc2[a][g * 2 + 0], ap[a], b2.x);
                    fma2(acc2[a][g * 2 + 1], ap[a], b2.y);
                }
            }
        }
    }

    float alpha = 1.f / (1.f + expf(-skipv[t]));
    float onema = 1.f - alpha;

    #pragma unroll
    for (int a = 0; a < 4; a++) {
        int row = ty * 4 + a;
        bool valid = row < count;
        int nid = valid ? d_snid[start + row] : 0;
        float accf[8];
        #pragma unroll
        for (int p = 0; p < 4; p++) unpack2(acc2[a][p], accf[2 * p], accf[2 * p + 1]);
        float v[8];
        float s1 = 0.f, s2 = 0.f;
        #pragma unroll
        for (int g = 0; g < 2; g++) {
            #pragma unroll
            for (int l = 0; l < 4; l++) {
                int c = 64 * g + 4 * tx + l;
                float val = accf[g * 4 + l] + ba[t * 128 + c];
                val = alpha * val + onema * x[(size_t)nid * C_ + c];
                v[g * 4 + l] = val;
                s1 += val;
                s2 = fmaf(val, val, s2);
            }
        }
        #pragma unroll
        for (int off = 1; off <= 8; off <<= 1) {
            s1 += __shfl_xor_sync(0xffffffffu, s1, off);
            s2 += __shfl_xor_sync(0xffffffffu, s2, off);
        }
        float mu = s1 * (1.f / 128.f);
        float var = s2 * (1.f / 128.f) - mu * mu;
        float rstd = rsqrtf(var + 1e-5f);
        if (valid) {
            #pragma unroll
            for (int g = 0; g < 2; g++) {
                int cb = 64 * g + 4 * tx;
                float4 o;
                o.x = (v[g * 4 + 0] - mu) * rstd * gamma[t * 128 + cb + 0] + beta[t * 128 + cb + 0];
                o.y = (v[g * 4 + 1] - mu) * rstd * gamma[t * 128 + cb + 1] + beta[t * 128 + cb + 1];
                o.z = (v[g * 4 + 2] - mu) * rstd * gamma[t * 128 + cb + 2] + beta[t * 128 + cb + 2];
                o.w = (v[g * 4 + 3] - mu) * rstd * gamma[t * 128 + cb + 3] + beta[t * 128 + cb + 3];
                *(float4*)&out[(size_t)nid * C_ + cb] = o;
            }
        }
    }
}

// ---------------- launch ----------------
extern "C" void kernel_launch(void* const* d_in, const int* in_sizes, int n_in,
                              void* d_out, int out_size) {
    const float* x      = (const float*)d_in[0];
    const int*   typeId = (const int*)d_in[1];
    const int*   ei     = (const int*)d_in[2];
    const int*   ea     = (const int*)d_in[3];
    const float* Wk     = (const float*)d_in[4];
    const float* bk     = (const float*)d_in[5];
    const float* Wq     = (const float*)d_in[6];
    const float* bq     = (const float*)d_in[7];
    const float* Wv     = (const float*)d_in[8];
    const float* bv     = (const float*)d_in[9];
    const float* Wa     = (const float*)d_in[10];
    const float* ba     = (const float*)d_in[11];
    const float* pri    = (const float*)d_in[12];
    const float* Aatt   = (const float*)d_in[13];
    const float* Amsg   = (const float*)d_in[14];
    const float* skipv  = (const float*)d_in[15];
    const float* gamma  = (const float*)d_in[16];
    const float* beta   = (const float*)d_in[17];
    float* out = (float*)d_out;

    // ncu capture window lands on launch index 3 -> k_edge_gemm.
    k_zero<<<(N_ + 255) / 256, 256>>>();                                       // 0
    k_setup<<<833, 384>>>(Wk, bk, Wq, bq, Wv, bv, pri, Aatt, Amsg,
                          ei, ea, typeId);                                     // 1
    k_scan<<<1, 1024>>>();                                                     // 2
    k_edge_gemm<<<dim3(CAPR / 64, R_), 256>>>(x);                              // 3 <- profiled
    k_scatterD<<<E_ / 256, 256>>>();                                           // 4
    k_aggregate<<<N_ / 8, 256>>>();                                            // 5
    k_out<<<dim3(CAPN / 64, T_), 256>>>(x, Wa, ba, skipv, gamma, beta, out);   // 6
}

// round 5
// speedup vs baseline: 1.0153x; 1.0153x over previous
#include <cuda_runtime.h>
#include <cuda_bf16.h>
#include <math.h>

#define N_ 32768
#define E_ 262144
#define C_ 128
#define H_ 8
#define R_ 8
#define T_ 8
#define CAPR 36864   // per-relation edge bucket capacity (expected 32768 +/- 165)
#define CAPN 4608    // per-type node bucket capacity (expected 4096 +/- 62)
#define KSTEP 8

// ---------------- f32x2 helpers ----------------
__device__ __forceinline__ unsigned long long dup2(float v) {
    unsigned long long r;
    asm("mov.b64 %0, {%1, %1};" : "=l"(r) : "f"(v));
    return r;
}
__device__ __forceinline__ void fma2(unsigned long long& acc, unsigned long long a,
                                     unsigned long long b) {
    asm("fma.rn.f32x2 %0, %1, %2, %0;" : "+l"(acc) : "l"(a), "l"(b));
}
__device__ __forceinline__ void unpack2(unsigned long long p, float& lo, float& hi) {
    asm("mov.b64 {%0, %1}, %2;" : "=f"(lo), "=f"(hi) : "l"(p));
}

// ---------------- scratch (device globals; no runtime alloc) ----------------
__device__ float d_Wall[R_][C_ * 384];   // fused weights: cols [0,128)=kt, [128,256)=vt, [256,384)=q
__device__ float d_ball[R_][384];        // fused biases
__device__ int   d_cursor8[R_];          // per-relation cursors (= counts after setup)
__device__ int   d_ssrc[R_ * CAPR];      // padded per-relation buckets
__device__ int   d_sdst[R_ * CAPR];

__device__ float d_att[E_ * H_];         // compact slot indexed
__device__ float d_vt[E_ * C_];          // compact slot indexed

__device__ int   d_cnt[N_];
__device__ int   d_rowPtr[N_ + 1];
__device__ int   d_cursor[N_];
__device__ int   d_bydst[E_];            // compact slots grouped by dst
__device__ float d_x0[N_ * C_];

__device__ int   d_cursorN8[T_];
__device__ int   d_snid[T_ * CAPN];

// ---------------- 0: zero init ----------------
__global__ void k_zero() {
    int i = blockIdx.x * blockDim.x + threadIdx.x;
    if (i < N_) { d_cnt[i] = 0; d_cursor[i] = 0; }
    if (i < R_) { d_cursor8[i] = 0; d_cursorN8[i] = 0; }
}

// ---------------- 1: fused setup: weight-fuse + edge scatter + node scatter ----------------
__global__ void __launch_bounds__(384) k_setup(
        const float* __restrict__ Wk, const float* __restrict__ bk,
        const float* __restrict__ Wq, const float* __restrict__ bq,
        const float* __restrict__ Wv, const float* __restrict__ bv,
        const float* __restrict__ pri, const float* __restrict__ Aatt,
        const float* __restrict__ Amsg,
        const int* __restrict__ ei, const int* __restrict__ ea,
        const int* __restrict__ tid_) {
    int b = blockIdx.x;
    int j = threadIdx.x;
    if (b < 64) {
        int r = b & 7, kc = b >> 3;
        int k0 = kc * 16;
        float* Wdst = d_Wall[r];
        if (j < 256) {
            bool isK = j < 128;
            int c = j & 127;
            int h = c >> 4, d2 = c & 15;
            const float* M  = (isK ? Aatt : Amsg) + ((r * 8 + h) * 256) + d2; // stride 16 over d
            const float* Ws = (isK ? Wk : Wv) + r * 16384 + h * 16;
            for (int k = k0; k < k0 + 16; k++) {
                float s = 0.f;
                #pragma unroll
                for (int d = 0; d < 16; d++) s = fmaf(Ws[k * 128 + d], M[d * 16], s);
                Wdst[k * 384 + j] = s;
            }
            if (kc == 0) {
                const float* bs = (isK ? bk : bv) + r * 128 + h * 16;
                float s = 0.f;
                #pragma unroll
                for (int d = 0; d < 16; d++) s = fmaf(bs[d], M[d * 16], s);
                d_ball[r][j] = s;
            }
        } else {
            int c = j - 256;
            int h = c >> 4;
            float sc = pri[r * 8 + h] * 0.25f;
            for (int k = k0; k < k0 + 16; k++)
                Wdst[k * 384 + j] = Wq[r * 16384 + k * 128 + c] * sc;
            if (kc == 0) d_ball[r][j] = bq[r * 128 + c] * sc;
        }
    } else if (b < 747) {
        int e = (b - 64) * 384 + j;
        if (e < E_) {
            int r = ea[e];
            int dst = ei[E_ + e];
            int pos = atomicAdd(&d_cursor8[r], 1);
            if (pos < CAPR) {
                d_ssrc[r * CAPR + pos] = ei[e];
                d_sdst[r * CAPR + pos] = dst;
            }
            atomicAdd(&d_cnt[dst], 1);
        }
    } else {
        int n = (b - 747) * 384 + j;
        if (n < N_) {
            int pos = atomicAdd(&d_cursorN8[tid_[n]], 1);
            if (pos < CAPN) d_snid[tid_[n] * CAPN + pos] = n;
        }
    }
}

// ---------------- 2: prefix scan of d_cnt -> d_rowPtr (single block) ----------------
__global__ void k_scan() {
    __shared__ int sums[1024];
    int tid = threadIdx.x;
    int base = tid * 32;
    int tot = 0;
    for (int i = 0; i < 32; i++) tot += d_cnt[base + i];
    sums[tid] = tot;
    __syncthreads();
    for (int off = 1; off < 1024; off <<= 1) {
        int v = (tid >= off) ? sums[tid - off] : 0;
        __syncthreads();
        sums[tid] += v;
        __syncthreads();
    }
    int run = sums[tid] - tot;   // exclusive prefix of this chunk
    for (int i = 0; i < 32; i++) {
        d_rowPtr[base + i] = run;
        run += d_cnt[base + i];
    }
    if (tid == 1023) d_rowPtr[N_] = run;
}

// ---------------- 3: edge GEMM (PROFILED): warp-column-specialized ----------------
// 64-edge tile x 384 cols, 12 warps; warp w owns cols [32w,32w+32) (side-pure),
// per-thread 8 rows x 8 cols. Double-buffered KSTEP=8 slices.
// Epilogue: vt -> gmem; kt staged transposed in smem; q warps do kt.q dots.
struct EgSmem {
    float A[2][2][KSTEP][68];   // [buf][side][kk][row]
    float B[2][KSTEP][388];     // [buf][kk][col]
};
__global__ void __launch_bounds__(384, 1) k_edge_gemm(const float* __restrict__ x) {
    int r = blockIdx.y;
    int i = blockIdx.x;

    __shared__ int s_cnt, s_gbase;
    __shared__ __align__(16) char smem_raw[35072];   // max(sizeof(EgSmem)=33536, K stage 34816)
    EgSmem& S = *reinterpret_cast<EgSmem*>(smem_raw);
    float (*Kst)[68] = reinterpret_cast<float(*)[68]>(smem_raw);  // [128][68] transposed kt stage

    if (threadIdx.x == 0) {
        int cnt = min(d_cursor8[r], CAPR);
        int gb = 0;
        #pragma unroll
        for (int q = 0; q < R_; q++) {
            int c = min(d_cursor8[q], CAPR);
            if (q < r) gb += c;
        }
        s_cnt = cnt;
        s_gbase = gb;
    }
    __syncthreads();
    int cnt = s_cnt;
    if (i * 64 >= cnt) return;
    int count = min(64, cnt - i * 64);
    int gstart = s_gbase + i * 64;          // compact output base for this tile
    int pstart = r * CAPR + i * 64;         // padded input base

    const float* __restrict__ W = d_Wall[r];

    int tid = threadIdx.x;
    int w = tid >> 5, lane = tid & 31;
    int rg = lane >> 2, cs = lane & 3;
    int sw = (w < 8) ? 0 : 1;               // cols [0,256)=src-driven, [256,384)=dst-driven
    int colbase = w * 32 + cs * 8;          // this thread's 8 cols

    // A gather role (threads 0..255): rowL, side, half
    int rowL = tid >> 2, q4 = tid & 3;
    int side = q4 >> 1, half = q4 & 1;
    int src = 0, dst = 0;
    bool aRole = tid < 256;
    if (aRole && rowL < count) { src = d_ssrc[pstart + rowL]; dst = d_sdst[pstart + rowL]; }
    const float* xg = x + (size_t)(side == 0 ? src : dst) * C_;

    // B load role: 2 float4 per thread per slice (768 total)
    int wkk0 = tid / 96, wc40 = tid % 96;
    int wkk1 = (tid + 384) / 96, wc41 = (tid + 384) % 96;

    unsigned long long acc2[8][4];
    #pragma unroll
    for (int a = 0; a < 8; a++)
        #pragma unroll
        for (int p = 0; p < 4; p++) acc2[a][p] = 0ull;

    // ---- prologue: load slice 0 ----
    float4 av = aRole ? *(const float4*)(xg + half * 4) : make_float4(0, 0, 0, 0);
    float4 wv0 = *(const float4*)(W + wkk0 * 384 + wc40 * 4);
    float4 wv1 = *(const float4*)(W + wkk1 * 384 + wc41 * 4);
    if (aRole) {
        int kb = half * 4;
        S.A[0][side][kb + 0][rowL] = av.x; S.A[0][side][kb + 1][rowL] = av.y;
        S.A[0][side][kb + 2][rowL] = av.z; S.A[0][side][kb + 3][rowL] = av.w;
    }
    *(float4*)&S.B[0][wkk0][wc40 * 4] = wv0;
    *(float4*)&S.B[0][wkk1][wc41 * 4] = wv1;
    __syncthreads();

    #pragma unroll 2
    for (int it = 0; it < 16; it++) {
        int cur = it & 1;
        if (it < 15) {
            int kbase = (it + 1) * KSTEP;
            if (aRole) av = *(const float4*)(xg + kbase + half * 4);
            wv0 = *(const float4*)(W + (kbase + wkk0) * 384 + wc40 * 4);
            wv1 = *(const float4*)(W + (kbase + wkk1) * 384 + wc41 * 4);
        }
        #pragma unroll
        for (int kk = 0; kk < KSTEP; kk++) {
            float4 alo = *(const float4*)&S.A[cur][sw][kk][rg * 8];
            float4 ahi = *(const float4*)&S.A[cur][sw][kk][rg * 8 + 4];
            unsigned long long ap[8];
            ap[0] = dup2(alo.x); ap[1] = dup2(alo.y); ap[2] = dup2(alo.z); ap[3] = dup2(alo.w);
            ap[4] = dup2(ahi.x); ap[5] = dup2(ahi.y); ap[6] = dup2(ahi.z); ap[7] = dup2(ahi.w);
            ulonglong2 b0 = *(const ulonglong2*)&S.B[cur][kk][colbase];
            ulonglong2 b1 = *(const ulonglong2*)&S.B[cur][kk][colbase + 4];
            #pragma unroll
            for (int a = 0; a < 8; a++) {
                fma2(acc2[a][0], ap[a], b0.x);
                fma2(acc2[a][1], ap[a], b0.y);
                fma2(acc2[a][2], ap[a], b1.x);
                fma2(acc2[a][3], ap[a], b1.y);
            }
        }
        if (it < 15) {
            int nxt = cur ^ 1;
            if (aRole) {
                int kb = half * 4;
                S.A[nxt][side][kb + 0][rowL] = av.x; S.A[nxt][side][kb + 1][rowL] = av.y;
                S.A[nxt][side][kb + 2][rowL] = av.z; S.A[nxt][side][kb + 3][rowL] = av.w;
            }
            *(float4*)&S.B[nxt][wkk0][wc40 * 4] = wv0;
            *(float4*)&S.B[nxt][wkk1][wc41 * 4] = wv1;
        }
        __syncthreads();
    }

    // ---- epilogue ----
    const float* __restrict__ bb = d_ball[r];
    float b8[8];
    {
        float4 bl = *(const float4*)(bb + colbase);
        float4 bh = *(const float4*)(bb + colbase + 4);
        b8[0] = bl.x; b8[1] = bl.y; b8[2] = bl.z; b8[3] = bl.w;
        b8[4] = bh.x; b8[5] = bh.y; b8[6] = bh.z; b8[7] = bh.w;
    }
    float accf[8][8];
    #pragma unroll
    for (int a = 0; a < 8; a++) {
        #pragma unroll
        for (int p = 0; p < 4; p++) {
            unpack2(acc2[a][p], accf[a][2 * p], accf[a][2 * p + 1]);
            accf[a][2 * p] += b8[2 * p];
            accf[a][2 * p + 1] += b8[2 * p + 1];
        }
    }

    // vt warps (4..7): write directly to gmem (registers only, no smem)
    if (w >= 4 && w < 8) {
        int cb = colbase - 128;
        #pragma unroll
        for (int a = 0; a < 8; a++) {
            int row = rg * 8 + a;
            if (row < count) {
                int slot = gstart + row;
                float4 o0 = make_float4(accf[a][0], accf[a][1], accf[a][2], accf[a][3]);
                float4 o1 = make_float4(accf[a][4], accf[a][5], accf[a][6], accf[a][7]);
                *(float4*)&d_vt[(size_t)slot * C_ + cb] = o0;
                *(float4*)&d_vt[(size_t)slot * C_ + cb + 4] = o1;
            }
        }
    }

    // kt warps (0..3): stage transposed into smem Kst[col][row]
    if (w < 4) {
        #pragma unroll
        for (int j = 0; j < 8; j++) {
            int c = colbase + j;
            *(float4*)&Kst[c][rg * 8] =
                make_float4(accf[0][j], accf[1][j], accf[2][j], accf[3][j]);
            *(float4*)&Kst[c][rg * 8 + 4] =
                make_float4(accf[4][j], accf[5][j], accf[6][j], accf[7][j]);
        }
    }
    __syncthreads();

    // q warps (8..11): att[row][h] = sum_d q*kt ; cs pair (xor 1) covers 16 dims
    if (w >= 8) {
        int qc = colbase - 256;          // [0,128)
        int h = qc >> 4;                 // head: cs pair-uniform
        #pragma unroll
        for (int a = 0; a < 8; a++) {
            int row = rg * 8 + a;
            float p = 0.f;
            #pragma unroll
            for (int j = 0; j < 8; j++)
                p = fmaf(accf[a][j], Kst[qc + j][row], p);
            p += __shfl_xor_sync(0xffffffffu, p, 1);
            if ((cs & 1) == 0 && row < count)
                d_att[(gstart + row) * 8 + h] = p;
        }
    }
}

// ---------------- 4: scatter compact slots by dst ----------------
__global__ void k_scatterD() {
    __shared__ int sb[R_ + 1];
    if (threadIdx.x < R_) sb[threadIdx.x + 1] = min(d_cursor8[threadIdx.x], CAPR);
    if (threadIdx.x == 0) sb[0] = 0;
    __syncthreads();
    if (threadIdx.x == 0) {
        #pragma unroll
        for (int q = 1; q <= R_; q++) sb[q] += sb[q - 1];
    }
    __syncthreads();
    int c = blockIdx.x * blockDim.x + threadIdx.x;
    if (c >= sb[R_]) return;
    int r = 0;
    #pragma unroll
    for (int q = 1; q < R_; q++) r += (c >= sb[q]);
    int padded = r * CAPR + (c - sb[r]);
    int dst = d_sdst[padded];
    int pos = d_rowPtr[dst] + atomicAdd(&d_cursor[dst], 1);
    d_bydst[pos] = c;
}

// ---------------- 5: per-node softmax + weighted mean (warp per node) ----------------
__global__ void k_aggregate() {
    int warp = threadIdx.x >> 5;
    int lane = threadIdx.x & 31;
    int n = blockIdx.x * (blockDim.x >> 5) + warp;
    if (n >= N_) return;
    int s = d_rowPtr[n], eEnd = d_rowPtr[n + 1];
    int deg = eEnd - s;
    if (deg == 0) {
        #pragma unroll
        for (int j = 0; j < 4; j++) d_x0[n * C_ + lane + 32 * j] = 0.f;
        return;
    }
    int slot = lane >> 3, h = lane & 7;
    float m = -1e30f;
    for (int b = s; b < eEnd; b += 4) {
        int idx = b + slot;
        if (idx < eEnd) {
            int e = d_bydst[idx];
            m = fmaxf(m, d_att[e * 8 + h]);
        }
    }
    m = fmaxf(m, __shfl_xor_sync(0xffffffffu, m, 8));
    m = fmaxf(m, __shfl_xor_sync(0xffffffffu, m, 16));
    float den = 0.f;
    for (int b = s; b < eEnd; b += 4) {
        int idx = b + slot;
        if (idx < eEnd) {
            int e = d_bydst[idx];
            den += expf(d_att[e * 8 + h] - m);
        }
    }
    den += __shfl_xor_sync(0xffffffffu, den, 8);
    den += __shfl_xor_sync(0xffffffffu, den, 16);

    int hb = lane >> 4; // channel c = lane + 32j -> head hb + 2j
    float mj[4], rj[4];
    #pragma unroll
    for (int j = 0; j < 4; j++) {
        int hh = hb + 2 * j;
        mj[j] = __shfl_sync(0xffffffffu, m, hh);
        rj[j] = 1.f / __shfl_sync(0xffffffffu, den, hh);
    }
    float acc[4] = {0.f, 0.f, 0.f, 0.f};
    for (int idx = s; idx < eEnd; idx++) {
        int e = d_bydst[idx];
        const float* ar = &d_att[e * 8];
        const float* vr = &d_vt[(size_t)e * C_];
        #pragma unroll
        for (int j = 0; j < 4; j++) {
            float w = expf(ar[hb + 2 * j] - mj[j]) * rj[j];
            acc[j] = fmaf(w, vr[lane + 32 * j], acc[j]);
        }
    }
    float inv = 1.f / (float)deg;
    #pragma unroll
    for (int j = 0; j < 4; j++) d_x0[n * C_ + lane + 32 * j] = acc[j] * inv;
}

// ---------------- 6: output: typed GEMM + gated residual + LayerNorm ----------------
__global__ void __launch_bounds__(256) k_out(const float* __restrict__ x,
                                             const float* __restrict__ Wa,
                                             const float* __restrict__ ba,
                                             const float* __restrict__ skipv,
                                             const float* __restrict__ gamma,
                                             const float* __restrict__ beta,
                                             float* __restrict__ out) {
    int t = blockIdx.y;
    int jt = blockIdx.x;
    int cntT = min(d_cursorN8[t], CAPN);
    if (jt * 64 >= cntT) return;
    int count = min(64, cntT - jt * 64);
    int start = t * CAPN + jt * 64;

    __shared__ __align__(16) float sA[16][68];
    __shared__ __align__(16) float sB[16][132];

    int tid = threadIdx.x;
    int ty = tid >> 4, tx = tid & 15;
    int rowL = tid >> 2, q4 = tid & 3;

    int nidL = (rowL < count) ? d_snid[start + rowL] : 0;
    const float* a_src = d_x0 + (size_t)nidL * C_;
    const float* W = Wa + t * 16384;

    unsigned long long acc2[4][4];
    #pragma unroll
    for (int a = 0; a < 4; a++)
        #pragma unroll
        for (int p = 0; p < 4; p++) acc2[a][p] = 0ull;

    for (int k0 = 0; k0 < 128; k0 += 16) {
        __syncthreads();
        float4 v = *(const float4*)(a_src + k0 + q4 * 4);
        sA[q4 * 4 + 0][rowL] = v.x; sA[q4 * 4 + 1][rowL] = v.y;
        sA[q4 * 4 + 2][rowL] = v.z; sA[q4 * 4 + 3][rowL] = v.w;
        #pragma unroll
        for (int a = 0; a < 2; a++) {
            int idx = tid + 256 * a;
            int kk = idx >> 5, c4 = idx & 31;
            *(float4*)&sB[kk][c4 * 4] = *(const float4*)(W + (k0 + kk) * 128 + c4 * 4);
        }
        __syncthreads();
        #pragma unroll
        for (int kk = 0; kk < 16; kk++) {
            float4 a4 = *(const float4*)&sA[kk][ty * 4];
            unsigned long long ap[4];
            ap[0] = dup2(a4.x); ap[1] = dup2(a4.y);
            ap[2] = dup2(a4.z); ap[3] = dup2(a4.w);
            #pragma unroll
            for (int g = 0; g < 2; g++) {
                ulonglong2 b2 = *(const ulonglong2*)&sB[kk][tx * 4 + 64 * g];
                #pragma unroll
                for (int a = 0; a < 4; a++) {
                    fma2(acc2[a][g * 2 + 0], ap[a], b2.x);
                    fma2(acc2[a][g * 2 + 1], ap[a], b2.y);
                }
            }
        }
    }

    float alpha = 1.f / (1.f + expf(-skipv[t]));
    float onema = 1.f - alpha;

    #pragma unroll
    for (int a = 0; a < 4; a++) {
        int row = ty * 4 + a;
        bool valid = row < count;
        int nid = valid ? d_snid[start + row] : 0;
        float accf[8];
        #pragma unroll
        for (int p = 0; p < 4; p++) unpack2(acc2[a][p], accf[2 * p], accf[2 * p + 1]);
        float v[8];
        float s1 = 0.f, s2 = 0.f;
        #pragma unroll
        for (int g = 0; g < 2; g++) {
            #pragma unroll
            for (int l = 0; l < 4; l++) {
                int c = 64 * g + 4 * tx + l;
                float val = accf[g * 4 + l] + ba[t * 128 + c];
                val = alpha * val + onema * x[(size_t)nid * C_ + c];
                v[g * 4 + l] = val;
                s1 += val;
                s2 = fmaf(val, val, s2);
            }
        }
        #pragma unroll
        for (int off = 1; off <= 8; off <<= 1) {
            s1 += __shfl_xor_sync(0xffffffffu, s1, off);
            s2 += __shfl_xor_sync(0xffffffffu, s2, off);
        }
        float mu = s1 * (1.f / 128.f);
        float var = s2 * (1.f / 128.f) - mu * mu;
        float rstd = rsqrtf(var + 1e-5f);
        if (valid) {
            #pragma unroll
            for (int g = 0; g < 2; g++) {
                int cb = 64 * g + 4 * tx;
                float4 o;
                o.x = (v[g * 4 + 0] - mu) * rstd * gamma[t * 128 + cb + 0] + beta[t * 128 + cb + 0];
                o.y = (v[g * 4 + 1] - mu) * rstd * gamma[t * 128 + cb + 1] + beta[t * 128 + cb + 1];
                o.z = (v[g * 4 + 2] - mu) * rstd * gamma[t * 128 + cb + 2] + beta[t * 128 + cb + 2];
                o.w = (v[g * 4 + 3] - mu) * rstd * gamma[t * 128 + cb + 3] + beta[t * 128 + cb + 3];
                *(float4*)&out[(size_t)nid * C_ + cb] = o;
            }
        }
    }
}

// ---------------- launch ----------------
extern "C" void kernel_launch(void* const* d_in, const int* in_sizes, int n_in,
                              void* d_out, int out_size) {
    const float* x      = (const float*)d_in[0];
    const int*   typeId = (const int*)d_in[1];
    const int*   ei     = (const int*)d_in[2];
    const int*   ea     = (const int*)d_in[3];
    const float* Wk     = (const float*)d_in[4];
    const float* bk     = (const float*)d_in[5];
    const float* Wq     = (const float*)d_in[6];
    const float* bq     = (const float*)d_in[7];
    const float* Wv     = (const float*)d_in[8];
    const float* bv     = (const float*)d_in[9];
    const float* Wa     = (const float*)d_in[10];
    const float* ba     = (const float*)d_in[11];
    const float* pri    = (const float*)d_in[12];
    const float* Aatt   = (const float*)d_in[13];
    const float* Amsg   = (const float*)d_in[14];
    const float* skipv  = (const float*)d_in[15];
    const float* gamma  = (const float*)d_in[16];
    const float* beta   = (const float*)d_in[17];
    float* out = (float*)d_out;

    // ncu capture window lands on launch index 3 -> k_edge_gemm.
    k_zero<<<(N_ + 255) / 256, 256>>>();                                       // 0
    k_setup<<<833, 384>>>(Wk, bk, Wq, bq, Wv, bv, pri, Aatt, Amsg,
                          ei, ea, typeId);                                     // 1
    k_scan<<<1, 1024>>>();                                                     // 2
    k_edge_gemm<<<dim3(CAPR / 64, R_), 384>>>(x);                              // 3 <- profiled
    k_scatterD<<<E_ / 256, 256>>>();                                           // 4
    k_aggregate<<<N_ / 8, 256>>>();                                            // 5
    k_out<<<dim3(CAPN / 64, T_), 256>>>(x, Wa, ba, skipv, gamma, beta, out);   // 6
}

// round 8
// speedup vs baseline: 1.6089x; 1.5846x over previous
#include <cuda_runtime.h>
#include <cuda_bf16.h>
#include <math.h>
#include <stdint.h>

#define N_ 32768
#define E_ 262144
#define C_ 128
#define H_ 8
#define R_ 8
#define T_ 8
#define CAPR 36864
#define CAPN 4608

// ---------------- f32x2 helpers ----------------
__device__ __forceinline__ unsigned long long dup2(float v) {
    unsigned long long r; asm("mov.b64 %0, {%1, %1};" : "=l"(r) : "f"(v)); return r;
}
__device__ __forceinline__ void fma2(unsigned long long& acc, unsigned long long a,
                                     unsigned long long b) {
    asm("fma.rn.f32x2 %0, %1, %2, %0;" : "+l"(acc) : "l"(a), "l"(b));
}
__device__ __forceinline__ void unpack2(unsigned long long p, float& lo, float& hi) {
    asm("mov.b64 {%0, %1}, %2;" : "=f"(lo), "=f"(hi) : "l"(p));
}

// ---------------- mma helpers ----------------
__device__ __forceinline__ void mma_bf16(float* c, const uint32_t* a, uint32_t b0, uint32_t b1) {
    asm volatile(
        "mma.sync.aligned.m16n8k16.row.col.f32.bf16.bf16.f32 "
        "{%0,%1,%2,%3}, {%4,%5,%6,%7}, {%8,%9}, {%0,%1,%2,%3};"
        : "+f"(c[0]), "+f"(c[1]), "+f"(c[2]), "+f"(c[3])
        : "r"(a[0]), "r"(a[1]), "r"(a[2]), "r"(a[3]), "r"(b0), "r"(b1));
}
__device__ __forceinline__ void packhl(float2 f, uint32_t& h, uint32_t& l) {
    __nv_bfloat162 H = __floats2bfloat162_rn(f.x, f.y);
    float lx = f.x - __bfloat162float(H.x);
    float ly = f.y - __bfloat162float(H.y);
    __nv_bfloat162 L = __floats2bfloat162_rn(lx, ly);
    h = *(uint32_t*)&H;
    l = *(uint32_t*)&L;
}

// ---------------- scratch ----------------
// W bf16 hi/lo, [n][k] per 32-col chunk, 136-elem row stride (conflict-free):
// index = ((r*12 + chunk)*2 + comp)*4352 + n*136 + k
__device__ __nv_bfloat16 d_Wbf[R_ * 12 * 2 * 4352];
__device__ float d_ball[R_][384];
__device__ int   d_cursor8[R_];
__device__ int   d_ssrc[R_ * CAPR];
__device__ int   d_sdst[R_ * CAPR];
__device__ float d_att[E_ * H_];
__device__ float d_vt[E_ * C_];
__device__ int   d_cnt[N_];
__device__ int   d_rowPtr[N_ + 1];
__device__ int   d_cursor[N_];
__device__ int   d_bydst[E_];
__device__ float d_x0[N_ * C_];
__device__ int   d_cursorN8[T_];
__device__ int   d_snid[T_ * CAPN];

// ---------------- 0: zero ----------------
__global__ void k_zero() {
    int i = blockIdx.x * blockDim.x + threadIdx.x;
    if (i < N_) { d_cnt[i] = 0; d_cursor[i] = 0; }
    if (i < R_) { d_cursor8[i] = 0; d_cursorN8[i] = 0; }
}

__device__ __forceinline__ void store_wbf(int r, int k, int j, float wv) {
    int chunk = j >> 5, n = j & 31;
    __nv_bfloat16 hi = __float2bfloat16_rn(wv);
    __nv_bfloat16 lo = __float2bfloat16_rn(wv - __bfloat162float(hi));
    size_t base = ((size_t)(r * 12 + chunk) * 2) * 4352 + n * 136 + k;
    d_Wbf[base] = hi;
    d_Wbf[base + 4352] = lo;
}

// ---------------- 1: setup ----------------
__global__ void __launch_bounds__(384) k_setup(
        const float* __restrict__ Wk, const float* __restrict__ bk,
        const float* __restrict__ Wq, const float* __restrict__ bq,
        const float* __restrict__ Wv, const float* __restrict__ bv,
        const float* __restrict__ pri, const float* __restrict__ Aatt,
        const float* __restrict__ Amsg,
        const int* __restrict__ ei, const int* __restrict__ ea,
        const int* __restrict__ tid_) {
    int b = blockIdx.x;
    int j = threadIdx.x;
    if (b < 64) {
        int r = b & 7, kc = b >> 3;
        int k0 = kc * 16;
        if (j < 256) {
            bool isK = j < 128;
            int c = j & 127;
            int h = c >> 4, d2 = c & 15;
            const float* M  = (isK ? Aatt : Amsg) + ((r * 8 + h) * 256) + d2;
            const float* Ws = (isK ? Wk : Wv) + r * 16384 + h * 16;
            for (int k = k0; k < k0 + 16; k++) {
                float s = 0.f;
                #pragma unroll
                for (int d = 0; d < 16; d++) s = fmaf(Ws[k * 128 + d], M[d * 16], s);
                store_wbf(r, k, j, s);
            }
            if (kc == 0) {
                const float* bs = (isK ? bk : bv) + r * 128 + h * 16;
                float s = 0.f;
                #pragma unroll
                for (int d = 0; d < 16; d++) s = fmaf(bs[d], M[d * 16], s);
                d_ball[r][j] = s;
            }
        } else {
            int c = j - 256;
            int h = c >> 4;
            float sc = pri[r * 8 + h] * 0.25f;
            for (int k = k0; k < k0 + 16; k++)
                store_wbf(r, k, j, Wq[r * 16384 + k * 128 + c] * sc);
            if (kc == 0) d_ball[r][j] = bq[r * 128 + c] * sc;
        }
    } else if (b < 747) {
        int e = (b - 64) * 384 + j;
        if (e < E_) {
            int r = ea[e];
            int dst = ei[E_ + e];
            int pos = atomicAdd(&d_cursor8[r], 1);
            if (pos < CAPR) {
                d_ssrc[r * CAPR + pos] = ei[e];
                d_sdst[r * CAPR + pos] = dst;
            }
            atomicAdd(&d_cnt[dst], 1);
        }
    } else {
        int n = (b - 747) * 384 + j;
        if (n < N_) {
            int pos = atomicAdd(&d_cursorN8[tid_[n]], 1);
            if (pos < CAPN) d_snid[tid_[n] * CAPN + pos] = n;
        }
    }
}

// ---------------- 2: scan ----------------
__global__ void k_scan() {
    __shared__ int sums[1024];
    int tid = threadIdx.x;
    int base = tid * 32;
    int tot = 0;
    for (int i = 0; i < 32; i++) tot += d_cnt[base + i];
    sums[tid] = tot;
    __syncthreads();
    for (int off = 1; off < 1024; off <<= 1) {
        int v = (tid >= off) ? sums[tid - off] : 0;
        __syncthreads();
        sums[tid] += v;
        __syncthreads();
    }
    int run = sums[tid] - tot;
    for (int i = 0; i < 32; i++) { d_rowPtr[base + i] = run; run += d_cnt[base + i]; }
    if (tid == 1023) d_rowPtr[N_] = run;
}

// ---------------- 3: edge GEMM via mma.sync bf16 3-pass (PROFILED) ----------------
// 128 edges x 384 cols x K=128 per block. 8 warps: warp owns 16 rows.
// Chunks of 32 cols: 0-3 kt (retain fragments), 4-7 vt (store), 8-11 q (dot vs kt -> att).
__global__ void __launch_bounds__(256, 1) k_edge_gemm(const float* __restrict__ x) {
    int r = blockIdx.y, i = blockIdx.x;
    int tid = threadIdx.x, wid = tid >> 5, lane = tid & 31;
    int g = lane >> 2, t = lane & 3;

    __shared__ int s_cnt, s_gb, s_src[128], s_dst[128];
    __shared__ __align__(16) uint4 sB[2][1088];   // [buf][hi 4352 bf16 | lo 4352 bf16]

    if (tid == 0) {
        int cnt = min(d_cursor8[r], CAPR);
        int gb = 0;
        #pragma unroll
        for (int q = 0; q < R_; q++) { int c = min(d_cursor8[q], CAPR); if (q < r) gb += c; }
        s_cnt = cnt; s_gb = gb;
    }
    __syncthreads();
    int cnt = s_cnt;
    if (i * 128 >= cnt) return;
    int count = min(128, cnt - i * 128);
    int gstart = s_gb + i * 128;
    int pstart = r * CAPR + i * 128;

    if (tid < 128) s_src[tid] = (i * 128 + tid < cnt) ? d_ssrc[pstart + tid] : 0;
    else {
        int m = tid - 128;
        s_dst[m] = (i * 128 + m < cnt) ? d_sdst[pstart + m] : 0;
    }

    // prologue: chunk 0 B -> buf 0
    {
        const uint4* w0 = (const uint4*)(d_Wbf + (size_t)(r * 12) * 8704);
        for (int idx = tid; idx < 1088; idx += 256) sB[0][idx] = w0[idx];
    }
    __syncthreads();

    int r0 = wid * 16 + g, r1 = r0 + 8;

    // A fragments from x[src] (hi/lo bf16 packed)
    uint32_t Ah[8][4], Al[8][4];
    {
        const float* p0 = x + (size_t)s_src[r0] * C_;
        const float* p1 = x + (size_t)s_src[r1] * C_;
        #pragma unroll
        for (int ks = 0; ks < 8; ks++) {
            int kb = ks * 16 + 2 * t;
            packhl(*(const float2*)(p0 + kb),     Ah[ks][0], Al[ks][0]);
            packhl(*(const float2*)(p1 + kb),     Ah[ks][1], Al[ks][1]);
            packhl(*(const float2*)(p0 + kb + 8), Ah[ks][2], Al[ks][2]);
            packhl(*(const float2*)(p1 + kb + 8), Ah[ks][3], Al[ks][3]);
        }
    }

    const float* __restrict__ bb = d_ball[r];
    float kt[4][16];
    bool v0 = r0 < count, v1 = r1 < count;
    int slot0 = gstart + r0, slot1 = gstart + r1;

    #pragma unroll
    for (int c = 0; c < 12; c++) {
        int buf = c & 1;
        // prefetch next chunk's B into regs
        uint4 pf[5];
        if (c < 11) {
            const uint4* wn = (const uint4*)(d_Wbf + (size_t)(r * 12 + c + 1) * 8704);
            #pragma unroll
            for (int j = 0; j < 5; j++) {
                int idx = tid + 256 * j;
                if (idx < 1088) pf[j] = wn[idx];
            }
        }
        // phase 2: reload A fragments from x[dst]
        if (c == 8) {
            const float* p0 = x + (size_t)s_dst[r0] * C_;
            const float* p1 = x + (size_t)s_dst[r1] * C_;
            #pragma unroll
            for (int ks = 0; ks < 8; ks++) {
                int kb = ks * 16 + 2 * t;
                packhl(*(const float2*)(p0 + kb),     Ah[ks][0], Al[ks][0]);
                packhl(*(const float2*)(p1 + kb),     Ah[ks][1], Al[ks][1]);
                packhl(*(const float2*)(p0 + kb + 8), Ah[ks][2], Al[ks][2]);
                packhl(*(const float2*)(p1 + kb + 8), Ah[ks][3], Al[ks][3]);
            }
        }

        float acc[16];
        #pragma unroll
        for (int j = 0; j < 16; j++) acc[j] = 0.f;

        const __nv_bfloat16* Bp = (const __nv_bfloat16*)sB[buf];
        #pragma unroll
        for (int ks = 0; ks < 8; ks++) {
            int kb = ks * 16 + 2 * t;
            #pragma unroll
            for (int nt = 0; nt < 4; nt++) {
                const __nv_bfloat16* bn = Bp + (nt * 8 + g) * 136 + kb;
                uint32_t b0h = *(const uint32_t*)bn;
                uint32_t b1h = *(const uint32_t*)(bn + 8);
                uint32_t b0l = *(const uint32_t*)(bn + 4352);
                uint32_t b1l = *(const uint32_t*)(bn + 4360);
                mma_bf16(&acc[nt * 4], Ah[ks], b0h, b1h);
                mma_bf16(&acc[nt * 4], Al[ks], b0h, b1h);
                mma_bf16(&acc[nt * 4], Ah[ks], b0l, b1l);
            }
        }

        // bias add
        #pragma unroll
        for (int nt = 0; nt < 4; nt++) {
            float bc0 = bb[c * 32 + nt * 8 + 2 * t];
            float bc1 = bb[c * 32 + nt * 8 + 2 * t + 1];
            acc[nt * 4 + 0] += bc0; acc[nt * 4 + 1] += bc1;
            acc[nt * 4 + 2] += bc0; acc[nt * 4 + 3] += bc1;
        }

        if (c < 4) {
            #pragma unroll
            for (int j = 0; j < 16; j++) kt[c][j] = acc[j];
        } else if (c < 8) {
            int cb = (c - 4) * 32;
            #pragma unroll
            for (int nt = 0; nt < 4; nt++) {
                int col = cb + nt * 8 + 2 * t;
                if (v0) *(float2*)&d_vt[(size_t)slot0 * C_ + col] =
                    make_float2(acc[nt * 4 + 0], acc[nt * 4 + 1]);
                if (v1) *(float2*)&d_vt[(size_t)slot1 * C_ + col] =
                    make_float2(acc[nt * 4 + 2], acc[nt * 4 + 3]);
            }
        } else {
            int cc = c - 8;
            int h0 = cc * 2;
            float p00 = acc[0] * kt[cc][0] + acc[1] * kt[cc][1]
                      + acc[4] * kt[cc][4] + acc[5] * kt[cc][5];
            float p10 = acc[2] * kt[cc][2] + acc[3] * kt[cc][3]
                      + acc[6] * kt[cc][6] + acc[7] * kt[cc][7];
            float p01 = acc[8] * kt[cc][8] + acc[9] * kt[cc][9]
                      + acc[12] * kt[cc][12] + acc[13] * kt[cc][13];
            float p11 = acc[10] * kt[cc][10] + acc[11] * kt[cc][11]
                      + acc[14] * kt[cc][14] + acc[15] * kt[cc][15];
            p00 += __shfl_xor_sync(0xffffffffu, p00, 1);
            p00 += __shfl_xor_sync(0xffffffffu, p00, 2);
            p10 += __shfl_xor_sync(0xffffffffu, p10, 1);
            p10 += __shfl_xor_sync(0xffffffffu, p10, 2);
            p01 += __shfl_xor_sync(0xffffffffu, p01, 1);
            p01 += __shfl_xor_sync(0xffffffffu, p01, 2);
            p11 += __shfl_xor_sync(0xffffffffu, p11, 1);
            p11 += __shfl_xor_sync(0xffffffffu, p11, 2);
            if (t == 0) {
                if (v0) {
                    d_att[(size_t)slot0 * 8 + h0] = p00;
                    d_att[(size_t)slot0 * 8 + h0 + 1] = p01;
                }
                if (v1) {
                    d_att[(size_t)slot1 * 8 + h0] = p10;
                    d_att[(size_t)slot1 * 8 + h0 + 1] = p11;
                }
            }
        }

        // store prefetched B to other buffer
        if (c < 11) {
            #pragma unroll
            for (int j = 0; j < 5; j++) {
                int idx = tid + 256 * j;
                if (idx < 1088) sB[buf ^ 1][idx] = pf[j];
            }
        }
        __syncthreads();
    }
}

// ---------------- 4: scatter compact slots by dst ----------------
__global__ void k_scatterD() {
    __shared__ int sb[R_ + 1];
    if (threadIdx.x < R_) sb[threadIdx.x + 1] = min(d_cursor8[threadIdx.x], CAPR);
    if (threadIdx.x == 0) sb[0] = 0;
    __syncthreads();
    if (threadIdx.x == 0) {
        #pragma unroll
        for (int q = 1; q <= R_; q++) sb[q] += sb[q - 1];
    }
    __syncthreads();
    int c = blockIdx.x * blockDim.x + threadIdx.x;
    if (c >= sb[R_]) return;
    int r = 0;
    #pragma unroll
    for (int q = 1; q < R_; q++) r += (c >= sb[q]);
    int padded = r * CAPR + (c - sb[r]);
    int dst = d_sdst[padded];
    int pos = d_rowPtr[dst] + atomicAdd(&d_cursor[dst], 1);
    d_bydst[pos] = c;
}

// ---------------- 5: aggregate ----------------
__global__ void k_aggregate() {
    int warp = threadIdx.x >> 5;
    int lane = threadIdx.x & 31;
    int n = blockIdx.x * (blockDim.x >> 5) + warp;
    if (n >= N_) return;
    int s = d_rowPtr[n], eEnd = d_rowPtr[n + 1];
    int deg = eEnd - s;
    if (deg == 0) {
        #pragma unroll
        for (int j = 0; j < 4; j++) d_x0[n * C_ + lane + 32 * j] = 0.f;
        return;
    }
    int slot = lane >> 3, h = lane & 7;
    float m = -1e30f;
    for (int b = s; b < eEnd; b += 4) {
        int idx = b + slot;
        if (idx < eEnd) m = fmaxf(m, d_att[d_bydst[idx] * 8 + h]);
    }
    m = fmaxf(m, __shfl_xor_sync(0xffffffffu, m, 8));
    m = fmaxf(m, __shfl_xor_sync(0xffffffffu, m, 16));
    float den = 0.f;
    for (int b = s; b < eEnd; b += 4) {
        int idx = b + slot;
        if (idx < eEnd) den += expf(d_att[d_bydst[idx] * 8 + h] - m);
    }
    den += __shfl_xor_sync(0xffffffffu, den, 8);
    den += __shfl_xor_sync(0xffffffffu, den, 16);
    int hb = lane >> 4;
    float mj[4], rj[4];
    #pragma unroll
    for (int j = 0; j < 4; j++) {
        int hh = hb + 2 * j;
        mj[j] = __shfl_sync(0xffffffffu, m, hh);
        rj[j] = 1.f / __shfl_sync(0xffffffffu, den, hh);
    }
    float acc[4] = {0.f, 0.f, 0.f, 0.f};
    for (int idx = s; idx < eEnd; idx++) {
        int e = d_bydst[idx];
        const float* ar = &d_att[e * 8];
        const float* vr = &d_vt[(size_t)e * C_];
        #pragma unroll
        for (int j = 0; j < 4; j++) {
            float w = expf(ar[hb + 2 * j] - mj[j]) * rj[j];
            acc[j] = fmaf(w, vr[lane + 32 * j], acc[j]);
        }
    }
    float inv = 1.f / (float)deg;
    #pragma unroll
    for (int j = 0; j < 4; j++) d_x0[n * C_ + lane + 32 * j] = acc[j] * inv;
}

// ---------------- 6: out GEMM + residual + LN ----------------
__global__ void __launch_bounds__(256) k_out(const float* __restrict__ x,
                                             const float* __restrict__ Wa,
                                             const float* __restrict__ ba,
                                             const float* __restrict__ skipv,
                                             const float* __restrict__ gamma,
                                             const float* __restrict__ beta,
                                             float* __restrict__ out) {
    int t = blockIdx.y;
    int jt = blockIdx.x;
    int cntT = min(d_cursorN8[t], CAPN);
    if (jt * 64 >= cntT) return;
    int count = min(64, cntT - jt * 64);
    int start = t * CAPN + jt * 64;

    __shared__ __align__(16) float sA[16][68];
    __shared__ __align__(16) float sB2[16][132];

    int tid = threadIdx.x;
    int ty = tid >> 4, tx = tid & 15;
    int rowL = tid >> 2, q4 = tid & 3;

    int nidL = (rowL < count) ? d_snid[start + rowL] : 0;
    const float* a_src = d_x0 + (size_t)nidL * C_;
    const float* W = Wa + t * 16384;

    unsigned long long acc2[4][4];
    #pragma unroll
    for (int a = 0; a < 4; a++)
        #pragma unroll
        for (int p = 0; p < 4; p++) acc2[a][p] = 0ull;

    for (int k0 = 0; k0 < 128; k0 += 16) {
        __syncthreads();
        float4 v = *(const float4*)(a_src + k0 + q4 * 4);
        sA[q4 * 4 + 0][rowL] = v.x; sA[q4 * 4 + 1][rowL] = v.y;
        sA[q4 * 4 + 2][rowL] = v.z; sA[q4 * 4 + 3][rowL] = v.w;
        #pragma unroll
        for (int a = 0; a < 2; a++) {
            int idx = tid + 256 * a;
            int kk = idx >> 5, c4 = idx & 31;
            *(float4*)&sB2[kk][c4 * 4] = *(const float4*)(W + (k0 + kk) * 128 + c4 * 4);
        }
        __syncthreads();
        #pragma unroll
        for (int kk = 0; kk < 16; kk++) {
            float4 a4 = *(const float4*)&sA[kk][ty * 4];
            unsigned long long ap[4];
            ap[0] = dup2(a4.x); ap[1] = dup2(a4.y);
            ap[2] = dup2(a4.z); ap[3] = dup2(a4.w);
            #pragma unroll
            for (int gg = 0; gg < 2; gg++) {
                ulonglong2 b2 = *(const ulonglong2*)&sB2[kk][tx * 4 + 64 * gg];
                #pragma unroll
                for (int a = 0; a < 4; a++) {
                    fma2(acc2[a][gg * 2 + 0], ap[a], b2.x);
                    fma2(acc2[a][gg * 2 + 1], ap[a], b2.y);
                }
            }
        }
    }

    float alpha = 1.f / (1.f + expf(-skipv[t]));
    float onema = 1.f - alpha;

    #pragma unroll
    for (int a = 0; a < 4; a++) {
        int row = ty * 4 + a;
        bool valid = row < count;
        int nid = valid ? d_snid[start + row] : 0;
        float accf[8];
        #pragma unroll
        for (int p = 0; p < 4; p++) unpack2(acc2[a][p], accf[2 * p], accf[2 * p + 1]);
        float v[8];
        float s1 = 0.f, s2 = 0.f;
        #pragma unroll
        for (int gg = 0; gg < 2; gg++) {
            #pragma unroll
            for (int l = 0; l < 4; l++) {
                int c = 64 * gg + 4 * tx + l;
                float val = accf[gg * 4 + l] + ba[t * 128 + c];
                val = alpha * val + onema * x[(size_t)nid * C_ + c];
                v[gg * 4 + l] = val;
                s1 += val;
                s2 = fmaf(val, val, s2);
            }
        }
        #pragma unroll
        for (int off = 1; off <= 8; off <<= 1) {
            s1 += __shfl_xor_sync(0xffffffffu, s1, off);
            s2 += __shfl_xor_sync(0xffffffffu, s2, off);
        }
        float mu = s1 * (1.f / 128.f);
        float var = s2 * (1.f / 128.f) - mu * mu;
        float rstd = rsqrtf(var + 1e-5f);
        if (valid) {
            #pragma unroll
            for (int gg = 0; gg < 2; gg++) {
                int cb = 64 * gg + 4 * tx;
                float4 o;
                o.x = (v[gg * 4 + 0] - mu) * rstd * gamma[t * 128 + cb + 0] + beta[t * 128 + cb + 0];
                o.y = (v[gg * 4 + 1] - mu) * rstd * gamma[t * 128 + cb + 1] + beta[t * 128 + cb + 1];
                o.z = (v[gg * 4 + 2] - mu) * rstd * gamma[t * 128 + cb + 2] + beta[t * 128 + cb + 2];
                o.w = (v[gg * 4 + 3] - mu) * rstd * gamma[t * 128 + cb + 3] + beta[t * 128 + cb + 3];
                *(float4*)&out[(size_t)nid * C_ + cb] = o;
            }
        }
    }
}

// ---------------- launch ----------------
extern "C" void kernel_launch(void* const* d_in, const int* in_sizes, int n_in,
                              void* d_out, int out_size) {
    const float* x      = (const float*)d_in[0];
    const int*   typeId = (const int*)d_in[1];
    const int*   ei     = (const int*)d_in[2];
    const int*   ea     = (const int*)d_in[3];
    const float* Wk     = (const float*)d_in[4];
    const float* bk     = (const float*)d_in[5];
    const float* Wq     = (const float*)d_in[6];
    const float* bq     = (const float*)d_in[7];
    const float* Wv     = (const float*)d_in[8];
    const float* bv     = (const float*)d_in[9];
    const float* Wa     = (const float*)d_in[10];
    const float* ba     = (const float*)d_in[11];
    const float* pri    = (const float*)d_in[12];
    const float* Aatt   = (const float*)d_in[13];
    const float* Amsg   = (const float*)d_in[14];
    const float* skipv  = (const float*)d_in[15];
    const float* gamma  = (const float*)d_in[16];
    const float* beta   = (const float*)d_in[17];
    float* out = (float*)d_out;

    k_zero<<<(N_ + 255) / 256, 256>>>();                                       // 0
    k_setup<<<833, 384>>>(Wk, bk, Wq, bq, Wv, bv, pri, Aatt, Amsg,
                          ei, ea, typeId);                                     // 1
    k_scan<<<1, 1024>>>();                                                     // 2
    k_edge_gemm<<<dim3(CAPR / 128, R_), 256>>>(x);                             // 3 <- profiled
    k_scatterD<<<E_ / 256, 256>>>();                                           // 4
    k_aggregate<<<N_ / 8, 256>>>();                                            // 5
    k_out<<<dim3(CAPN / 64, T_), 256>>>(x, Wa, ba, skipv, gamma, beta, out);   // 6
}

// round 9
// speedup vs baseline: 1.6847x; 1.0471x over previous
#include <cuda_runtime.h>
#include <cuda_bf16.h>
#include <math.h>
#include <stdint.h>

#define N_ 32768
#define E_ 262144
#define C_ 128
#define H_ 8
#define R_ 8
#define T_ 8
#define CAPR 36864
#define CAPN 4608

// ---------------- mma helpers ----------------
__device__ __forceinline__ void mma_bf16(float* c, const uint32_t* a, uint32_t b0, uint32_t b1) {
    asm volatile(
        "mma.sync.aligned.m16n8k16.row.col.f32.bf16.bf16.f32 "
        "{%0,%1,%2,%3}, {%4,%5,%6,%7}, {%8,%9}, {%0,%1,%2,%3};"
        : "+f"(c[0]), "+f"(c[1]), "+f"(c[2]), "+f"(c[3])
        : "r"(a[0]), "r"(a[1]), "r"(a[2]), "r"(a[3]), "r"(b0), "r"(b1));
}

// ---------------- scratch ----------------
// W bf16 hi/lo, [n][k] per 32-col chunk, 136-elem row stride:
__device__ __nv_bfloat16 d_Wbf[R_ * 12 * 2 * 4352];
__device__ __nv_bfloat16 d_Wabf[T_ * 4 * 2 * 4352];
__device__ __nv_bfloat16 d_xhi[N_ * C_];
__device__ __nv_bfloat16 d_xlo[N_ * C_];
__device__ __nv_bfloat16 d_x0hi[N_ * C_];
__device__ __nv_bfloat16 d_x0lo[N_ * C_];
__device__ float d_ball[R_][384];
__device__ int   d_cursor8[R_];
__device__ int   d_ssrc[R_ * CAPR];
__device__ int   d_sdst[R_ * CAPR];
__device__ float d_att[E_ * H_];
__device__ float d_vt[E_ * C_];
__device__ int   d_cnt[N_];
__device__ int   d_rowPtr[N_ + 1];
__device__ int   d_cursor[N_];
__device__ int   d_bydst[E_];
__device__ int   d_cursorN8[T_];
__device__ int   d_snid[T_ * CAPN];

// ---------------- 0: zero ----------------
__global__ void k_zero() {
    int i = blockIdx.x * blockDim.x + threadIdx.x;
    if (i < N_) { d_cnt[i] = 0; d_cursor[i] = 0; }
    if (i < R_) { d_cursor8[i] = 0; d_cursorN8[i] = 0; }
}

__device__ __forceinline__ void store_wbf(int r, int k, int j, float wv) {
    int chunk = j >> 5, n = j & 31;
    __nv_bfloat16 hi = __float2bfloat16_rn(wv);
    __nv_bfloat16 lo = __float2bfloat16_rn(wv - __bfloat162float(hi));
    size_t base = ((size_t)(r * 12 + chunk) * 2) * 4352 + n * 136 + k;
    d_Wbf[base] = hi;
    d_Wbf[base + 4352] = lo;
}

// ---------------- 1: setup ----------------
// blocks [0,64): fuse weights   [64,747): edge scatter   [747,833): node scatter
// [833,961): x hi/lo split      [961,1025): Wa hi/lo split
__global__ void __launch_bounds__(384) k_setup(
        const float* __restrict__ Wk, const float* __restrict__ bk,
        const float* __restrict__ Wq, const float* __restrict__ bq,
        const float* __restrict__ Wv, const float* __restrict__ bv,
        const float* __restrict__ pri, const float* __restrict__ Aatt,
        const float* __restrict__ Amsg, const float* __restrict__ Wa,
        const float* __restrict__ x,
        const int* __restrict__ ei, const int* __restrict__ ea,
        const int* __restrict__ tid_) {
    int b = blockIdx.x;
    int j = threadIdx.x;
    if (b < 64) {
        int r = b & 7, kc = b >> 3;
        int k0 = kc * 16;
        if (j < 256) {
            bool isK = j < 128;
            int c = j & 127;
            int h = c >> 4, d2 = c & 15;
            const float* M  = (isK ? Aatt : Amsg) + ((r * 8 + h) * 256) + d2;
            const float* Ws = (isK ? Wk : Wv) + r * 16384 + h * 16;
            for (int k = k0; k < k0 + 16; k++) {
                float s = 0.f;
                #pragma unroll
                for (int d = 0; d < 16; d++) s = fmaf(Ws[k * 128 + d], M[d * 16], s);
                store_wbf(r, k, j, s);
            }
            if (kc == 0) {
                const float* bs = (isK ? bk : bv) + r * 128 + h * 16;
                float s = 0.f;
                #pragma unroll
                for (int d = 0; d < 16; d++) s = fmaf(bs[d], M[d * 16], s);
                d_ball[r][j] = s;
            }
        } else {
            int c = j - 256;
            int h = c >> 4;
            float sc = pri[r * 8 + h] * 0.25f;
            for (int k = k0; k < k0 + 16; k++)
                store_wbf(r, k, j, Wq[r * 16384 + k * 128 + c] * sc);
            if (kc == 0) d_ball[r][j] = bq[r * 128 + c] * sc;
        }
    } else if (b < 747) {
        int e = (b - 64) * 384 + j;
        bool act = e < E_;
        int r = 0, srcv = 0, dstv = 0;
        if (act) { r = ea[e]; srcv = ei[e]; dstv = ei[E_ + e]; }
        unsigned amask = __ballot_sync(0xffffffffu, act);
        if (act) {
            unsigned mask = __match_any_sync(amask, r);
            int lane = j & 31;
            int leader = __ffs(mask) - 1;
            int prefix = __popc(mask & ((1u << lane) - 1));
            int base = 0;
            if (lane == leader) base = atomicAdd(&d_cursor8[r], __popc(mask));
            base = __shfl_sync(mask, base, leader);
            int pos = base + prefix;
            if (pos < CAPR) {
                d_ssrc[r * CAPR + pos] = srcv;
                d_sdst[r * CAPR + pos] = dstv;
            }
            atomicAdd(&d_cnt[dstv], 1);
        }
    } else if (b < 833) {
        int n = (b - 747) * 384 + j;
        if (n < N_) {
            int pos = atomicAdd(&d_cursorN8[tid_[n]], 1);
            if (pos < CAPN) d_snid[tid_[n] * CAPN + pos] = n;
        }
    } else if (b < 961) {
        // x split: float4 granularity
        for (int idx = (b - 833) * 384 + j; idx < N_ * C_ / 4; idx += 128 * 384) {
            float4 v = ((const float4*)x)[idx];
            __nv_bfloat162 ha = __floats2bfloat162_rn(v.x, v.y);
            __nv_bfloat162 hb = __floats2bfloat162_rn(v.z, v.w);
            __nv_bfloat162 la = __floats2bfloat162_rn(v.x - __bfloat162float(ha.x),
                                                      v.y - __bfloat162float(ha.y));
            __nv_bfloat162 lb = __floats2bfloat162_rn(v.z - __bfloat162float(hb.x),
                                                      v.w - __bfloat162float(hb.y));
            uint2 H, L;
            H.x = *(uint32_t*)&ha; H.y = *(uint32_t*)&hb;
            L.x = *(uint32_t*)&la; L.y = *(uint32_t*)&lb;
            ((uint2*)d_xhi)[idx] = H;
            ((uint2*)d_xlo)[idx] = L;
        }
    } else {
        int b2 = b - 961;
        int t = b2 & 7, kc = b2 >> 3;
        if (j < 128) {
            int n = j, chunk = n >> 5;
            for (int k = kc * 16; k < kc * 16 + 16; k++) {
                float wv = Wa[t * 16384 + k * 128 + n];
                __nv_bfloat16 hi = __float2bfloat16_rn(wv);
                __nv_bfloat16 lo = __float2bfloat16_rn(wv - __bfloat162float(hi));
                size_t base = ((size_t)(t * 4 + chunk) * 2) * 4352 + (n & 31) * 136 + k;
                d_Wabf[base] = hi;
                d_Wabf[base + 4352] = lo;
            }
        }
    }
}

// ---------------- 2: scan ----------------
__global__ void k_scan() {
    __shared__ int sums[1024];
    int tid = threadIdx.x;
    int base = tid * 32;
    int tot = 0;
    for (int i = 0; i < 32; i++) tot += d_cnt[base + i];
    sums[tid] = tot;
    __syncthreads();
    for (int off = 1; off < 1024; off <<= 1) {
        int v = (tid >= off) ? sums[tid - off] : 0;
        __syncthreads();
        sums[tid] += v;
        __syncthreads();
    }
    int run = sums[tid] - tot;
    for (int i = 0; i < 32; i++) { d_rowPtr[base + i] = run; run += d_cnt[base + i]; }
    if (tid == 1023) d_rowPtr[N_] = run;
}

// ---------------- 3: edge GEMM via mma.sync bf16 3-pass (PROFILED) ----------------
__global__ void __launch_bounds__(256, 1) k_edge_gemm() {
    int r = blockIdx.y, i = blockIdx.x;
    int tid = threadIdx.x, wid = tid >> 5, lane = tid & 31;
    int g = lane >> 2, t = lane & 3;

    __shared__ int s_cnt, s_gb, s_src[128], s_dst[128];
    __shared__ __align__(16) uint4 sB[2][1088];

    if (tid == 0) {
        int cnt = min(d_cursor8[r], CAPR);
        int gb = 0;
        #pragma unroll
        for (int q = 0; q < R_; q++) { int c = min(d_cursor8[q], CAPR); if (q < r) gb += c; }
        s_cnt = cnt; s_gb = gb;
    }
    __syncthreads();
    int cnt = s_cnt;
    if (i * 128 >= cnt) return;
    int count = min(128, cnt - i * 128);
    int gstart = s_gb + i * 128;
    int pstart = r * CAPR + i * 128;

    if (tid < 128) s_src[tid] = (i * 128 + tid < cnt) ? d_ssrc[pstart + tid] : 0;
    else {
        int m = tid - 128;
        s_dst[m] = (i * 128 + m < cnt) ? d_sdst[pstart + m] : 0;
    }

    {
        const uint4* w0 = (const uint4*)(d_Wbf + (size_t)(r * 12) * 8704);
        for (int idx = tid; idx < 1088; idx += 256) sB[0][idx] = w0[idx];
    }
    __syncthreads();

    int r0 = wid * 16 + g, r1 = r0 + 8;

    // A fragments: direct LDG of pre-split bf16x2
    uint32_t Ah[8][4], Al[8][4];
    {
        const uint32_t* ph0 = (const uint32_t*)d_xhi + (size_t)s_src[r0] * 64;
        const uint32_t* ph1 = (const uint32_t*)d_xhi + (size_t)s_src[r1] * 64;
        const uint32_t* pl0 = (const uint32_t*)d_xlo + (size_t)s_src[r0] * 64;
        const uint32_t* pl1 = (const uint32_t*)d_xlo + (size_t)s_src[r1] * 64;
        #pragma unroll
        for (int ks = 0; ks < 8; ks++) {
            Ah[ks][0] = ph0[ks * 8 + t];     Ah[ks][1] = ph1[ks * 8 + t];
            Ah[ks][2] = ph0[ks * 8 + t + 4]; Ah[ks][3] = ph1[ks * 8 + t + 4];
            Al[ks][0] = pl0[ks * 8 + t];     Al[ks][1] = pl1[ks * 8 + t];
            Al[ks][2] = pl0[ks * 8 + t + 4]; Al[ks][3] = pl1[ks * 8 + t + 4];
        }
    }

    const float* __restrict__ bb = d_ball[r];
    float kt[4][16];
    bool v0 = r0 < count, v1 = r1 < count;
    int slot0 = gstart + r0, slot1 = gstart + r1;

    #pragma unroll
    for (int c = 0; c < 12; c++) {
        int buf = c & 1;
        uint4 pf[5];
        if (c < 11) {
            const uint4* wn = (const uint4*)(d_Wbf + (size_t)(r * 12 + c + 1) * 8704);
            #pragma unroll
            for (int j = 0; j < 5; j++) {
                int idx = tid + 256 * j;
                if (idx < 1088) pf[j] = wn[idx];
            }
        }
        if (c == 8) {
            const uint32_t* ph0 = (const uint32_t*)d_xhi + (size_t)s_dst[r0] * 64;
            const uint32_t* ph1 = (const uint32_t*)d_xhi + (size_t)s_dst[r1] * 64;
            const uint32_t* pl0 = (const uint32_t*)d_xlo + (size_t)s_dst[r0] * 64;
            const uint32_t* pl1 = (const uint32_t*)d_xlo + (size_t)s_dst[r1] * 64;
            #pragma unroll
            for (int ks = 0; ks < 8; ks++) {
                Ah[ks][0] = ph0[ks * 8 + t];     Ah[ks][1] = ph1[ks * 8 + t];
                Ah[ks][2] = ph0[ks * 8 + t + 4]; Ah[ks][3] = ph1[ks * 8 + t + 4];
                Al[ks][0] = pl0[ks * 8 + t];     Al[ks][1] = pl1[ks * 8 + t];
                Al[ks][2] = pl0[ks * 8 + t + 4]; Al[ks][3] = pl1[ks * 8 + t + 4];
            }
        }

        float acc[16];
        #pragma unroll
        for (int j = 0; j < 16; j++) acc[j] = 0.f;

        const __nv_bfloat16* Bp = (const __nv_bfloat16*)sB[buf];
        #pragma unroll
        for (int ks = 0; ks < 8; ks++) {
            int kb = ks * 16 + 2 * t;
            #pragma unroll
            for (int nt = 0; nt < 4; nt++) {
                const __nv_bfloat16* bn = Bp + (nt * 8 + g) * 136 + kb;
                uint32_t b0h = *(const uint32_t*)bn;
                uint32_t b1h = *(const uint32_t*)(bn + 8);
                uint32_t b0l = *(const uint32_t*)(bn + 4352);
                uint32_t b1l = *(const uint32_t*)(bn + 4360);
                mma_bf16(&acc[nt * 4], Ah[ks], b0h, b1h);
                mma_bf16(&acc[nt * 4], Al[ks], b0h, b1h);
                mma_bf16(&acc[nt * 4], Ah[ks], b0l, b1l);
            }
        }

        #pragma unroll
        for (int nt = 0; nt < 4; nt++) {
            float bc0 = bb[c * 32 + nt * 8 + 2 * t];
            float bc1 = bb[c * 32 + nt * 8 + 2 * t + 1];
            acc[nt * 4 + 0] += bc0; acc[nt * 4 + 1] += bc1;
            acc[nt * 4 + 2] += bc0; acc[nt * 4 + 3] += bc1;
        }

        if (c < 4) {
            #pragma unroll
            for (int j = 0; j < 16; j++) kt[c][j] = acc[j];
        } else if (c < 8) {
            int cb = (c - 4) * 32;
            #pragma unroll
            for (int nt = 0; nt < 4; nt++) {
                int col = cb + nt * 8 + 2 * t;
                if (v0) *(float2*)&d_vt[(size_t)slot0 * C_ + col] =
                    make_float2(acc[nt * 4 + 0], acc[nt * 4 + 1]);
                if (v1) *(float2*)&d_vt[(size_t)slot1 * C_ + col] =
                    make_float2(acc[nt * 4 + 2], acc[nt * 4 + 3]);
            }
        } else {
            int cc = c - 8;
            int h0 = cc * 2;
            float p00 = acc[0] * kt[cc][0] + acc[1] * kt[cc][1]
                      + acc[4] * kt[cc][4] + acc[5] * kt[cc][5];
            float p10 = acc[2] * kt[cc][2] + acc[3] * kt[cc][3]
                      + acc[6] * kt[cc][6] + acc[7] * kt[cc][7];
            float p01 = acc[8] * kt[cc][8] + acc[9] * kt[cc][9]
                      + acc[12] * kt[cc][12] + acc[13] * kt[cc][13];
            float p11 = acc[10] * kt[cc][10] + acc[11] * kt[cc][11]
                      + acc[14] * kt[cc][14] + acc[15] * kt[cc][15];
            p00 += __shfl_xor_sync(0xffffffffu, p00, 1);
            p00 += __shfl_xor_sync(0xffffffffu, p00, 2);
            p10 += __shfl_xor_sync(0xffffffffu, p10, 1);
            p10 += __shfl_xor_sync(0xffffffffu, p10, 2);
            p01 += __shfl_xor_sync(0xffffffffu, p01, 1);
            p01 += __shfl_xor_sync(0xffffffffu, p01, 2);
            p11 += __shfl_xor_sync(0xffffffffu, p11, 1);
            p11 += __shfl_xor_sync(0xffffffffu, p11, 2);
            if (t == 0) {
                if (v0) {
                    d_att[(size_t)slot0 * 8 + h0] = p00;
                    d_att[(size_t)slot0 * 8 + h0 + 1] = p01;
                }
                if (v1) {
                    d_att[(size_t)slot1 * 8 + h0] = p10;
                    d_att[(size_t)slot1 * 8 + h0 + 1] = p11;
                }
            }
        }

        if (c < 11) {
            #pragma unroll
            for (int j = 0; j < 5; j++) {
                int idx = tid + 256 * j;
                if (idx < 1088) sB[buf ^ 1][idx] = pf[j];
            }
        }
        __syncthreads();
    }
}

// ---------------- 4: scatter compact slots by dst ----------------
__global__ void k_scatterD() {
    __shared__ int sb[R_ + 1];
    if (threadIdx.x < R_) sb[threadIdx.x + 1] = min(d_cursor8[threadIdx.x], CAPR);
    if (threadIdx.x == 0) sb[0] = 0;
    __syncthreads();
    if (threadIdx.x == 0) {
        #pragma unroll
        for (int q = 1; q <= R_; q++) sb[q] += sb[q - 1];
    }
    __syncthreads();
    int c = blockIdx.x * blockDim.x + threadIdx.x;
    if (c >= sb[R_]) return;
    int r = 0;
    #pragma unroll
    for (int q = 1; q < R_; q++) r += (c >= sb[q]);
    int padded = r * CAPR + (c - sb[r]);
    int dst = d_sdst[padded];
    int pos = d_rowPtr[dst] + atomicAdd(&d_cursor[dst], 1);
    d_bydst[pos] = c;
}

// ---------------- 5: aggregate (writes x0 as bf16 hi/lo) ----------------
__global__ void k_aggregate() {
    int warp = threadIdx.x >> 5;
    int lane = threadIdx.x & 31;
    int n = blockIdx.x * (blockDim.x >> 5) + warp;
    if (n >= N_) return;
    int s = d_rowPtr[n], eEnd = d_rowPtr[n + 1];
    int deg = eEnd - s;
    if (deg == 0) {
        #pragma unroll
        for (int j = 0; j < 4; j++) {
            d_x0hi[n * C_ + lane + 32 * j] = __float2bfloat16_rn(0.f);
            d_x0lo[n * C_ + lane + 32 * j] = __float2bfloat16_rn(0.f);
        }
        return;
    }
    int slot = lane >> 3, h = lane & 7;
    float m = -1e30f;
    for (int b = s; b < eEnd; b += 4) {
        int idx = b + slot;
        if (idx < eEnd) m = fmaxf(m, d_att[d_bydst[idx] * 8 + h]);
    }
    m = fmaxf(m, __shfl_xor_sync(0xffffffffu, m, 8));
    m = fmaxf(m, __shfl_xor_sync(0xffffffffu, m, 16));
    float den = 0.f;
    for (int b = s; b < eEnd; b += 4) {
        int idx = b + slot;
        if (idx < eEnd) den += expf(d_att[d_bydst[idx] * 8 + h] - m);
    }
    den += __shfl_xor_sync(0xffffffffu, den, 8);
    den += __shfl_xor_sync(0xffffffffu, den, 16);
    int hb = lane >> 4;
    float mj[4], rj[4];
    #pragma unroll
    for (int j = 0; j < 4; j++) {
        int hh = hb + 2 * j;
        mj[j] = __shfl_sync(0xffffffffu, m, hh);
        rj[j] = 1.f / __shfl_sync(0xffffffffu, den, hh);
    }
    float acc[4] = {0.f, 0.f, 0.f, 0.f};
    for (int idx = s; idx < eEnd; idx++) {
        int e = d_bydst[idx];
        const float* ar = &d_att[e * 8];
        const float* vr = &d_vt[(size_t)e * C_];
        #pragma unroll
        for (int j = 0; j < 4; j++) {
            float w = expf(ar[hb + 2 * j] - mj[j]) * rj[j];
            acc[j] = fmaf(w, vr[lane + 32 * j], acc[j]);
        }
    }
    float inv = 1.f / (float)deg;
    #pragma unroll
    for (int j = 0; j < 4; j++) {
        float val = acc[j] * inv;
        __nv_bfloat16 h2 = __float2bfloat16_rn(val);
        __nv_bfloat16 l2 = __float2bfloat16_rn(val - __bfloat162float(h2));
        d_x0hi[n * C_ + lane + 32 * j] = h2;
        d_x0lo[n * C_ + lane + 32 * j] = l2;
    }
}

// ---------------- 6: out GEMM (mma) + residual + LN ----------------
__global__ void __launch_bounds__(256, 1) k_out(const float* __restrict__ x,
                                                const float* __restrict__ ba,
                                                const float* __restrict__ skipv,
                                                const float* __restrict__ gamma,
                                                const float* __restrict__ beta,
                                                float* __restrict__ out) {
    int t = blockIdx.y, i = blockIdx.x;
    int tid = threadIdx.x, wid = tid >> 5, lane = tid & 31;
    int g = lane >> 2, tq = lane & 3;

    int cntT = min(d_cursorN8[t], CAPN);
    if (i * 128 >= cntT) return;
    int count = min(128, cntT - i * 128);
    int start = t * CAPN + i * 128;

    __shared__ int s_nid[128];
    __shared__ __align__(16) uint4 sB[2][1088];

    if (tid < 128) s_nid[tid] = (i * 128 + tid < cntT) ? d_snid[start + tid] : 0;
    {
        const uint4* w0 = (const uint4*)(d_Wabf + (size_t)(t * 4) * 8704);
        for (int idx = tid; idx < 1088; idx += 256) sB[0][idx] = w0[idx];
    }
    __syncthreads();

    int r0 = wid * 16 + g, r1 = r0 + 8;
    int nid0 = s_nid[r0], nid1 = s_nid[r1];

    uint32_t Ah[8][4], Al[8][4];
    {
        const uint32_t* ph0 = (const uint32_t*)d_x0hi + (size_t)nid0 * 64;
        const uint32_t* ph1 = (const uint32_t*)d_x0hi + (size_t)nid1 * 64;
        const uint32_t* pl0 = (const uint32_t*)d_x0lo + (size_t)nid0 * 64;
        const uint32_t* pl1 = (const uint32_t*)d_x0lo + (size_t)nid1 * 64;
        #pragma unroll
        for (int ks = 0; ks < 8; ks++) {
            Ah[ks][0] = ph0[ks * 8 + tq];     Ah[ks][1] = ph1[ks * 8 + tq];
            Ah[ks][2] = ph0[ks * 8 + tq + 4]; Ah[ks][3] = ph1[ks * 8 + tq + 4];
            Al[ks][0] = pl0[ks * 8 + tq];     Al[ks][1] = pl1[ks * 8 + tq];
            Al[ks][2] = pl0[ks * 8 + tq + 4]; Al[ks][3] = pl1[ks * 8 + tq + 4];
        }
    }

    float vout[2][32];   // [row][chunk*8 + nt*2 + u]

    #pragma unroll
    for (int c = 0; c < 4; c++) {
        int buf = c & 1;
        uint4 pf[5];
        if (c < 3) {
            const uint4* wn = (const uint4*)(d_Wabf + (size_t)(t * 4 + c + 1) * 8704);
            #pragma unroll
            for (int j = 0; j < 5; j++) {
                int idx = tid + 256 * j;
                if (idx < 1088) pf[j] = wn[idx];
            }
        }
        float acc[16];
        #pragma unroll
        for (int j = 0; j < 16; j++) acc[j] = 0.f;
        const __nv_bfloat16* Bp = (const __nv_bfloat16*)sB[buf];
        #pragma unroll
        for (int ks = 0; ks < 8; ks++) {
            int kb = ks * 16 + 2 * tq;
            #pragma unroll
            for (int nt = 0; nt < 4; nt++) {
                const __nv_bfloat16* bn = Bp + (nt * 8 + g) * 136 + kb;
                uint32_t b0h = *(const uint32_t*)bn;
                uint32_t b1h = *(const uint32_t*)(bn + 8);
                uint32_t b0l = *(const uint32_t*)(bn + 4352);
                uint32_t b1l = *(const uint32_t*)(bn + 4360);
                mma_bf16(&acc[nt * 4], Ah[ks], b0h, b1h);
                mma_bf16(&acc[nt * 4], Al[ks], b0h, b1h);
                mma_bf16(&acc[nt * 4], Ah[ks], b0l, b1l);
            }
        }
        #pragma unroll
        for (int nt = 0; nt < 4; nt++) {
            int col = c * 32 + nt * 8 + 2 * tq;
            float bc0 = ba[t * 128 + col];
            float bc1 = ba[t * 128 + col + 1];
            vout[0][c * 8 + nt * 2 + 0] = acc[nt * 4 + 0] + bc0;
            vout[0][c * 8 + nt * 2 + 1] = acc[nt * 4 + 1] + bc1;
            vout[1][c * 8 + nt * 2 + 0] = acc[nt * 4 + 2] + bc0;
            vout[1][c * 8 + nt * 2 + 1] = acc[nt * 4 + 3] + bc1;
        }
        if (c < 3) {
            #pragma unroll
            for (int j = 0; j < 5; j++) {
                int idx = tid + 256 * j;
                if (idx < 1088) sB[buf ^ 1][idx] = pf[j];
            }
        }
        __syncthreads();
    }

    float alpha = 1.f / (1.f + expf(-skipv[t]));
    float onema = 1.f - alpha;

    #pragma unroll
    for (int rr = 0; rr < 2; rr++) {
        int row = (rr == 0) ? r0 : r1;
        int nid = (rr == 0) ? nid0 : nid1;
        bool valid = row < count;
        float s1 = 0.f, s2 = 0.f;
        float v[32];
        #pragma unroll
        for (int c = 0; c < 4; c++)
            #pragma unroll
            for (int nt = 0; nt < 4; nt++) {
                int col = c * 32 + nt * 8 + 2 * tq;
                float2 rx = *(const float2*)(x + (size_t)nid * C_ + col);
                float v0 = alpha * vout[rr][c * 8 + nt * 2 + 0] + onema * rx.x;
                float v1 = alpha * vout[rr][c * 8 + nt * 2 + 1] + onema * rx.y;
                v[c * 8 + nt * 2 + 0] = v0;
                v[c * 8 + nt * 2 + 1] = v1;
                s1 += v0 + v1;
                s2 = fmaf(v0, v0, s2);
                s2 = fmaf(v1, v1, s2);
            }
        s1 += __shfl_xor_sync(0xffffffffu, s1, 1);
        s1 += __shfl_xor_sync(0xffffffffu, s1, 2);
        s2 += __shfl_xor_sync(0xffffffffu, s2, 1);
        s2 += __shfl_xor_sync(0xffffffffu, s2, 2);
        float mu = s1 * (1.f / 128.f);
        float var = s2 * (1.f / 128.f) - mu * mu;
        float rstd = rsqrtf(var + 1e-5f);
        if (valid) {
            #pragma unroll
            for (int c = 0; c < 4; c++)
                #pragma unroll
                for (int nt = 0; nt < 4; nt++) {
                    int col = c * 32 + nt * 8 + 2 * tq;
                    float2 o;
                    o.x = (v[c * 8 + nt * 2 + 0] - mu) * rstd * gamma[t * 128 + col]
                        + beta[t * 128 + col];
                    o.y = (v[c * 8 + nt * 2 + 1] - mu) * rstd * gamma[t * 128 + col + 1]
                        + beta[t * 128 + col + 1];
                    *(float2*)&out[(size_t)nid * C_ + col] = o;
                }
        }
    }
}

// ---------------- launch ----------------
extern "C" void kernel_launch(void* const* d_in, const int* in_sizes, int n_in,
                              void* d_out, int out_size) {
    const float* x      = (const float*)d_in[0];
    const int*   typeId = (const int*)d_in[1];
    const int*   ei     = (const int*)d_in[2];
    const int*   ea     = (const int*)d_in[3];
    const float* Wk     = (const float*)d_in[4];
    const float* bk     = (const float*)d_in[5];
    const float* Wq     = (const float*)d_in[6];
    const float* bq     = (const float*)d_in[7];
    const float* Wv     = (const float*)d_in[8];
    const float* bv     = (const float*)d_in[9];
    const float* Wa     = (const float*)d_in[10];
    const float* ba     = (const float*)d_in[11];
    const float* pri    = (const float*)d_in[12];
    const float* Aatt   = (const float*)d_in[13];
    const float* Amsg   = (const float*)d_in[14];
    const float* skipv  = (const float*)d_in[15];
    const float* gamma  = (const float*)d_in[16];
    const float* beta   = (const float*)d_in[17];
    float* out = (float*)d_out;

    k_zero<<<(N_ + 255) / 256, 256>>>();                                       // 0
    k_setup<<<1025, 384>>>(Wk, bk, Wq, bq, Wv, bv, pri, Aatt, Amsg, Wa, x,
                           ei, ea, typeId);                                    // 1
    k_scan<<<1, 1024>>>();                                                     // 2
    k_edge_gemm<<<dim3(CAPR / 128, R_), 256>>>();                              // 3 <- profiled
    k_scatterD<<<E_ / 256, 256>>>();                                           // 4
    k_aggregate<<<N_ / 8, 256>>>();                                            // 5
    k_out<<<dim3(CAPN / 128, T_), 256>>>(x, ba, skipv, gamma, beta, out);      // 6
}

// round 10
// speedup vs baseline: 1.7524x; 1.0402x over previous
#include <cuda_runtime.h>
#include <cuda_bf16.h>
#include <math.h>
#include <stdint.h>

#define N_ 32768
#define E_ 262144
#define C_ 128
#define H_ 8
#define R_ 8
#define T_ 8
#define CAPR 36864
#define CAPN 4608

// ---------------- mma / ldmatrix / cp.async helpers ----------------
__device__ __forceinline__ void mma_bf16(float* c, const uint32_t* a, uint32_t b0, uint32_t b1) {
    asm volatile(
        "mma.sync.aligned.m16n8k16.row.col.f32.bf16.bf16.f32 "
        "{%0,%1,%2,%3}, {%4,%5,%6,%7}, {%8,%9}, {%0,%1,%2,%3};"
        : "+f"(c[0]), "+f"(c[1]), "+f"(c[2]), "+f"(c[3])
        : "r"(a[0]), "r"(a[1]), "r"(a[2]), "r"(a[3]), "r"(b0), "r"(b1));
}
__device__ __forceinline__ uint32_t smem_u32(const void* p) {
    uint32_t a;
    asm("{ .reg .u64 t; cvta.to.shared.u64 t, %1; cvt.u32.u64 %0, t; }" : "=r"(a) : "l"(p));
    return a;
}
__device__ __forceinline__ void ldmx4(uint32_t& r0, uint32_t& r1, uint32_t& r2, uint32_t& r3,
                                      uint32_t addr) {
    asm volatile("ldmatrix.sync.aligned.m8n8.x4.shared.b16 {%0,%1,%2,%3}, [%4];"
                 : "=r"(r0), "=r"(r1), "=r"(r2), "=r"(r3) : "r"(addr));
}
__device__ __forceinline__ void cp16(uint32_t d, const void* s) {
    asm volatile("cp.async.cg.shared.global [%0], [%1], 16;" :: "r"(d), "l"(s));
}
#define CP_COMMIT() asm volatile("cp.async.commit_group;" ::: "memory")
#define CP_WAIT0()  asm volatile("cp.async.wait_group 0;" ::: "memory")

// ---------------- scratch ----------------
__device__ __nv_bfloat16 d_Wbf[R_ * 12 * 2 * 4352];
__device__ __nv_bfloat16 d_Wabf[T_ * 4 * 2 * 4352];
__device__ __nv_bfloat16 d_xhi[N_ * C_];
__device__ __nv_bfloat16 d_xlo[N_ * C_];
__device__ __nv_bfloat16 d_x0hi[N_ * C_];
__device__ __nv_bfloat16 d_x0lo[N_ * C_];
__device__ float d_ball[R_][384];
__device__ int   d_cursor8[R_];
__device__ int   d_ssrc[R_ * CAPR];
__device__ int   d_sdst[R_ * CAPR];
__device__ float d_att[E_ * H_];
__device__ float d_vt[E_ * C_];
__device__ int   d_cnt[N_];
__device__ int   d_rowPtr[N_ + 1];
__device__ int   d_cursor[N_];
__device__ int   d_bydst[E_];
__device__ int   d_cursorN8[T_];
__device__ int   d_snid[T_ * CAPN];

// ---------------- 0: zero ----------------
__global__ void k_zero() {
    int i = blockIdx.x * blockDim.x + threadIdx.x;
    if (i < N_) { d_cnt[i] = 0; d_cursor[i] = 0; }
    if (i < R_) { d_cursor8[i] = 0; d_cursorN8[i] = 0; }
}

__device__ __forceinline__ void store_wbf(int r, int k, int j, float wv) {
    int chunk = j >> 5, n = j & 31;
    __nv_bfloat16 hi = __float2bfloat16_rn(wv);
    __nv_bfloat16 lo = __float2bfloat16_rn(wv - __bfloat162float(hi));
    size_t base = ((size_t)(r * 12 + chunk) * 2) * 4352 + n * 136 + k;
    d_Wbf[base] = hi;
    d_Wbf[base + 4352] = lo;
}

// ---------------- 1: setup ----------------
__global__ void __launch_bounds__(384) k_setup(
        const float* __restrict__ Wk, const float* __restrict__ bk,
        const float* __restrict__ Wq, const float* __restrict__ bq,
        const float* __restrict__ Wv, const float* __restrict__ bv,
        const float* __restrict__ pri, const float* __restrict__ Aatt,
        const float* __restrict__ Amsg, const float* __restrict__ Wa,
        const float* __restrict__ x,
        const int* __restrict__ ei, const int* __restrict__ ea,
        const int* __restrict__ tid_) {
    int b = blockIdx.x;
    int j = threadIdx.x;
    if (b < 64) {
        int r = b & 7, kc = b >> 3;
        int k0 = kc * 16;
        if (j < 256) {
            bool isK = j < 128;
            int c = j & 127;
            int h = c >> 4, d2 = c & 15;
            const float* M  = (isK ? Aatt : Amsg) + ((r * 8 + h) * 256) + d2;
            const float* Ws = (isK ? Wk : Wv) + r * 16384 + h * 16;
            for (int k = k0; k < k0 + 16; k++) {
                float s = 0.f;
                #pragma unroll
                for (int d = 0; d < 16; d++) s = fmaf(Ws[k * 128 + d], M[d * 16], s);
                store_wbf(r, k, j, s);
            }
            if (kc == 0) {
                const float* bs = (isK ? bk : bv) + r * 128 + h * 16;
                float s = 0.f;
                #pragma unroll
                for (int d = 0; d < 16; d++) s = fmaf(bs[d], M[d * 16], s);
                d_ball[r][j] = s;
            }
        } else {
            int c = j - 256;
            int h = c >> 4;
            float sc = pri[r * 8 + h] * 0.25f;
            for (int k = k0; k < k0 + 16; k++)
                store_wbf(r, k, j, Wq[r * 16384 + k * 128 + c] * sc);
            if (kc == 0) d_ball[r][j] = bq[r * 128 + c] * sc;
        }
    } else if (b < 747) {
        int e = (b - 64) * 384 + j;
        bool act = e < E_;
        int r = 0, srcv = 0, dstv = 0;
        if (act) { r = ea[e]; srcv = ei[e]; dstv = ei[E_ + e]; }
        unsigned amask = __ballot_sync(0xffffffffu, act);
        if (act) {
            unsigned mask = __match_any_sync(amask, r);
            int lane = j & 31;
            int leader = __ffs(mask) - 1;
            int prefix = __popc(mask & ((1u << lane) - 1));
            int base = 0;
            if (lane == leader) base = atomicAdd(&d_cursor8[r], __popc(mask));
            base = __shfl_sync(mask, base, leader);
            int pos = base + prefix;
            if (pos < CAPR) {
                d_ssrc[r * CAPR + pos] = srcv;
                d_sdst[r * CAPR + pos] = dstv;
            }
            atomicAdd(&d_cnt[dstv], 1);
        }
    } else if (b < 833) {
        int n = (b - 747) * 384 + j;
        if (n < N_) {
            int pos = atomicAdd(&d_cursorN8[tid_[n]], 1);
            if (pos < CAPN) d_snid[tid_[n] * CAPN + pos] = n;
        }
    } else if (b < 961) {
        for (int idx = (b - 833) * 384 + j; idx < N_ * C_ / 4; idx += 128 * 384) {
            float4 v = ((const float4*)x)[idx];
            __nv_bfloat162 ha = __floats2bfloat162_rn(v.x, v.y);
            __nv_bfloat162 hb = __floats2bfloat162_rn(v.z, v.w);
            __nv_bfloat162 la = __floats2bfloat162_rn(v.x - __bfloat162float(ha.x),
                                                      v.y - __bfloat162float(ha.y));
            __nv_bfloat162 lb = __floats2bfloat162_rn(v.z - __bfloat162float(hb.x),
                                                      v.w - __bfloat162float(hb.y));
            uint2 H, L;
            H.x = *(uint32_t*)&ha; H.y = *(uint32_t*)&hb;
            L.x = *(uint32_t*)&la; L.y = *(uint32_t*)&lb;
            ((uint2*)d_xhi)[idx] = H;
            ((uint2*)d_xlo)[idx] = L;
        }
    } else {
        int b2 = b - 961;
        int t = b2 & 7, kc = b2 >> 3;
        if (j < 128) {
            int n = j, chunk = n >> 5;
            for (int k = kc * 16; k < kc * 16 + 16; k++) {
                float wv = Wa[t * 16384 + k * 128 + n];
                __nv_bfloat16 hi = __float2bfloat16_rn(wv);
                __nv_bfloat16 lo = __float2bfloat16_rn(wv - __bfloat162float(hi));
                size_t base = ((size_t)(t * 4 + chunk) * 2) * 4352 + (n & 31) * 136 + k;
                d_Wabf[base] = hi;
                d_Wabf[base + 4352] = lo;
            }
        }
    }
}

// ---------------- 2: scan ----------------
__global__ void k_scan() {
    __shared__ int sums[1024];
    int tid = threadIdx.x;
    int base = tid * 32;
    int tot = 0;
    for (int i = 0; i < 32; i++) tot += d_cnt[base + i];
    sums[tid] = tot;
    __syncthreads();
    for (int off = 1; off < 1024; off <<= 1) {
        int v = (tid >= off) ? sums[tid - off] : 0;
        __syncthreads();
        sums[tid] += v;
        __syncthreads();
    }
    int run = sums[tid] - tot;
    for (int i = 0; i < 32; i++) { d_rowPtr[base + i] = run; run += d_cnt[base + i]; }
    if (tid == 1023) d_rowPtr[N_] = run;
}

// ---------------- 3: edge GEMM via mma.sync bf16 3-pass + ldmatrix + cp.async ----------------
__global__ void __launch_bounds__(256, 1) k_edge_gemm() {
    int r = blockIdx.y, i = blockIdx.x;
    int tid = threadIdx.x, wid = tid >> 5, lane = tid & 31;
    int g = lane >> 2, t = lane & 3;

    __shared__ int s_cnt, s_gb, s_src[128], s_dst[128];
    __shared__ __align__(16) uint4 sB[2][1088];

    if (tid == 0) {
        int cnt = min(d_cursor8[r], CAPR);
        int gb = 0;
        #pragma unroll
        for (int q = 0; q < R_; q++) { int c = min(d_cursor8[q], CAPR); if (q < r) gb += c; }
        s_cnt = cnt; s_gb = gb;
    }
    __syncthreads();
    int cnt = s_cnt;
    if (i * 128 >= cnt) return;
    int count = min(128, cnt - i * 128);
    int gstart = s_gb + i * 128;
    int pstart = r * CAPR + i * 128;

    if (tid < 128) s_src[tid] = (i * 128 + tid < cnt) ? d_ssrc[pstart + tid] : 0;
    else {
        int m = tid - 128;
        s_dst[m] = (i * 128 + m < cnt) ? d_sdst[pstart + m] : 0;
    }

    uint32_t sB_u32 = smem_u32(sB);
    {
        const uint4* w0 = (const uint4*)(d_Wbf + (size_t)(r * 12) * 8704);
        for (int idx = tid; idx < 1088; idx += 256) cp16(sB_u32 + idx * 16, w0 + idx);
        CP_COMMIT();
        CP_WAIT0();
    }
    __syncthreads();

    int r0 = wid * 16 + g, r1 = r0 + 8;

    // ldmatrix per-lane address components: q8 = matrix slot, i8 = row within matrix
    int i8 = lane & 7, q8 = lane >> 3;
    uint32_t rowL0 = (uint32_t)(((q8 >> 1) * 8 + i8) * 272 + (q8 & 1) * 16);  // nt0/nt1
    // nt2/nt3 = rowL0 + 16 rows * 272 = +4352; lo component = +8704

    // A fragments
    uint32_t Ah[8][4], Al[8][4];
    {
        const uint32_t* ph0 = (const uint32_t*)d_xhi + (size_t)s_src[r0] * 64;
        const uint32_t* ph1 = (const uint32_t*)d_xhi + (size_t)s_src[r1] * 64;
        const uint32_t* pl0 = (const uint32_t*)d_xlo + (size_t)s_src[r0] * 64;
        const uint32_t* pl1 = (const uint32_t*)d_xlo + (size_t)s_src[r1] * 64;
        #pragma unroll
        for (int ks = 0; ks < 8; ks++) {
            Ah[ks][0] = ph0[ks * 8 + t];     Ah[ks][1] = ph1[ks * 8 + t];
            Ah[ks][2] = ph0[ks * 8 + t + 4]; Ah[ks][3] = ph1[ks * 8 + t + 4];
            Al[ks][0] = pl0[ks * 8 + t];     Al[ks][1] = pl1[ks * 8 + t];
            Al[ks][2] = pl0[ks * 8 + t + 4]; Al[ks][3] = pl1[ks * 8 + t + 4];
        }
    }

    const float* __restrict__ bb = d_ball[r];
    float kt[4][16];
    bool v0 = r0 < count, v1 = r1 < count;
    int slot0 = gstart + r0, slot1 = gstart + r1;

    #pragma unroll
    for (int c = 0; c < 12; c++) {
        int buf = c & 1;
        uint32_t bufbase = sB_u32 + buf * 17408;
        // prefetch chunk c+1 into other buffer (overlaps compute)
        if (c < 11) {
            const uint4* wn = (const uint4*)(d_Wbf + (size_t)(r * 12 + c + 1) * 8704);
            uint32_t dstb = sB_u32 + (buf ^ 1) * 17408;
            for (int idx = tid; idx < 1088; idx += 256) cp16(dstb + idx * 16, wn + idx);
            CP_COMMIT();
        }
        if (c == 8) {
            const uint32_t* ph0 = (const uint32_t*)d_xhi + (size_t)s_dst[r0] * 64;
            const uint32_t* ph1 = (const uint32_t*)d_xhi + (size_t)s_dst[r1] * 64;
            const uint32_t* pl0 = (const uint32_t*)d_xlo + (size_t)s_dst[r0] * 64;
            const uint32_t* pl1 = (const uint32_t*)d_xlo + (size_t)s_dst[r1] * 64;
            #pragma unroll
            for (int ks = 0; ks < 8; ks++) {
                Ah[ks][0] = ph0[ks * 8 + t];     Ah[ks][1] = ph1[ks * 8 + t];
                Ah[ks][2] = ph0[ks * 8 + t + 4]; Ah[ks][3] = ph1[ks * 8 + t + 4];
                Al[ks][0] = pl0[ks * 8 + t];     Al[ks][1] = pl1[ks * 8 + t];
                Al[ks][2] = pl0[ks * 8 + t + 4]; Al[ks][3] = pl1[ks * 8 + t + 4];
            }
        }

        float acc[16];
        #pragma unroll
        for (int j = 0; j < 16; j++) acc[j] = 0.f;

        #pragma unroll
        for (int ks = 0; ks < 8; ks++) {
            uint32_t kof = 32u * ks;
            uint32_t h0[4], h1[4], l0[4], l1[4];
            ldmx4(h0[0], h0[1], h0[2], h0[3], bufbase + rowL0 + kof);
            ldmx4(h1[0], h1[1], h1[2], h1[3], bufbase + rowL0 + 4352 + kof);
            ldmx4(l0[0], l0[1], l0[2], l0[3], bufbase + rowL0 + 8704 + kof);
            ldmx4(l1[0], l1[1], l1[2], l1[3], bufbase + rowL0 + 13056 + kof);
            mma_bf16(&acc[0],  Ah[ks], h0[0], h0[1]);
            mma_bf16(&acc[0],  Al[ks], h0[0], h0[1]);
            mma_bf16(&acc[0],  Ah[ks], l0[0], l0[1]);
            mma_bf16(&acc[4],  Ah[ks], h0[2], h0[3]);
            mma_bf16(&acc[4],  Al[ks], h0[2], h0[3]);
            mma_bf16(&acc[4],  Ah[ks], l0[2], l0[3]);
            mma_bf16(&acc[8],  Ah[ks], h1[0], h1[1]);
            mma_bf16(&acc[8],  Al[ks], h1[0], h1[1]);
            mma_bf16(&acc[8],  Ah[ks], l1[0], l1[1]);
            mma_bf16(&acc[12], Ah[ks], h1[2], h1[3]);
            mma_bf16(&acc[12], Al[ks], h1[2], h1[3]);
            mma_bf16(&acc[12], Ah[ks], l1[2], l1[3]);
        }

        #pragma unroll
        for (int nt = 0; nt < 4; nt++) {
            float bc0 = bb[c * 32 + nt * 8 + 2 * t];
            float bc1 = bb[c * 32 + nt * 8 + 2 * t + 1];
            acc[nt * 4 + 0] += bc0; acc[nt * 4 + 1] += bc1;
            acc[nt * 4 + 2] += bc0; acc[nt * 4 + 3] += bc1;
        }

        if (c < 4) {
            #pragma unroll
            for (int j = 0; j < 16; j++) kt[c][j] = acc[j];
        } else if (c < 8) {
            int cb = (c - 4) * 32;
            #pragma unroll
            for (int nt = 0; nt < 4; nt++) {
                int col = cb + nt * 8 + 2 * t;
                if (v0) *(float2*)&d_vt[(size_t)slot0 * C_ + col] =
                    make_float2(acc[nt * 4 + 0], acc[nt * 4 + 1]);
                if (v1) *(float2*)&d_vt[(size_t)slot1 * C_ + col] =
                    make_float2(acc[nt * 4 + 2], acc[nt * 4 + 3]);
            }
        } else {
            int cc = c - 8;
            int h0c = cc * 2;
            float p00 = acc[0] * kt[cc][0] + acc[1] * kt[cc][1]
                      + acc[4] * kt[cc][4] + acc[5] * kt[cc][5];
            float p10 = acc[2] * kt[cc][2] + acc[3] * kt[cc][3]
                      + acc[6] * kt[cc][6] + acc[7] * kt[cc][7];
            float p01 = acc[8] * kt[cc][8] + acc[9] * kt[cc][9]
                      + acc[12] * kt[cc][12] + acc[13] * kt[cc][13];
            float p11 = acc[10] * kt[cc][10] + acc[11] * kt[cc][11]
                      + acc[14] * kt[cc][14] + acc[15] * kt[cc][15];
            p00 += __shfl_xor_sync(0xffffffffu, p00, 1);
            p00 += __shfl_xor_sync(0xffffffffu, p00, 2);
            p10 += __shfl_xor_sync(0xffffffffu, p10, 1);
            p10 += __shfl_xor_sync(0xffffffffu, p10, 2);
            p01 += __shfl_xor_sync(0xffffffffu, p01, 1);
            p01 += __shfl_xor_sync(0xffffffffu, p01, 2);
            p11 += __shfl_xor_sync(0xffffffffu, p11, 1);
            p11 += __shfl_xor_sync(0xffffffffu, p11, 2);
            if (t == 0) {
                if (v0) {
                    d_att[(size_t)slot0 * 8 + h0c] = p00;
                    d_att[(size_t)slot0 * 8 + h0c + 1] = p01;
                }
                if (v1) {
                    d_att[(size_t)slot1 * 8 + h0c] = p10;
                    d_att[(size_t)slot1 * 8 + h0c + 1] = p11;
                }
            }
        }

        if (c < 11) CP_WAIT0();
        __syncthreads();
    }
}

// ---------------- 4: scatter compact slots by dst ----------------
__global__ void k_scatterD() {
    __shared__ int sb[R_ + 1];
    if (threadIdx.x < R_) sb[threadIdx.x + 1] = min(d_cursor8[threadIdx.x], CAPR);
    if (threadIdx.x == 0) sb[0] = 0;
    __syncthreads();
    if (threadIdx.x == 0) {
        #pragma unroll
        for (int q = 1; q <= R_; q++) sb[q] += sb[q - 1];
    }
    __syncthreads();
    int c = blockIdx.x * blockDim.x + threadIdx.x;
    if (c >= sb[R_]) return;
    int r = 0;
    #pragma unroll
    for (int q = 1; q < R_; q++) r += (c >= sb[q]);
    int padded = r * CAPR + (c - sb[r]);
    int dst = d_sdst[padded];
    int pos = d_rowPtr[dst] + atomicAdd(&d_cursor[dst], 1);
    d_bydst[pos] = c;
}

// ---------------- 5: aggregate (writes x0 as bf16 hi/lo) ----------------
__global__ void k_aggregate() {
    int warp = threadIdx.x >> 5;
    int lane = threadIdx.x & 31;
    int n = blockIdx.x * (blockDim.x >> 5) + warp;
    if (n >= N_) return;
    int s = d_rowPtr[n], eEnd = d_rowPtr[n + 1];
    int deg = eEnd - s;
    if (deg == 0) {
        #pragma unroll
        for (int j = 0; j < 4; j++) {
            d_x0hi[n * C_ + lane + 32 * j] = __float2bfloat16_rn(0.f);
            d_x0lo[n * C_ + lane + 32 * j] = __float2bfloat16_rn(0.f);
        }
        return;
    }
    int slot = lane >> 3, h = lane & 7;
    float m = -1e30f;
    for (int b = s; b < eEnd; b += 4) {
        int idx = b + slot;
        if (idx < eEnd) m = fmaxf(m, d_att[d_bydst[idx] * 8 + h]);
    }
    m = fmaxf(m, __shfl_xor_sync(0xffffffffu, m, 8));
    m = fmaxf(m, __shfl_xor_sync(0xffffffffu, m, 16));
    float den = 0.f;
    for (int b = s; b < eEnd; b += 4) {
        int idx = b + slot;
        if (idx < eEnd) den += expf(d_att[d_bydst[idx] * 8 + h] - m);
    }
    den += __shfl_xor_sync(0xffffffffu, den, 8);
    den += __shfl_xor_sync(0xffffffffu, den, 16);
    int hb = lane >> 4;
    float mj[4], rj[4];
    #pragma unroll
    for (int j = 0; j < 4; j++) {
        int hh = hb + 2 * j;
        mj[j] = __shfl_sync(0xffffffffu, m, hh);
        rj[j] = 1.f / __shfl_sync(0xffffffffu, den, hh);
    }
    float acc[4] = {0.f, 0.f, 0.f, 0.f};
    for (int idx = s; idx < eEnd; idx++) {
        int e = d_bydst[idx];
        const float* ar = &d_att[e * 8];
        const float* vr = &d_vt[(size_t)e * C_];
        #pragma unroll
        for (int j = 0; j < 4; j++) {
            float w = expf(ar[hb + 2 * j] - mj[j]) * rj[j];
            acc[j] = fmaf(w, vr[lane + 32 * j], acc[j]);
        }
    }
    float inv = 1.f / (float)deg;
    #pragma unroll
    for (int j = 0; j < 4; j++) {
        float val = acc[j] * inv;
        __nv_bfloat16 h2 = __float2bfloat16_rn(val);
        __nv_bfloat16 l2 = __float2bfloat16_rn(val - __bfloat162float(h2));
        d_x0hi[n * C_ + lane + 32 * j] = h2;
        d_x0lo[n * C_ + lane + 32 * j] = l2;
    }
}

// ---------------- 6: out GEMM (mma + ldmatrix + cp.async) + residual + LN ----------------
__global__ void __launch_bounds__(256, 1) k_out(const float* __restrict__ x,
                                                const float* __restrict__ ba,
                                                const float* __restrict__ skipv,
                                                const float* __restrict__ gamma,
                                                const float* __restrict__ beta,
                                                float* __restrict__ out) {
    int t = blockIdx.y, i = blockIdx.x;
    int tid = threadIdx.x, wid = tid >> 5, lane = tid & 31;
    int g = lane >> 2, tq = lane & 3;

    int cntT = min(d_cursorN8[t], CAPN);
    if (i * 128 >= cntT) return;
    int count = min(128, cntT - i * 128);
    int start = t * CAPN + i * 128;

    __shared__ int s_nid[128];
    __shared__ __align__(16) uint4 sB[2][1088];

    if (tid < 128) s_nid[tid] = (i * 128 + tid < cntT) ? d_snid[start + tid] : 0;
    uint32_t sB_u32 = smem_u32(sB);
    {
        const uint4* w0 = (const uint4*)(d_Wabf + (size_t)(t * 4) * 8704);
        for (int idx = tid; idx < 1088; idx += 256) cp16(sB_u32 + idx * 16, w0 + idx);
        CP_COMMIT();
        CP_WAIT0();
    }
    __syncthreads();

    int r0 = wid * 16 + g, r1 = r0 + 8;
    int nid0 = s_nid[r0], nid1 = s_nid[r1];

    int i8 = lane & 7, q8 = lane >> 3;
    uint32_t rowL0 = (uint32_t)(((q8 >> 1) * 8 + i8) * 272 + (q8 & 1) * 16);

    uint32_t Ah[8][4], Al[8][4];
    {
        const uint32_t* ph0 = (const uint32_t*)d_x0hi + (size_t)nid0 * 64;
        const uint32_t* ph1 = (const uint32_t*)d_x0hi + (size_t)nid1 * 64;
        const uint32_t* pl0 = (const uint32_t*)d_x0lo + (size_t)nid0 * 64;
        const uint32_t* pl1 = (const uint32_t*)d_x0lo + (size_t)nid1 * 64;
        #pragma unroll
        for (int ks = 0; ks < 8; ks++) {
            Ah[ks][0] = ph0[ks * 8 + tq];     Ah[ks][1] = ph1[ks * 8 + tq];
            Ah[ks][2] = ph0[ks * 8 + tq + 4]; Ah[ks][3] = ph1[ks * 8 + tq + 4];
            Al[ks][0] = pl0[ks * 8 + tq];     Al[ks][1] = pl1[ks * 8 + tq];
            Al[ks][2] = pl0[ks * 8 + tq + 4]; Al[ks][3] = pl1[ks * 8 + tq + 4];
        }
    }

    float vout[2][32];

    #pragma unroll
    for (int c = 0; c < 4; c++) {
        int buf = c & 1;
        uint32_t bufbase = sB_u32 + buf * 17408;
        if (c < 3) {
            const uint4* wn = (const uint4*)(d_Wabf + (size_t)(t * 4 + c + 1) * 8704);
            uint32_t dstb = sB_u32 + (buf ^ 1) * 17408;
            for (int idx = tid; idx < 1088; idx += 256) cp16(dstb + idx * 16, wn + idx);
            CP_COMMIT();
        }
        float acc[16];
        #pragma unroll
        for (int j = 0; j < 16; j++) acc[j] = 0.f;
        #pragma unroll
        for (int ks = 0; ks < 8; ks++) {
            uint32_t kof = 32u * ks;
            uint32_t h0[4], h1[4], l0[4], l1[4];
            ldmx4(h0[0], h0[1], h0[2], h0[3], bufbase + rowL0 + kof);
            ldmx4(h1[0], h1[1], h1[2], h1[3], bufbase + rowL0 + 4352 + kof);
            ldmx4(l0[0], l0[1], l0[2], l0[3], bufbase + rowL0 + 8704 + kof);
            ldmx4(l1[0], l1[1], l1[2], l1[3], bufbase + rowL0 + 13056 + kof);
            mma_bf16(&acc[0],  Ah[ks], h0[0], h0[1]);
            mma_bf16(&acc[0],  Al[ks], h0[0], h0[1]);
            mma_bf16(&acc[0],  Ah[ks], l0[0], l0[1]);
            mma_bf16(&acc[4],  Ah[ks], h0[2], h0[3]);
            mma_bf16(&acc[4],  Al[ks], h0[2], h0[3]);
            mma_bf16(&acc[4],  Ah[ks], l0[2], l0[3]);
            mma_bf16(&acc[8],  Ah[ks], h1[0], h1[1]);
            mma_bf16(&acc[8],  Al[ks], h1[0], h1[1]);
            mma_bf16(&acc[8],  Ah[ks], l1[0], l1[1]);
            mma_bf16(&acc[12], Ah[ks], h1[2], h1[3]);
            mma_bf16(&acc[12], Al[ks], h1[2], h1[3]);
            mma_bf16(&acc[12], Ah[ks], l1[2], l1[3]);
        }
        #pragma unroll
        for (int nt = 0; nt < 4; nt++) {
            int col = c * 32 + nt * 8 + 2 * tq;
            float bc0 = ba[t * 128 + col];
            float bc1 = ba[t * 128 + col + 1];
            vout[0][c * 8 + nt * 2 + 0] = acc[nt * 4 + 0] + bc0;
            vout[0][c * 8 + nt * 2 + 1] = acc[nt * 4 + 1] + bc1;
            vout[1][c * 8 + nt * 2 + 0] = acc[nt * 4 + 2] + bc0;
            vout[1][c * 8 + nt * 2 + 1] = acc[nt * 4 + 3] + bc1;
        }
        if (c < 3) CP_WAIT0();
        __syncthreads();
    }

    float alpha = 1.f / (1.f + expf(-skipv[t]));
    float onema = 1.f - alpha;

    #pragma unroll
    for (int rr = 0; rr < 2; rr++) {
        int row = (rr == 0) ? r0 : r1;
        int nid = (rr == 0) ? nid0 : nid1;
        bool valid = row < count;
        float s1 = 0.f, s2 = 0.f;
        float v[32];
        #pragma unroll
        for (int c = 0; c < 4; c++)
            #pragma unroll
            for (int nt = 0; nt < 4; nt++) {
                int col = c * 32 + nt * 8 + 2 * tq;
                float2 rx = *(const float2*)(x + (size_t)nid * C_ + col);
                float v0 = alpha * vout[rr][c * 8 + nt * 2 + 0] + onema * rx.x;
                float v1 = alpha * vout[rr][c * 8 + nt * 2 + 1] + onema * rx.y;
                v[c * 8 + nt * 2 + 0] = v0;
                v[c * 8 + nt * 2 + 1] = v1;
                s1 += v0 + v1;
                s2 = fmaf(v0, v0, s2);
                s2 = fmaf(v1, v1, s2);
            }
        s1 += __shfl_xor_sync(0xffffffffu, s1, 1);
        s1 += __shfl_xor_sync(0xffffffffu, s1, 2);
        s2 += __shfl_xor_sync(0xffffffffu, s2, 1);
        s2 += __shfl_xor_sync(0xffffffffu, s2, 2);
        float mu = s1 * (1.f / 128.f);
        float var = s2 * (1.f / 128.f) - mu * mu;
        float rstd = rsqrtf(var + 1e-5f);
        if (valid) {
            #pragma unroll
            for (int c = 0; c < 4; c++)
                #pragma unroll
                for (int nt = 0; nt < 4; nt++) {
                    int col = c * 32 + nt * 8 + 2 * tq;
                    float2 o;
                    o.x = (v[c * 8 + nt * 2 + 0] - mu) * rstd * gamma[t * 128 + col]
                        + beta[t * 128 + col];
                    o.y = (v[c * 8 + nt * 2 + 1] - mu) * rstd * gamma[t * 128 + col + 1]
                        + beta[t * 128 + col + 1];
                    *(float2*)&out[(size_t)nid * C_ + col] = o;
                }
        }
    }
}

// ---------------- launch ----------------
extern "C" void kernel_launch(void* const* d_in, const int* in_sizes, int n_in,
                              void* d_out, int out_size) {
    const float* x      = (const float*)d_in[0];
    const int*   typeId = (const int*)d_in[1];
    const int*   ei     = (const int*)d_in[2];
    const int*   ea     = (const int*)d_in[3];
    const float* Wk     = (const float*)d_in[4];
    const float* bk     = (const float*)d_in[5];
    const float* Wq     = (const float*)d_in[6];
    const float* bq     = (const float*)d_in[7];
    const float* Wv     = (const float*)d_in[8];
    const float* bv     = (const float*)d_in[9];
    const float* Wa     = (const float*)d_in[10];
    const float* ba     = (const float*)d_in[11];
    const float* pri    = (const float*)d_in[12];
    const float* Aatt   = (const float*)d_in[13];
    const float* Amsg   = (const float*)d_in[14];
    const float* skipv  = (const float*)d_in[15];
    const float* gamma  = (const float*)d_in[16];
    const float* beta   = (const float*)d_in[17];
    float* out = (float*)d_out;

    k_zero<<<(N_ + 255) / 256, 256>>>();                                       // 0
    k_setup<<<1025, 384>>>(Wk, bk, Wq, bq, Wv, bv, pri, Aatt, Amsg, Wa, x,
                           ei, ea, typeId);                                    // 1
    k_scan<<<1, 1024>>>();                                                     // 2
    k_edge_gemm<<<dim3(CAPR / 128, R_), 256>>>();                              // 3 <- profiled
    k_scatterD<<<E_ / 256, 256>>>();                                           // 4
    k_aggregate<<<N_ / 8, 256>>>();                                            // 5
    k_out<<<dim3(CAPN / 128, T_), 256>>>(x, ba, skipv, gamma, beta, out);      // 6
}

// round 11
// speedup vs baseline: 1.9104x; 1.0901x over previous
#include <cuda_runtime.h>
#include <cuda_bf16.h>
#include <math.h>
#include <stdint.h>

#define N_ 32768
#define E_ 262144
#define C_ 128
#define H_ 8
#define R_ 8
#define T_ 8
#define CAPR 36864
#define CAPN 4608
#define EG_DYN (34816 + 65536)   // B double buffer + kt stage

// ---------------- mma / ldmatrix / cp.async helpers ----------------
__device__ __forceinline__ void mma_bf16(float* c, const uint32_t* a, uint32_t b0, uint32_t b1) {
    asm volatile(
        "mma.sync.aligned.m16n8k16.row.col.f32.bf16.bf16.f32 "
        "{%0,%1,%2,%3}, {%4,%5,%6,%7}, {%8,%9}, {%0,%1,%2,%3};"
        : "+f"(c[0]), "+f"(c[1]), "+f"(c[2]), "+f"(c[3])
        : "r"(a[0]), "r"(a[1]), "r"(a[2]), "r"(a[3]), "r"(b0), "r"(b1));
}
__device__ __forceinline__ uint32_t smem_u32(const void* p) {
    uint32_t a;
    asm("{ .reg .u64 t; cvta.to.shared.u64 t, %1; cvt.u32.u64 %0, t; }" : "=r"(a) : "l"(p));
    return a;
}
__device__ __forceinline__ void ldmx4(uint32_t& r0, uint32_t& r1, uint32_t& r2, uint32_t& r3,
                                      uint32_t addr) {
    asm volatile("ldmatrix.sync.aligned.m8n8.x4.shared.b16 {%0,%1,%2,%3}, [%4];"
                 : "=r"(r0), "=r"(r1), "=r"(r2), "=r"(r3) : "r"(addr));
}
__device__ __forceinline__ void cp16(uint32_t d, const void* s) {
    asm volatile("cp.async.cg.shared.global [%0], [%1], 16;" :: "r"(d), "l"(s));
}
#define CP_COMMIT() asm volatile("cp.async.commit_group;" ::: "memory")
#define CP_WAIT0()  asm volatile("cp.async.wait_group 0;" ::: "memory")

// ---------------- scratch ----------------
__device__ __nv_bfloat16 d_Wbf[R_ * 12 * 2 * 4352];
__device__ __nv_bfloat16 d_Wabf[T_ * 4 * 2 * 4352];
__device__ __nv_bfloat16 d_xhi[N_ * C_];
__device__ __nv_bfloat16 d_xlo[N_ * C_];
__device__ __nv_bfloat16 d_x0hi[N_ * C_];
__device__ __nv_bfloat16 d_x0lo[N_ * C_];
__device__ float d_ball[R_][384];
__device__ int   d_cursor8[R_];
__device__ int   d_ssrc[R_ * CAPR];
__device__ int   d_sdst[R_ * CAPR];
__device__ float d_att[E_ * H_];
__device__ float d_vt[E_ * C_];
__device__ int   d_cnt[N_];
__device__ int   d_rowPtr[N_ + 1];
__device__ int   d_cursor[N_];
__device__ int   d_bydst[E_];
__device__ int   d_cursorN8[T_];
__device__ int   d_snid[T_ * CAPN];

// ---------------- 0: zero ----------------
__global__ void k_zero() {
    int i = blockIdx.x * blockDim.x + threadIdx.x;
    if (i < N_) { d_cnt[i] = 0; d_cursor[i] = 0; }
    if (i < R_) { d_cursor8[i] = 0; d_cursorN8[i] = 0; }
}

__device__ __forceinline__ void store_wbf(int r, int k, int j, float wv) {
    int chunk = j >> 5, n = j & 31;
    __nv_bfloat16 hi = __float2bfloat16_rn(wv);
    __nv_bfloat16 lo = __float2bfloat16_rn(wv - __bfloat162float(hi));
    size_t base = ((size_t)(r * 12 + chunk) * 2) * 4352 + n * 136 + k;
    d_Wbf[base] = hi;
    d_Wbf[base + 4352] = lo;
}

// ---------------- 1: setup ----------------
__global__ void __launch_bounds__(384) k_setup(
        const float* __restrict__ Wk, const float* __restrict__ bk,
        const float* __restrict__ Wq, const float* __restrict__ bq,
        const float* __restrict__ Wv, const float* __restrict__ bv,
        const float* __restrict__ pri, const float* __restrict__ Aatt,
        const float* __restrict__ Amsg, const float* __restrict__ Wa,
        const float* __restrict__ x,
        const int* __restrict__ ei, const int* __restrict__ ea,
        const int* __restrict__ tid_) {
    int b = blockIdx.x;
    int j = threadIdx.x;
    if (b < 64) {
        int r = b & 7, kc = b >> 3;
        int k0 = kc * 16;
        if (j < 256) {
            bool isK = j < 128;
            int c = j & 127;
            int h = c >> 4, d2 = c & 15;
            const float* M  = (isK ? Aatt : Amsg) + ((r * 8 + h) * 256) + d2;
            const float* Ws = (isK ? Wk : Wv) + r * 16384 + h * 16;
            for (int k = k0; k < k0 + 16; k++) {
                float s = 0.f;
                #pragma unroll
                for (int d = 0; d < 16; d++) s = fmaf(Ws[k * 128 + d], M[d * 16], s);
                store_wbf(r, k, j, s);
            }
            if (kc == 0) {
                const float* bs = (isK ? bk : bv) + r * 128 + h * 16;
                float s = 0.f;
                #pragma unroll
                for (int d = 0; d < 16; d++) s = fmaf(bs[d], M[d * 16], s);
                d_ball[r][j] = s;
            }
        } else {
            int c = j - 256;
            int h = c >> 4;
            float sc = pri[r * 8 + h] * 0.25f;
            for (int k = k0; k < k0 + 16; k++)
                store_wbf(r, k, j, Wq[r * 16384 + k * 128 + c] * sc);
            if (kc == 0) d_ball[r][j] = bq[r * 128 + c] * sc;
        }
    } else if (b < 747) {
        int e = (b - 64) * 384 + j;
        bool act = e < E_;
        int r = 0, srcv = 0, dstv = 0;
        if (act) { r = ea[e]; srcv = ei[e]; dstv = ei[E_ + e]; }
        unsigned amask = __ballot_sync(0xffffffffu, act);
        if (act) {
            unsigned mask = __match_any_sync(amask, r);
            int lane = j & 31;
            int leader = __ffs(mask) - 1;
            int prefix = __popc(mask & ((1u << lane) - 1));
            int base = 0;
            if (lane == leader) base = atomicAdd(&d_cursor8[r], __popc(mask));
            base = __shfl_sync(mask, base, leader);
            int pos = base + prefix;
            if (pos < CAPR) {
                d_ssrc[r * CAPR + pos] = srcv;
                d_sdst[r * CAPR + pos] = dstv;
            }
            atomicAdd(&d_cnt[dstv], 1);
        }
    } else if (b < 833) {
        int n = (b - 747) * 384 + j;
        if (n < N_) {
            int pos = atomicAdd(&d_cursorN8[tid_[n]], 1);
            if (pos < CAPN) d_snid[tid_[n] * CAPN + pos] = n;
        }
    } else if (b < 961) {
        for (int idx = (b - 833) * 384 + j; idx < N_ * C_ / 4; idx += 128 * 384) {
            float4 v = ((const float4*)x)[idx];
            __nv_bfloat162 ha = __floats2bfloat162_rn(v.x, v.y);
            __nv_bfloat162 hb = __floats2bfloat162_rn(v.z, v.w);
            __nv_bfloat162 la = __floats2bfloat162_rn(v.x - __bfloat162float(ha.x),
                                                      v.y - __bfloat162float(ha.y));
            __nv_bfloat162 lb = __floats2bfloat162_rn(v.z - __bfloat162float(hb.x),
                                                      v.w - __bfloat162float(hb.y));
            uint2 H, L;
            H.x = *(uint32_t*)&ha; H.y = *(uint32_t*)&hb;
            L.x = *(uint32_t*)&la; L.y = *(uint32_t*)&lb;
            ((uint2*)d_xhi)[idx] = H;
            ((uint2*)d_xlo)[idx] = L;
        }
    } else {
        int b2 = b - 961;
        int t = b2 & 7, kc = b2 >> 3;
        if (j < 128) {
            int n = j, chunk = n >> 5;
            for (int k = kc * 16; k < kc * 16 + 16; k++) {
                float wv = Wa[t * 16384 + k * 128 + n];
                __nv_bfloat16 hi = __float2bfloat16_rn(wv);
                __nv_bfloat16 lo = __float2bfloat16_rn(wv - __bfloat162float(hi));
                size_t base = ((size_t)(t * 4 + chunk) * 2) * 4352 + (n & 31) * 136 + k;
                d_Wabf[base] = hi;
                d_Wabf[base + 4352] = lo;
            }
        }
    }
}

// ---------------- 2: scan ----------------
__global__ void k_scan() {
    __shared__ int sums[1024];
    int tid = threadIdx.x;
    int base = tid * 32;
    int tot = 0;
    for (int i = 0; i < 32; i++) tot += d_cnt[base + i];
    sums[tid] = tot;
    __syncthreads();
    for (int off = 1; off < 1024; off <<= 1) {
        int v = (tid >= off) ? sums[tid - off] : 0;
        __syncthreads();
        sums[tid] += v;
        __syncthreads();
    }
    int run = sums[tid] - tot;
    for (int i = 0; i < 32; i++) { d_rowPtr[base + i] = run; run += d_cnt[base + i]; }
    if (tid == 1023) d_rowPtr[N_] = run;
}

// ---------------- 3: edge GEMM: mma bf16 3-pass, kt staged in smem, 2 CTA/SM ----------------
__global__ void __launch_bounds__(256, 2) k_edge_gemm() {
    extern __shared__ __align__(16) char dyn[];
    int r = blockIdx.y, i = blockIdx.x;
    int tid = threadIdx.x, wid = tid >> 5, lane = tid & 31;
    int g = lane >> 2, t = lane & 3;

    __shared__ int s_cnt, s_gb, s_src[128], s_dst[128];

    if (tid == 0) {
        int cnt = min(d_cursor8[r], CAPR);
        int gb = 0;
        #pragma unroll
        for (int q = 0; q < R_; q++) { int c = min(d_cursor8[q], CAPR); if (q < r) gb += c; }
        s_cnt = cnt; s_gb = gb;
    }
    __syncthreads();
    int cnt = s_cnt;
    if (i * 128 >= cnt) return;
    int count = min(128, cnt - i * 128);
    int gstart = s_gb + i * 128;
    int pstart = r * CAPR + i * 128;

    if (tid < 128) s_src[tid] = (i * 128 + tid < cnt) ? d_ssrc[pstart + tid] : 0;
    else {
        int m = tid - 128;
        s_dst[m] = (i * 128 + m < cnt) ? d_sdst[pstart + m] : 0;
    }

    uint32_t sB_u32 = smem_u32(dyn);
    float* kt_s = (float*)(dyn + 34816);   // [4 chunks][16 j][256 tid]
    {
        const uint4* w0 = (const uint4*)(d_Wbf + (size_t)(r * 12) * 8704);
        for (int idx = tid; idx < 1088; idx += 256) cp16(sB_u32 + idx * 16, w0 + idx);
        CP_COMMIT();
        CP_WAIT0();
    }
    __syncthreads();

    int r0 = wid * 16 + g, r1 = r0 + 8;

    int i8 = lane & 7, q8 = lane >> 3;
    uint32_t rowL0 = (uint32_t)(((q8 >> 1) * 8 + i8) * 272 + (q8 & 1) * 16);

    uint32_t Ah[8][4], Al[8][4];
    {
        const uint32_t* ph0 = (const uint32_t*)d_xhi + (size_t)s_src[r0] * 64;
        const uint32_t* ph1 = (const uint32_t*)d_xhi + (size_t)s_src[r1] * 64;
        const uint32_t* pl0 = (const uint32_t*)d_xlo + (size_t)s_src[r0] * 64;
        const uint32_t* pl1 = (const uint32_t*)d_xlo + (size_t)s_src[r1] * 64;
        #pragma unroll
        for (int ks = 0; ks < 8; ks++) {
            Ah[ks][0] = ph0[ks * 8 + t];     Ah[ks][1] = ph1[ks * 8 + t];
            Ah[ks][2] = ph0[ks * 8 + t + 4]; Ah[ks][3] = ph1[ks * 8 + t + 4];
            Al[ks][0] = pl0[ks * 8 + t];     Al[ks][1] = pl1[ks * 8 + t];
            Al[ks][2] = pl0[ks * 8 + t + 4]; Al[ks][3] = pl1[ks * 8 + t + 4];
        }
    }

    const float* __restrict__ bb = d_ball[r];
    bool v0 = r0 < count, v1 = r1 < count;
    int slot0 = gstart + r0, slot1 = gstart + r1;

    #pragma unroll
    for (int c = 0; c < 12; c++) {
        int buf = c & 1;
        uint32_t bufbase = sB_u32 + buf * 17408;
        if (c < 11) {
            const uint4* wn = (const uint4*)(d_Wbf + (size_t)(r * 12 + c + 1) * 8704);
            uint32_t dstb = sB_u32 + (buf ^ 1) * 17408;
            for (int idx = tid; idx < 1088; idx += 256) cp16(dstb + idx * 16, wn + idx);
            CP_COMMIT();
        }
        if (c == 8) {
            const uint32_t* ph0 = (const uint32_t*)d_xhi + (size_t)s_dst[r0] * 64;
            const uint32_t* ph1 = (const uint32_t*)d_xhi + (size_t)s_dst[r1] * 64;
            const uint32_t* pl0 = (const uint32_t*)d_xlo + (size_t)s_dst[r0] * 64;
            const uint32_t* pl1 = (const uint32_t*)d_xlo + (size_t)s_dst[r1] * 64;
            #pragma unroll
            for (int ks = 0; ks < 8; ks++) {
                Ah[ks][0] = ph0[ks * 8 + t];     Ah[ks][1] = ph1[ks * 8 + t];
                Ah[ks][2] = ph0[ks * 8 + t + 4]; Ah[ks][3] = ph1[ks * 8 + t + 4];
                Al[ks][0] = pl0[ks * 8 + t];     Al[ks][1] = pl1[ks * 8 + t];
                Al[ks][2] = pl0[ks * 8 + t + 4]; Al[ks][3] = pl1[ks * 8 + t + 4];
            }
        }

        float acc[16];
        #pragma unroll
        for (int j = 0; j < 16; j++) acc[j] = 0.f;

        #pragma unroll
        for (int ks = 0; ks < 8; ks++) {
            uint32_t kof = 32u * ks;
            uint32_t h0[4], h1[4], l0[4], l1[4];
            ldmx4(h0[0], h0[1], h0[2], h0[3], bufbase + rowL0 + kof);
            ldmx4(h1[0], h1[1], h1[2], h1[3], bufbase + rowL0 + 4352 + kof);
            ldmx4(l0[0], l0[1], l0[2], l0[3], bufbase + rowL0 + 8704 + kof);
            ldmx4(l1[0], l1[1], l1[2], l1[3], bufbase + rowL0 + 13056 + kof);
            mma_bf16(&acc[0],  Ah[ks], h0[0], h0[1]);
            mma_bf16(&acc[0],  Al[ks], h0[0], h0[1]);
            mma_bf16(&acc[0],  Ah[ks], l0[0], l0[1]);
            mma_bf16(&acc[4],  Ah[ks], h0[2], h0[3]);
            mma_bf16(&acc[4],  Al[ks], h0[2], h0[3]);
            mma_bf16(&acc[4],  Ah[ks], l0[2], l0[3]);
            mma_bf16(&acc[8],  Ah[ks], h1[0], h1[1]);
            mma_bf16(&acc[8],  Al[ks], h1[0], h1[1]);
            mma_bf16(&acc[8],  Ah[ks], l1[0], l1[1]);
            mma_bf16(&acc[12], Ah[ks], h1[2], h1[3]);
            mma_bf16(&acc[12], Al[ks], h1[2], h1[3]);
            mma_bf16(&acc[12], Ah[ks], l1[2], l1[3]);
        }

        #pragma unroll
        for (int nt = 0; nt < 4; nt++) {
            float bc0 = bb[c * 32 + nt * 8 + 2 * t];
            float bc1 = bb[c * 32 + nt * 8 + 2 * t + 1];
            acc[nt * 4 + 0] += bc0; acc[nt * 4 + 1] += bc1;
            acc[nt * 4 + 2] += bc0; acc[nt * 4 + 3] += bc1;
        }

        if (c < 4) {
            // stage kt in smem: [c*16+j][tid], conflict-free
            #pragma unroll
            for (int j = 0; j < 16; j++) kt_s[(c * 16 + j) * 256 + tid] = acc[j];
        } else if (c < 8) {
            int cb = (c - 4) * 32;
            #pragma unroll
            for (int nt = 0; nt < 4; nt++) {
                int col = cb + nt * 8 + 2 * t;
                if (v0) *(float2*)&d_vt[(size_t)slot0 * C_ + col] =
                    make_float2(acc[nt * 4 + 0], acc[nt * 4 + 1]);
                if (v1) *(float2*)&d_vt[(size_t)slot1 * C_ + col] =
                    make_float2(acc[nt * 4 + 2], acc[nt * 4 + 3]);
            }
        } else {
            int cc = c - 8;
            int h0c = cc * 2;
            const float* kb = kt_s + cc * 16 * 256 + tid;
            float p00 = acc[0] * kb[0 * 256] + acc[1] * kb[1 * 256]
                      + acc[4] * kb[4 * 256] + acc[5] * kb[5 * 256];
            float p10 = acc[2] * kb[2 * 256] + acc[3] * kb[3 * 256]
                      + acc[6] * kb[6 * 256] + acc[7] * kb[7 * 256];
            float p01 = acc[8] * kb[8 * 256] + acc[9] * kb[9 * 256]
                      + acc[12] * kb[12 * 256] + acc[13] * kb[13 * 256];
            float p11 = acc[10] * kb[10 * 256] + acc[11] * kb[11 * 256]
                      + acc[14] * kb[14 * 256] + acc[15] * kb[15 * 256];
            p00 += __shfl_xor_sync(0xffffffffu, p00, 1);
            p00 += __shfl_xor_sync(0xffffffffu, p00, 2);
            p10 += __shfl_xor_sync(0xffffffffu, p10, 1);
            p10 += __shfl_xor_sync(0xffffffffu, p10, 2);
            p01 += __shfl_xor_sync(0xffffffffu, p01, 1);
            p01 += __shfl_xor_sync(0xffffffffu, p01, 2);
            p11 += __shfl_xor_sync(0xffffffffu, p11, 1);
            p11 += __shfl_xor_sync(0xffffffffu, p11, 2);
            if (t == 0) {
                if (v0) {
                    d_att[(size_t)slot0 * 8 + h0c] = p00;
                    d_att[(size_t)slot0 * 8 + h0c + 1] = p01;
                }
                if (v1) {
                    d_att[(size_t)slot1 * 8 + h0c] = p10;
                    d_att[(size_t)slot1 * 8 + h0c + 1] = p11;
                }
            }
        }

        if (c < 11) CP_WAIT0();
        __syncthreads();
    }
}

// ---------------- 4: scatter compact slots by dst ----------------
__global__ void k_scatterD() {
    __shared__ int sb[R_ + 1];
    if (threadIdx.x < R_) sb[threadIdx.x + 1] = min(d_cursor8[threadIdx.x], CAPR);
    if (threadIdx.x == 0) sb[0] = 0;
    __syncthreads();
    if (threadIdx.x == 0) {
        #pragma unroll
        for (int q = 1; q <= R_; q++) sb[q] += sb[q - 1];
    }
    __syncthreads();
    int c = blockIdx.x * blockDim.x + threadIdx.x;
    if (c >= sb[R_]) return;
    int r = 0;
    #pragma unroll
    for (int q = 1; q < R_; q++) r += (c >= sb[q]);
    int padded = r * CAPR + (c - sb[r]);
    int dst = d_sdst[padded];
    int pos = d_rowPtr[dst] + atomicAdd(&d_cursor[dst], 1);
    d_bydst[pos] = c;
}

// ---------------- 5: aggregate (writes x0 as bf16 hi/lo) ----------------
__global__ void k_aggregate() {
    int warp = threadIdx.x >> 5;
    int lane = threadIdx.x & 31;
    int n = blockIdx.x * (blockDim.x >> 5) + warp;
    if (n >= N_) return;
    int s = d_rowPtr[n], eEnd = d_rowPtr[n + 1];
    int deg = eEnd - s;
    if (deg == 0) {
        #pragma unroll
        for (int j = 0; j < 4; j++) {
            d_x0hi[n * C_ + lane + 32 * j] = __float2bfloat16_rn(0.f);
            d_x0lo[n * C_ + lane + 32 * j] = __float2bfloat16_rn(0.f);
        }
        return;
    }
    int slot = lane >> 3, h = lane & 7;
    float m = -1e30f;
    for (int b = s; b < eEnd; b += 4) {
        int idx = b + slot;
        if (idx < eEnd) m = fmaxf(m, d_att[d_bydst[idx] * 8 + h]);
    }
    m = fmaxf(m, __shfl_xor_sync(0xffffffffu, m, 8));
    m = fmaxf(m, __shfl_xor_sync(0xffffffffu, m, 16));
    float den = 0.f;
    for (int b = s; b < eEnd; b += 4) {
        int idx = b + slot;
        if (idx < eEnd) den += expf(d_att[d_bydst[idx] * 8 + h] - m);
    }
    den += __shfl_xor_sync(0xffffffffu, den, 8);
    den += __shfl_xor_sync(0xffffffffu, den, 16);
    int hb = lane >> 4;
    float mj[4], rj[4];
    #pragma unroll
    for (int j = 0; j < 4; j++) {
        int hh = hb + 2 * j;
        mj[j] = __shfl_sync(0xffffffffu, m, hh);
        rj[j] = 1.f / __shfl_sync(0xffffffffu, den, hh);
    }
    float acc[4] = {0.f, 0.f, 0.f, 0.f};
    for (int idx = s; idx < eEnd; idx++) {
        int e = d_bydst[idx];
        const float* ar = &d_att[e * 8];
        const float* vr = &d_vt[(size_t)e * C_];
        #pragma unroll
        for (int j = 0; j < 4; j++) {
            float w = expf(ar[hb + 2 * j] - mj[j]) * rj[j];
            acc[j] = fmaf(w, vr[lane + 32 * j], acc[j]);
        }
    }
    float inv = 1.f / (float)deg;
    #pragma unroll
    for (int j = 0; j < 4; j++) {
        float val = acc[j] * inv;
        __nv_bfloat16 h2 = __float2bfloat16_rn(val);
        __nv_bfloat16 l2 = __float2bfloat16_rn(val - __bfloat162float(h2));
        d_x0hi[n * C_ + lane + 32 * j] = h2;
        d_x0lo[n * C_ + lane + 32 * j] = l2;
    }
}

// ---------------- 6: out GEMM (mma + ldmatrix + cp.async) + residual + LN ----------------
__global__ void __launch_bounds__(256, 1) k_out(const float* __restrict__ x,
                                                const float* __restrict__ ba,
                                                const float* __restrict__ skipv,
                                                const float* __restrict__ gamma,
                                                const float* __restrict__ beta,
                                                float* __restrict__ out) {
    int t = blockIdx.y, i = blockIdx.x;
    int tid = threadIdx.x, wid = tid >> 5, lane = tid & 31;
    int g = lane >> 2, tq = lane & 3;

    int cntT = min(d_cursorN8[t], CAPN);
    if (i * 128 >= cntT) return;
    int count = min(128, cntT - i * 128);
    int start = t * CAPN + i * 128;

    __shared__ int s_nid[128];
    __shared__ __align__(16) uint4 sB[2][1088];

    if (tid < 128) s_nid[tid] = (i * 128 + tid < cntT) ? d_snid[start + tid] : 0;
    uint32_t sB_u32 = smem_u32(sB);
    {
        const uint4* w0 = (const uint4*)(d_Wabf + (size_t)(t * 4) * 8704);
        for (int idx = tid; idx < 1088; idx += 256) cp16(sB_u32 + idx * 16, w0 + idx);
        CP_COMMIT();
        CP_WAIT0();
    }
    __syncthreads();

    int r0 = wid * 16 + g, r1 = r0 + 8;
    int nid0 = s_nid[r0], nid1 = s_nid[r1];

    int i8 = lane & 7, q8 = lane >> 3;
    uint32_t rowL0 = (uint32_t)(((q8 >> 1) * 8 + i8) * 272 + (q8 & 1) * 16);

    uint32_t Ah[8][4], Al[8][4];
    {
        const uint32_t* ph0 = (const uint32_t*)d_x0hi + (size_t)nid0 * 64;
        const uint32_t* ph1 = (const uint32_t*)d_x0hi + (size_t)nid1 * 64;
        const uint32_t* pl0 = (const uint32_t*)d_x0lo + (size_t)nid0 * 64;
        const uint32_t* pl1 = (const uint32_t*)d_x0lo + (size_t)nid1 * 64;
        #pragma unroll
        for (int ks = 0; ks < 8; ks++) {
            Ah[ks][0] = ph0[ks * 8 + tq];     Ah[ks][1] = ph1[ks * 8 + tq];
            Ah[ks][2] = ph0[ks * 8 + tq + 4]; Ah[ks][3] = ph1[ks * 8 + tq + 4];
            Al[ks][0] = pl0[ks * 8 + tq];     Al[ks][1] = pl1[ks * 8 + tq];
            Al[ks][2] = pl0[ks * 8 + tq + 4]; Al[ks][3] = pl1[ks * 8 + tq + 4];
        }
    }

    float vout[2][32];

    #pragma unroll
    for (int c = 0; c < 4; c++) {
        int buf = c & 1;
        uint32_t bufbase = sB_u32 + buf * 17408;
        if (c < 3) {
            const uint4* wn = (const uint4*)(d_Wabf + (size_t)(t * 4 + c + 1) * 8704);
            uint32_t dstb = sB_u32 + (buf ^ 1) * 17408;
            for (int idx = tid; idx < 1088; idx += 256) cp16(dstb + idx * 16, wn + idx);
            CP_COMMIT();
        }
        float acc[16];
        #pragma unroll
        for (int j = 0; j < 16; j++) acc[j] = 0.f;
        #pragma unroll
        for (int ks = 0; ks < 8; ks++) {
            uint32_t kof = 32u * ks;
            uint32_t h0[4], h1[4], l0[4], l1[4];
            ldmx4(h0[0], h0[1], h0[2], h0[3], bufbase + rowL0 + kof);
            ldmx4(h1[0], h1[1], h1[2], h1[3], bufbase + rowL0 + 4352 + kof);
            ldmx4(l0[0], l0[1], l0[2], l0[3], bufbase + rowL0 + 8704 + kof);
            ldmx4(l1[0], l1[1], l1[2], l1[3], bufbase + rowL0 + 13056 + kof);
            mma_bf16(&acc[0],  Ah[ks], h0[0], h0[1]);
            mma_bf16(&acc[0],  Al[ks], h0[0], h0[1]);
            mma_bf16(&acc[0],  Ah[ks], l0[0], l0[1]);
            mma_bf16(&acc[4],  Ah[ks], h0[2], h0[3]);
            mma_bf16(&acc[4],  Al[ks], h0[2], h0[3]);
            mma_bf16(&acc[4],  Ah[ks], l0[2], l0[3]);
            mma_bf16(&acc[8],  Ah[ks], h1[0], h1[1]);
            mma_bf16(&acc[8],  Al[ks], h1[0], h1[1]);
            mma_bf16(&acc[8],  Ah[ks], l1[0], l1[1]);
            mma_bf16(&acc[12], Ah[ks], h1[2], h1[3]);
            mma_bf16(&acc[12], Al[ks], h1[2], h1[3]);
            mma_bf16(&acc[12], Ah[ks], l1[2], l1[3]);
        }
        #pragma unroll
        for (int nt = 0; nt < 4; nt++) {
            int col = c * 32 + nt * 8 + 2 * tq;
            float bc0 = ba[t * 128 + col];
            float bc1 = ba[t * 128 + col + 1];
            vout[0][c * 8 + nt * 2 + 0] = acc[nt * 4 + 0] + bc0;
            vout[0][c * 8 + nt * 2 + 1] = acc[nt * 4 + 1] + bc1;
            vout[1][c * 8 + nt * 2 + 0] = acc[nt * 4 + 2] + bc0;
            vout[1][c * 8 + nt * 2 + 1] = acc[nt * 4 + 3] + bc1;
        }
        if (c < 3) CP_WAIT0();
        __syncthreads();
    }

    float alpha = 1.f / (1.f + expf(-skipv[t]));
    float onema = 1.f - alpha;

    #pragma unroll
    for (int rr = 0; rr < 2; rr++) {
        int row = (rr == 0) ? r0 : r1;
        int nid = (rr == 0) ? nid0 : nid1;
        bool valid = row < count;
        float s1 = 0.f, s2 = 0.f;
        float v[32];
        #pragma unroll
        for (int c = 0; c < 4; c++)
            #pragma unroll
            for (int nt = 0; nt < 4; nt++) {
                int col = c * 32 + nt * 8 + 2 * tq;
                float2 rx = *(const float2*)(x + (size_t)nid * C_ + col);
                float v0 = alpha * vout[rr][c * 8 + nt * 2 + 0] + onema * rx.x;
                float v1 = alpha * vout[rr][c * 8 + nt * 2 + 1] + onema * rx.y;
                v[c * 8 + nt * 2 + 0] = v0;
                v[c * 8 + nt * 2 + 1] = v1;
                s1 += v0 + v1;
                s2 = fmaf(v0, v0, s2);
                s2 = fmaf(v1, v1, s2);
            }
        s1 += __shfl_xor_sync(0xffffffffu, s1, 1);
        s1 += __shfl_xor_sync(0xffffffffu, s1, 2);
        s2 += __shfl_xor_sync(0xffffffffu, s2, 1);
        s2 += __shfl_xor_sync(0xffffffffu, s2, 2);
        float mu = s1 * (1.f / 128.f);
        float var = s2 * (1.f / 128.f) - mu * mu;
        float rstd = rsqrtf(var + 1e-5f);
        if (valid) {
            #pragma unroll
            for (int c = 0; c < 4; c++)
                #pragma unroll
                for (int nt = 0; nt < 4; nt++) {
                    int col = c * 32 + nt * 8 + 2 * tq;
                    float2 o;
                    o.x = (v[c * 8 + nt * 2 + 0] - mu) * rstd * gamma[t * 128 + col]
                        + beta[t * 128 + col];
                    o.y = (v[c * 8 + nt * 2 + 1] - mu) * rstd * gamma[t * 128 + col + 1]
                        + beta[t * 128 + col + 1];
                    *(float2*)&out[(size_t)nid * C_ + col] = o;
                }
        }
    }
}

// ---------------- launch ----------------
extern "C" void kernel_launch(void* const* d_in, const int* in_sizes, int n_in,
                              void* d_out, int out_size) {
    const float* x      = (const float*)d_in[0];
    const int*   typeId = (const int*)d_in[1];
    const int*   ei     = (const int*)d_in[2];
    const int*   ea     = (const int*)d_in[3];
    const float* Wk     = (const float*)d_in[4];
    const float* bk     = (const float*)d_in[5];
    const float* Wq     = (const float*)d_in[6];
    const float* bq     = (const float*)d_in[7];
    const float* Wv     = (const float*)d_in[8];
    const float* bv     = (const float*)d_in[9];
    const float* Wa     = (const float*)d_in[10];
    const float* ba     = (const float*)d_in[11];
    const float* pri    = (const float*)d_in[12];
    const float* Aatt   = (const float*)d_in[13];
    const float* Amsg   = (const float*)d_in[14];
    const float* skipv  = (const float*)d_in[15];
    const float* gamma  = (const float*)d_in[16];
    const float* beta   = (const float*)d_in[17];
    float* out = (float*)d_out;

    static bool attr_set = false;
    if (!attr_set) {
        cudaFuncSetAttribute(k_edge_gemm, cudaFuncAttributeMaxDynamicSharedMemorySize, EG_DYN);
        attr_set = true;
    }

    k_zero<<<(N_ + 255) / 256, 256>>>();                                       // 0
    k_setup<<<1025, 384>>>(Wk, bk, Wq, bq, Wv, bv, pri, Aatt, Amsg, Wa, x,
                           ei, ea, typeId);                                    // 1
    k_scan<<<1, 1024>>>();                                                     // 2
    k_edge_gemm<<<dim3(CAPR / 128, R_), 256, EG_DYN>>>();                      // 3 <- profiled
    k_scatterD<<<E_ / 256, 256>>>();                                           // 4
    k_aggregate<<<N_ / 8, 256>>>();                                            // 5
    k_out<<<dim3(CAPN / 128, T_), 256>>>(x, ba, skipv, gamma, beta, out);      // 6
}

// round 12
// speedup vs baseline: 2.3049x; 1.2065x over previous
#include <cuda_runtime.h>
#include <cuda_bf16.h>
#include <math.h>
#include <stdint.h>

#define N_ 32768
#define E_ 262144
#define C_ 128
#define H_ 8
#define R_ 8
#define T_ 8
#define CAPR 36864
#define CAPN 4608
#define EG_DYN (34816 + 65536)   // B double buffer + kt stage

// ---------------- mma / ldmatrix / cp.async helpers ----------------
__device__ __forceinline__ void mma_bf16(float* c, const uint32_t* a, uint32_t b0, uint32_t b1) {
    asm volatile(
        "mma.sync.aligned.m16n8k16.row.col.f32.bf16.bf16.f32 "
        "{%0,%1,%2,%3}, {%4,%5,%6,%7}, {%8,%9}, {%0,%1,%2,%3};"
        : "+f"(c[0]), "+f"(c[1]), "+f"(c[2]), "+f"(c[3])
        : "r"(a[0]), "r"(a[1]), "r"(a[2]), "r"(a[3]), "r"(b0), "r"(b1));
}
__device__ __forceinline__ uint32_t smem_u32(const void* p) {
    uint32_t a;
    asm("{ .reg .u64 t; cvta.to.shared.u64 t, %1; cvt.u32.u64 %0, t; }" : "=r"(a) : "l"(p));
    return a;
}
__device__ __forceinline__ void ldmx4(uint32_t& r0, uint32_t& r1, uint32_t& r2, uint32_t& r3,
                                      uint32_t addr) {
    asm volatile("ldmatrix.sync.aligned.m8n8.x4.shared.b16 {%0,%1,%2,%3}, [%4];"
                 : "=r"(r0), "=r"(r1), "=r"(r2), "=r"(r3) : "r"(addr));
}
__device__ __forceinline__ void cp16(uint32_t d, const void* s) {
    asm volatile("cp.async.cg.shared.global [%0], [%1], 16;" :: "r"(d), "l"(s));
}
#define CP_COMMIT() asm volatile("cp.async.commit_group;" ::: "memory")
#define CP_WAIT0()  asm volatile("cp.async.wait_group 0;" ::: "memory")

// ---------------- scratch ----------------
__device__ __nv_bfloat16 d_Wbf[R_ * 12 * 2 * 4352];
__device__ __nv_bfloat16 d_Wabf[T_ * 4 * 2 * 4352];
__device__ __nv_bfloat16 d_xhi[N_ * C_];
__device__ __nv_bfloat16 d_xlo[N_ * C_];
__device__ __nv_bfloat16 d_x0hi[N_ * C_];
__device__ __nv_bfloat16 d_x0lo[N_ * C_];
__device__ float d_ball[R_][384];
__device__ int   d_cursor8[R_];
__device__ int   d_ssrc[R_ * CAPR];
__device__ int   d_sdst[R_ * CAPR];
__device__ float d_att[E_ * H_];
__device__ float d_vt[E_ * C_];
__device__ int   d_cnt[N_];
__device__ int   d_rowPtr[N_ + 1];
__device__ int   d_cursor[N_];
__device__ int   d_bydst[E_];
__device__ int   d_cursorN8[T_];
__device__ int   d_snid[T_ * CAPN];

// ---------------- 0: zero ----------------
__global__ void k_zero() {
    int i = blockIdx.x * blockDim.x + threadIdx.x;
    if (i < N_) { d_cnt[i] = 0; d_cursor[i] = 0; }
    if (i < R_) { d_cursor8[i] = 0; d_cursorN8[i] = 0; }
}

__device__ __forceinline__ void store_wbf(int r, int k, int j, float wv) {
    int chunk = j >> 5, n = j & 31;
    __nv_bfloat16 hi = __float2bfloat16_rn(wv);
    __nv_bfloat16 lo = __float2bfloat16_rn(wv - __bfloat162float(hi));
    size_t base = ((size_t)(r * 12 + chunk) * 2) * 4352 + n * 136 + k;
    d_Wbf[base] = hi;
    d_Wbf[base + 4352] = lo;
}

// ---------------- 1: setup ----------------
__global__ void __launch_bounds__(384) k_setup(
        const float* __restrict__ Wk, const float* __restrict__ bk,
        const float* __restrict__ Wq, const float* __restrict__ bq,
        const float* __restrict__ Wv, const float* __restrict__ bv,
        const float* __restrict__ pri, const float* __restrict__ Aatt,
        const float* __restrict__ Amsg, const float* __restrict__ Wa,
        const float* __restrict__ x,
        const int* __restrict__ ei, const int* __restrict__ ea,
        const int* __restrict__ tid_) {
    int b = blockIdx.x;
    int j = threadIdx.x;
    if (b < 64) {
        int r = b & 7, kc = b >> 3;
        int k0 = kc * 16;
        if (j < 256) {
            bool isK = j < 128;
            int c = j & 127;
            int h = c >> 4, d2 = c & 15;
            const float* M  = (isK ? Aatt : Amsg) + ((r * 8 + h) * 256) + d2;
            const float* Ws = (isK ? Wk : Wv) + r * 16384 + h * 16;
            for (int k = k0; k < k0 + 16; k++) {
                float s = 0.f;
                #pragma unroll
                for (int d = 0; d < 16; d++) s = fmaf(Ws[k * 128 + d], M[d * 16], s);
                store_wbf(r, k, j, s);
            }
            if (kc == 0) {
                const float* bs = (isK ? bk : bv) + r * 128 + h * 16;
                float s = 0.f;
                #pragma unroll
                for (int d = 0; d < 16; d++) s = fmaf(bs[d], M[d * 16], s);
                d_ball[r][j] = s;
            }
        } else {
            int c = j - 256;
            int h = c >> 4;
            float sc = pri[r * 8 + h] * 0.25f;
            for (int k = k0; k < k0 + 16; k++)
                store_wbf(r, k, j, Wq[r * 16384 + k * 128 + c] * sc);
            if (kc == 0) d_ball[r][j] = bq[r * 128 + c] * sc;
        }
    } else if (b < 747) {
        int e = (b - 64) * 384 + j;
        bool act = e < E_;
        int r = 0, srcv = 0, dstv = 0;
        if (act) { r = ea[e]; srcv = ei[e]; dstv = ei[E_ + e]; }
        unsigned amask = __ballot_sync(0xffffffffu, act);
        if (act) {
            unsigned mask = __match_any_sync(amask, r);
            int lane = j & 31;
            int leader = __ffs(mask) - 1;
            int prefix = __popc(mask & ((1u << lane) - 1));
            int base = 0;
            if (lane == leader) base = atomicAdd(&d_cursor8[r], __popc(mask));
            base = __shfl_sync(mask, base, leader);
            int pos = base + prefix;
            if (pos < CAPR) {
                d_ssrc[r * CAPR + pos] = srcv;
                d_sdst[r * CAPR + pos] = dstv;
            }
            atomicAdd(&d_cnt[dstv], 1);
        }
    } else if (b < 833) {
        int n = (b - 747) * 384 + j;
        if (n < N_) {
            int pos = atomicAdd(&d_cursorN8[tid_[n]], 1);
            if (pos < CAPN) d_snid[tid_[n] * CAPN + pos] = n;
        }
    } else if (b < 961) {
        for (int idx = (b - 833) * 384 + j; idx < N_ * C_ / 4; idx += 128 * 384) {
            float4 v = ((const float4*)x)[idx];
            __nv_bfloat162 ha = __floats2bfloat162_rn(v.x, v.y);
            __nv_bfloat162 hb = __floats2bfloat162_rn(v.z, v.w);
            __nv_bfloat162 la = __floats2bfloat162_rn(v.x - __bfloat162float(ha.x),
                                                      v.y - __bfloat162float(ha.y));
            __nv_bfloat162 lb = __floats2bfloat162_rn(v.z - __bfloat162float(hb.x),
                                                      v.w - __bfloat162float(hb.y));
            uint2 H, L;
            H.x = *(uint32_t*)&ha; H.y = *(uint32_t*)&hb;
            L.x = *(uint32_t*)&la; L.y = *(uint32_t*)&lb;
            ((uint2*)d_xhi)[idx] = H;
            ((uint2*)d_xlo)[idx] = L;
        }
    } else {
        int b2 = b - 961;
        int t = b2 & 7, kc = b2 >> 3;
        if (j < 128) {
            int n = j, chunk = n >> 5;
            for (int k = kc * 16; k < kc * 16 + 16; k++) {
                float wv = Wa[t * 16384 + k * 128 + n];
                __nv_bfloat16 hi = __float2bfloat16_rn(wv);
                __nv_bfloat16 lo = __float2bfloat16_rn(wv - __bfloat162float(hi));
                size_t base = ((size_t)(t * 4 + chunk) * 2) * 4352 + (n & 31) * 136 + k;
                d_Wabf[base] = hi;
                d_Wabf[base + 4352] = lo;
            }
        }
    }
}

// ---------------- 2: scan ----------------
__global__ void k_scan() {
    __shared__ int sums[1024];
    int tid = threadIdx.x;
    int base = tid * 32;
    int tot = 0;
    for (int i = 0; i < 32; i++) tot += d_cnt[base + i];
    sums[tid] = tot;
    __syncthreads();
    for (int off = 1; off < 1024; off <<= 1) {
        int v = (tid >= off) ? sums[tid - off] : 0;
        __syncthreads();
        sums[tid] += v;
        __syncthreads();
    }
    int run = sums[tid] - tot;
    for (int i = 0; i < 32; i++) { d_rowPtr[base + i] = run; run += d_cnt[base + i]; }
    if (tid == 1023) d_rowPtr[N_] = run;
}

// ---------------- 3: edge GEMM: mma bf16 3-pass, kt staged in smem, 2 CTA/SM ----------------
__global__ void __launch_bounds__(256, 2) k_edge_gemm() {
    extern __shared__ __align__(16) char dyn[];
    int r = blockIdx.y, i = blockIdx.x;
    int tid = threadIdx.x, wid = tid >> 5, lane = tid & 31;
    int g = lane >> 2, t = lane & 3;

    __shared__ int s_cnt, s_gb, s_src[128], s_dst[128];

    if (tid == 0) {
        int cnt = min(d_cursor8[r], CAPR);
        int gb = 0;
        #pragma unroll
        for (int q = 0; q < R_; q++) { int c = min(d_cursor8[q], CAPR); if (q < r) gb += c; }
        s_cnt = cnt; s_gb = gb;
    }
    __syncthreads();
    int cnt = s_cnt;
    if (i * 128 >= cnt) return;
    int count = min(128, cnt - i * 128);
    int gstart = s_gb + i * 128;
    int pstart = r * CAPR + i * 128;

    if (tid < 128) s_src[tid] = (i * 128 + tid < cnt) ? d_ssrc[pstart + tid] : 0;
    else {
        int m = tid - 128;
        s_dst[m] = (i * 128 + m < cnt) ? d_sdst[pstart + m] : 0;
    }

    uint32_t sB_u32 = smem_u32(dyn);
    float* kt_s = (float*)(dyn + 34816);   // [4 chunks][16 j][256 tid]
    {
        const uint4* w0 = (const uint4*)(d_Wbf + (size_t)(r * 12) * 8704);
        for (int idx = tid; idx < 1088; idx += 256) cp16(sB_u32 + idx * 16, w0 + idx);
        CP_COMMIT();
        CP_WAIT0();
    }
    __syncthreads();

    int r0 = wid * 16 + g, r1 = r0 + 8;

    int i8 = lane & 7, q8 = lane >> 3;
    uint32_t rowL0 = (uint32_t)(((q8 >> 1) * 8 + i8) * 272 + (q8 & 1) * 16);

    uint32_t Ah[8][4], Al[8][4];
    {
        const uint32_t* ph0 = (const uint32_t*)d_xhi + (size_t)s_src[r0] * 64;
        const uint32_t* ph1 = (const uint32_t*)d_xhi + (size_t)s_src[r1] * 64;
        const uint32_t* pl0 = (const uint32_t*)d_xlo + (size_t)s_src[r0] * 64;
        const uint32_t* pl1 = (const uint32_t*)d_xlo + (size_t)s_src[r1] * 64;
        #pragma unroll
        for (int ks = 0; ks < 8; ks++) {
            Ah[ks][0] = ph0[ks * 8 + t];     Ah[ks][1] = ph1[ks * 8 + t];
            Ah[ks][2] = ph0[ks * 8 + t + 4]; Ah[ks][3] = ph1[ks * 8 + t + 4];
            Al[ks][0] = pl0[ks * 8 + t];     Al[ks][1] = pl1[ks * 8 + t];
            Al[ks][2] = pl0[ks * 8 + t + 4]; Al[ks][3] = pl1[ks * 8 + t + 4];
        }
    }

    const float* __restrict__ bb = d_ball[r];
    bool v0 = r0 < count, v1 = r1 < count;
    int slot0 = gstart + r0, slot1 = gstart + r1;

    #pragma unroll
    for (int c = 0; c < 12; c++) {
        int buf = c & 1;
        uint32_t bufbase = sB_u32 + buf * 17408;
        if (c < 11) {
            const uint4* wn = (const uint4*)(d_Wbf + (size_t)(r * 12 + c + 1) * 8704);
            uint32_t dstb = sB_u32 + (buf ^ 1) * 17408;
            for (int idx = tid; idx < 1088; idx += 256) cp16(dstb + idx * 16, wn + idx);
            CP_COMMIT();
        }
        if (c == 8) {
            const uint32_t* ph0 = (const uint32_t*)d_xhi + (size_t)s_dst[r0] * 64;
            const uint32_t* ph1 = (const uint32_t*)d_xhi + (size_t)s_dst[r1] * 64;
            const uint32_t* pl0 = (const uint32_t*)d_xlo + (size_t)s_dst[r0] * 64;
            const uint32_t* pl1 = (const uint32_t*)d_xlo + (size_t)s_dst[r1] * 64;
            #pragma unroll
            for (int ks = 0; ks < 8; ks++) {
                Ah[ks][0] = ph0[ks * 8 + t];     Ah[ks][1] = ph1[ks * 8 + t];
                Ah[ks][2] = ph0[ks * 8 + t + 4]; Ah[ks][3] = ph1[ks * 8 + t + 4];
                Al[ks][0] = pl0[ks * 8 + t];     Al[ks][1] = pl1[ks * 8 + t];
                Al[ks][2] = pl0[ks * 8 + t + 4]; Al[ks][3] = pl1[ks * 8 + t + 4];
            }
        }

        float acc[16];
        #pragma unroll
        for (int j = 0; j < 16; j++) acc[j] = 0.f;

        #pragma unroll
        for (int ks = 0; ks < 8; ks++) {
            uint32_t kof = 32u * ks;
            uint32_t h0[4], h1[4], l0[4], l1[4];
            ldmx4(h0[0], h0[1], h0[2], h0[3], bufbase + rowL0 + kof);
            ldmx4(h1[0], h1[1], h1[2], h1[3], bufbase + rowL0 + 4352 + kof);
            ldmx4(l0[0], l0[1], l0[2], l0[3], bufbase + rowL0 + 8704 + kof);
            ldmx4(l1[0], l1[1], l1[2], l1[3], bufbase + rowL0 + 13056 + kof);
            mma_bf16(&acc[0],  Ah[ks], h0[0], h0[1]);
            mma_bf16(&acc[0],  Al[ks], h0[0], h0[1]);
            mma_bf16(&acc[0],  Ah[ks], l0[0], l0[1]);
            mma_bf16(&acc[4],  Ah[ks], h0[2], h0[3]);
            mma_bf16(&acc[4],  Al[ks], h0[2], h0[3]);
            mma_bf16(&acc[4],  Ah[ks], l0[2], l0[3]);
            mma_bf16(&acc[8],  Ah[ks], h1[0], h1[1]);
            mma_bf16(&acc[8],  Al[ks], h1[0], h1[1]);
            mma_bf16(&acc[8],  Ah[ks], l1[0], l1[1]);
            mma_bf16(&acc[12], Ah[ks], h1[2], h1[3]);
            mma_bf16(&acc[12], Al[ks], h1[2], h1[3]);
            mma_bf16(&acc[12], Ah[ks], l1[2], l1[3]);
        }

        #pragma unroll
        for (int nt = 0; nt < 4; nt++) {
            float bc0 = bb[c * 32 + nt * 8 + 2 * t];
            float bc1 = bb[c * 32 + nt * 8 + 2 * t + 1];
            acc[nt * 4 + 0] += bc0; acc[nt * 4 + 1] += bc1;
            acc[nt * 4 + 2] += bc0; acc[nt * 4 + 3] += bc1;
        }

        if (c < 4) {
            #pragma unroll
            for (int j = 0; j < 16; j++) kt_s[(c * 16 + j) * 256 + tid] = acc[j];
        } else if (c < 8) {
            int cb = (c - 4) * 32;
            #pragma unroll
            for (int nt = 0; nt < 4; nt++) {
                int col = cb + nt * 8 + 2 * t;
                if (v0) __stcs((float2*)&d_vt[(size_t)slot0 * C_ + col],
                               make_float2(acc[nt * 4 + 0], acc[nt * 4 + 1]));
                if (v1) __stcs((float2*)&d_vt[(size_t)slot1 * C_ + col],
                               make_float2(acc[nt * 4 + 2], acc[nt * 4 + 3]));
            }
        } else {
            int cc = c - 8;
            int h0c = cc * 2;
            const float* kb = kt_s + cc * 16 * 256 + tid;
            float p00 = acc[0] * kb[0 * 256] + acc[1] * kb[1 * 256]
                      + acc[4] * kb[4 * 256] + acc[5] * kb[5 * 256];
            float p10 = acc[2] * kb[2 * 256] + acc[3] * kb[3 * 256]
                      + acc[6] * kb[6 * 256] + acc[7] * kb[7 * 256];
            float p01 = acc[8] * kb[8 * 256] + acc[9] * kb[9 * 256]
                      + acc[12] * kb[12 * 256] + acc[13] * kb[13 * 256];
            float p11 = acc[10] * kb[10 * 256] + acc[11] * kb[11 * 256]
                      + acc[14] * kb[14 * 256] + acc[15] * kb[15 * 256];
            p00 += __shfl_xor_sync(0xffffffffu, p00, 1);
            p00 += __shfl_xor_sync(0xffffffffu, p00, 2);
            p10 += __shfl_xor_sync(0xffffffffu, p10, 1);
            p10 += __shfl_xor_sync(0xffffffffu, p10, 2);
            p01 += __shfl_xor_sync(0xffffffffu, p01, 1);
            p01 += __shfl_xor_sync(0xffffffffu, p01, 2);
            p11 += __shfl_xor_sync(0xffffffffu, p11, 1);
            p11 += __shfl_xor_sync(0xffffffffu, p11, 2);
            if (t == 0) {
                if (v0) {
                    d_att[(size_t)slot0 * 8 + h0c] = p00;
                    d_att[(size_t)slot0 * 8 + h0c + 1] = p01;
                }
                if (v1) {
                    d_att[(size_t)slot1 * 8 + h0c] = p10;
                    d_att[(size_t)slot1 * 8 + h0c + 1] = p11;
                }
            }
        }

        if (c < 11) CP_WAIT0();
        __syncthreads();
    }
}

// ---------------- 4: scatter compact slots by dst ----------------
__global__ void k_scatterD() {
    __shared__ int sb[R_ + 1];
    if (threadIdx.x < R_) sb[threadIdx.x + 1] = min(d_cursor8[threadIdx.x], CAPR);
    if (threadIdx.x == 0) sb[0] = 0;
    __syncthreads();
    if (threadIdx.x == 0) {
        #pragma unroll
        for (int q = 1; q <= R_; q++) sb[q] += sb[q - 1];
    }
    __syncthreads();
    int c = blockIdx.x * blockDim.x + threadIdx.x;
    if (c >= sb[R_]) return;
    int r = 0;
    #pragma unroll
    for (int q = 1; q < R_; q++) r += (c >= sb[q]);
    int padded = r * CAPR + (c - sb[r]);
    int dst = d_sdst[padded];
    int pos = d_rowPtr[dst] + atomicAdd(&d_cursor[dst], 1);
    d_bydst[pos] = c;
}

// ---------------- 5: aggregate (writes x0 as bf16 hi/lo) ----------------
__global__ void k_aggregate() {
    int warp = threadIdx.x >> 5;
    int lane = threadIdx.x & 31;
    int n = blockIdx.x * (blockDim.x >> 5) + warp;
    if (n >= N_) return;
    int s = d_rowPtr[n], eEnd = d_rowPtr[n + 1];
    int deg = eEnd - s;
    if (deg == 0) {
        #pragma unroll
        for (int j = 0; j < 4; j++) {
            d_x0hi[n * C_ + lane + 32 * j] = __float2bfloat16_rn(0.f);
            d_x0lo[n * C_ + lane + 32 * j] = __float2bfloat16_rn(0.f);
        }
        return;
    }
    int slot = lane >> 3, h = lane & 7;
    float m = -1e30f;
    for (int b = s; b < eEnd; b += 4) {
        int idx = b + slot;
        if (idx < eEnd) m = fmaxf(m, d_att[d_bydst[idx] * 8 + h]);
    }
    m = fmaxf(m, __shfl_xor_sync(0xffffffffu, m, 8));
    m = fmaxf(m, __shfl_xor_sync(0xffffffffu, m, 16));
    float den = 0.f;
    for (int b = s; b < eEnd; b += 4) {
        int idx = b + slot;
        if (idx < eEnd) den += expf(d_att[d_bydst[idx] * 8 + h] - m);
    }
    den += __shfl_xor_sync(0xffffffffu, den, 8);
    den += __shfl_xor_sync(0xffffffffu, den, 16);
    int hb = lane >> 4;
    float mj[4], rj[4];
    #pragma unroll
    for (int j = 0; j < 4; j++) {
        int hh = hb + 2 * j;
        mj[j] = __shfl_sync(0xffffffffu, m, hh);
        rj[j] = 1.f / __shfl_sync(0xffffffffu, den, hh);
    }
    float acc[4] = {0.f, 0.f, 0.f, 0.f};
    for (int idx = s; idx < eEnd; idx++) {
        int e = d_bydst[idx];
        const float* ar = &d_att[e * 8];
        const float* vr = &d_vt[(size_t)e * C_];
        #pragma unroll
        for (int j = 0; j < 4; j++) {
            float w = expf(ar[hb + 2 * j] - mj[j]) * rj[j];
            acc[j] = fmaf(w, __ldcs(&vr[lane + 32 * j]), acc[j]);
        }
    }
    float inv = 1.f / (float)deg;
    #pragma unroll
    for (int j = 0; j < 4; j++) {
        float val = acc[j] * inv;
        __nv_bfloat16 h2 = __float2bfloat16_rn(val);
        __nv_bfloat16 l2 = __float2bfloat16_rn(val - __bfloat162float(h2));
        d_x0hi[n * C_ + lane + 32 * j] = h2;
        d_x0lo[n * C_ + lane + 32 * j] = l2;
    }
}

// ---------------- 6: out GEMM (mma + ldmatrix + cp.async) + residual + LN ----------------
__global__ void __launch_bounds__(256, 1) k_out(const float* __restrict__ x,
                                                const float* __restrict__ ba,
                                                const float* __restrict__ skipv,
                                                const float* __restrict__ gamma,
                                                const float* __restrict__ beta,
                                                float* __restrict__ out) {
    int t = blockIdx.y, i = blockIdx.x;
    int tid = threadIdx.x, wid = tid >> 5, lane = tid & 31;
    int g = lane >> 2, tq = lane & 3;

    int cntT = min(d_cursorN8[t], CAPN);
    if (i * 128 >= cntT) return;
    int count = min(128, cntT - i * 128);
    int start = t * CAPN + i * 128;

    __shared__ int s_nid[128];
    __shared__ __align__(16) uint4 sB[2][1088];

    if (tid < 128) s_nid[tid] = (i * 128 + tid < cntT) ? d_snid[start + tid] : 0;
    uint32_t sB_u32 = smem_u32(sB);
    {
        const uint4* w0 = (const uint4*)(d_Wabf + (size_t)(t * 4) * 8704);
        for (int idx = tid; idx < 1088; idx += 256) cp16(sB_u32 + idx * 16, w0 + idx);
        CP_COMMIT();
        CP_WAIT0();
    }
    __syncthreads();

    int r0 = wid * 16 + g, r1 = r0 + 8;
    int nid0 = s_nid[r0], nid1 = s_nid[r1];

    int i8 = lane & 7, q8 = lane >> 3;
    uint32_t rowL0 = (uint32_t)(((q8 >> 1) * 8 + i8) * 272 + (q8 & 1) * 16);

    uint32_t Ah[8][4], Al[8][4];
    {
        const uint32_t* ph0 = (const uint32_t*)d_x0hi + (size_t)nid0 * 64;
        const uint32_t* ph1 = (const uint32_t*)d_x0hi + (size_t)nid1 * 64;
        const uint32_t* pl0 = (const uint32_t*)d_x0lo + (size_t)nid0 * 64;
        const uint32_t* pl1 = (const uint32_t*)d_x0lo + (size_t)nid1 * 64;
        #pragma unroll
        for (int ks = 0; ks < 8; ks++) {
            Ah[ks][0] = ph0[ks * 8 + tq];     Ah[ks][1] = ph1[ks * 8 + tq];
            Ah[ks][2] = ph0[ks * 8 + tq + 4]; Ah[ks][3] = ph1[ks * 8 + tq + 4];
            Al[ks][0] = pl0[ks * 8 + tq];     Al[ks][1] = pl1[ks * 8 + tq];
            Al[ks][2] = pl0[ks * 8 + tq + 4]; Al[ks][3] = pl1[ks * 8 + tq + 4];
        }
    }

    float vout[2][32];

    #pragma unroll
    for (int c = 0; c < 4; c++) {
        int buf = c & 1;
        uint32_t bufbase = sB_u32 + buf * 17408;
        if (c < 3) {
            const uint4* wn = (const uint4*)(d_Wabf + (size_t)(t * 4 + c + 1) * 8704);
            uint32_t dstb = sB_u32 + (buf ^ 1) * 17408;
            for (int idx = tid; idx < 1088; idx += 256) cp16(dstb + idx * 16, wn + idx);
            CP_COMMIT();
        }
        float acc[16];
        #pragma unroll
        for (int j = 0; j < 16; j++) acc[j] = 0.f;
        #pragma unroll
        for (int ks = 0; ks < 8; ks++) {
            uint32_t kof = 32u * ks;
            uint32_t h0[4], h1[4], l0[4], l1[4];
            ldmx4(h0[0], h0[1], h0[2], h0[3], bufbase + rowL0 + kof);
            ldmx4(h1[0], h1[1], h1[2], h1[3], bufbase + rowL0 + 4352 + kof);
            ldmx4(l0[0], l0[1], l0[2], l0[3], bufbase + rowL0 + 8704 + kof);
            ldmx4(l1[0], l1[1], l1[2], l1[3], bufbase + rowL0 + 13056 + kof);
            mma_bf16(&acc[0],  Ah[ks], h0[0], h0[1]);
            mma_bf16(&acc[0],  Al[ks], h0[0], h0[1]);
            mma_bf16(&acc[0],  Ah[ks], l0[0], l0[1]);
            mma_bf16(&acc[4],  Ah[ks], h0[2], h0[3]);
            mma_bf16(&acc[4],  Al[ks], h0[2], h0[3]);
            mma_bf16(&acc[4],  Ah[ks], l0[2], l0[3]);
            mma_bf16(&acc[8],  Ah[ks], h1[0], h1[1]);
            mma_bf16(&acc[8],  Al[ks], h1[0], h1[1]);
            mma_bf16(&acc[8],  Ah[ks], l1[0], l1[1]);
            mma_bf16(&acc[12], Ah[ks], h1[2], h1[3]);
            mma_bf16(&acc[12], Al[ks], h1[2], h1[3]);
            mma_bf16(&acc[12], Ah[ks], l1[2], l1[3]);
        }
        #pragma unroll
        for (int nt = 0; nt < 4; nt++) {
            int col = c * 32 + nt * 8 + 2 * tq;
            float bc0 = ba[t * 128 + col];
            float bc1 = ba[t * 128 + col + 1];
            vout[0][c * 8 + nt * 2 + 0] = acc[nt * 4 + 0] + bc0;
            vout[0][c * 8 + nt * 2 + 1] = acc[nt * 4 + 1] + bc1;
            vout[1][c * 8 + nt * 2 + 0] = acc[nt * 4 + 2] + bc0;
            vout[1][c * 8 + nt * 2 + 1] = acc[nt * 4 + 3] + bc1;
        }
        if (c < 3) CP_WAIT0();
        __syncthreads();
    }

    float alpha = 1.f / (1.f + expf(-skipv[t]));
    float onema = 1.f - alpha;

    #pragma unroll
    for (int rr = 0; rr < 2; rr++) {
        int row = (rr == 0) ? r0 : r1;
        int nid = (rr == 0) ? nid0 : nid1;
        bool valid = row < count;
        float s1 = 0.f, s2 = 0.f;
        float v[32];
        #pragma unroll
        for (int c = 0; c < 4; c++)
            #pragma unroll
            for (int nt = 0; nt < 4; nt++) {
                int col = c * 32 + nt * 8 + 2 * tq;
                float2 rx = *(const float2*)(x + (size_t)nid * C_ + col);
                float v0 = alpha * vout[rr][c * 8 + nt * 2 + 0] + onema * rx.x;
                float v1 = alpha * vout[rr][c * 8 + nt * 2 + 1] + onema * rx.y;
                v[c * 8 + nt * 2 + 0] = v0;
                v[c * 8 + nt * 2 + 1] = v1;
                s1 += v0 + v1;
                s2 = fmaf(v0, v0, s2);
                s2 = fmaf(v1, v1, s2);
            }
        s1 += __shfl_xor_sync(0xffffffffu, s1, 1);
        s1 += __shfl_xor_sync(0xffffffffu, s1, 2);
        s2 += __shfl_xor_sync(0xffffffffu, s2, 1);
        s2 += __shfl_xor_sync(0xffffffffu, s2, 2);
        float mu = s1 * (1.f / 128.f);
        float var = s2 * (1.f / 128.f) - mu * mu;
        float rstd = rsqrtf(var + 1e-5f);
        if (valid) {
            #pragma unroll
            for (int c = 0; c < 4; c++)
                #pragma unroll
                for (int nt = 0; nt < 4; nt++) {
                    int col = c * 32 + nt * 8 + 2 * tq;
                    float2 o;
                    o.x = (v[c * 8 + nt * 2 + 0] - mu) * rstd * gamma[t * 128 + col]
                        + beta[t * 128 + col];
                    o.y = (v[c * 8 + nt * 2 + 1] - mu) * rstd * gamma[t * 128 + col + 1]
                        + beta[t * 128 + col + 1];
                    *(float2*)&out[(size_t)nid * C_ + col] = o;
                }
        }
    }
}

// ---------------- launch ----------------
extern "C" void kernel_launch(void* const* d_in, const int* in_sizes, int n_in,
                              void* d_out, int out_size) {
    const float* x      = (const float*)d_in[0];
    const int*   typeId = (const int*)d_in[1];
    const int*   ei     = (const int*)d_in[2];
    const int*   ea     = (const int*)d_in[3];
    const float* Wk     = (const float*)d_in[4];
    const float* bk     = (const float*)d_in[5];
    const float* Wq     = (const float*)d_in[6];
    const float* bq     = (const float*)d_in[7];
    const float* Wv     = (const float*)d_in[8];
    const float* bv     = (const float*)d_in[9];
    const float* Wa     = (const float*)d_in[10];
    const float* ba     = (const float*)d_in[11];
    const float* pri    = (const float*)d_in[12];
    const float* Aatt   = (const float*)d_in[13];
    const float* Amsg   = (const float*)d_in[14];
    const float* skipv  = (const float*)d_in[15];
    const float* gamma  = (const float*)d_in[16];
    const float* beta   = (const float*)d_in[17];
    float* out = (float*)d_out;

    static cudaStream_t s1 = nullptr;
    static cudaEvent_t evFork = nullptr, evJoin = nullptr;
    if (!s1) {
        cudaStreamCreateWithFlags(&s1, cudaStreamNonBlocking);
        cudaEventCreateWithFlags(&evFork, cudaEventDisableTiming);
        cudaEventCreateWithFlags(&evJoin, cudaEventDisableTiming);
        cudaFuncSetAttribute(k_edge_gemm, cudaFuncAttributeMaxDynamicSharedMemorySize, EG_DYN);
    }

    k_zero<<<(N_ + 255) / 256, 256>>>();                                       // 0
    k_setup<<<1025, 384>>>(Wk, bk, Wq, bq, Wv, bv, pri, Aatt, Amsg, Wa, x,
                           ei, ea, typeId);                                    // 1
    // fork: scan + scatterD run concurrently with the edge GEMM
    cudaEventRecord(evFork, 0);
    cudaStreamWaitEvent(s1, evFork, 0);
    k_scan<<<1, 1024, 0, s1>>>();
    k_scatterD<<<E_ / 256, 256, 0, s1>>>();
    cudaEventRecord(evJoin, s1);
    k_edge_gemm<<<dim3(CAPR / 128, R_), 256, EG_DYN>>>();                      // 3 <- profiled
    cudaStreamWaitEvent(0, evJoin, 0);
    k_aggregate<<<N_ / 8, 256>>>();
    k_out<<<dim3(CAPN / 128, T_), 256>>>(x, ba, skipv, gamma, beta, out);
}

// round 13
// speedup vs baseline: 2.4291x; 1.0539x over previous
#include <cuda_runtime.h>
#include <cuda_bf16.h>
#include <math.h>
#include <stdint.h>

#define N_ 32768
#define E_ 262144
#define C_ 128
#define H_ 8
#define R_ 8
#define T_ 8
#define CAPR 36864
#define CAPN 4608
#define EG_DYN (34816 + 65536)   // B double buffer + kt stage

// ---------------- mma / ldmatrix / cp.async helpers ----------------
__device__ __forceinline__ void mma_bf16(float* c, const uint32_t* a, uint32_t b0, uint32_t b1) {
    asm volatile(
        "mma.sync.aligned.m16n8k16.row.col.f32.bf16.bf16.f32 "
        "{%0,%1,%2,%3}, {%4,%5,%6,%7}, {%8,%9}, {%0,%1,%2,%3};"
        : "+f"(c[0]), "+f"(c[1]), "+f"(c[2]), "+f"(c[3])
        : "r"(a[0]), "r"(a[1]), "r"(a[2]), "r"(a[3]), "r"(b0), "r"(b1));
}
__device__ __forceinline__ uint32_t smem_u32(const void* p) {
    uint32_t a;
    asm("{ .reg .u64 t; cvta.to.shared.u64 t, %1; cvt.u32.u64 %0, t; }" : "=r"(a) : "l"(p));
    return a;
}
__device__ __forceinline__ void ldmx4(uint32_t& r0, uint32_t& r1, uint32_t& r2, uint32_t& r3,
                                      uint32_t addr) {
    asm volatile("ldmatrix.sync.aligned.m8n8.x4.shared.b16 {%0,%1,%2,%3}, [%4];"
                 : "=r"(r0), "=r"(r1), "=r"(r2), "=r"(r3) : "r"(addr));
}
__device__ __forceinline__ void cp16(uint32_t d, const void* s) {
    asm volatile("cp.async.cg.shared.global [%0], [%1], 16;" :: "r"(d), "l"(s));
}
#define CP_COMMIT() asm volatile("cp.async.commit_group;" ::: "memory")
#define CP_WAIT0()  asm volatile("cp.async.wait_group 0;" ::: "memory")

// ---------------- scratch ----------------
__device__ __nv_bfloat16 d_Wbf[R_ * 12 * 2 * 4352];
__device__ __nv_bfloat16 d_Wabf[T_ * 4 * 2 * 4352];
__device__ __nv_bfloat16 d_xhi[N_ * C_];
__device__ __nv_bfloat16 d_xlo[N_ * C_];
__device__ __nv_bfloat16 d_x0hi[N_ * C_];
__device__ __nv_bfloat16 d_x0lo[N_ * C_];
__device__ float d_ball[R_][384];
__device__ int   d_cursor8[R_];
__device__ int   d_ssrc[R_ * CAPR];
__device__ int   d_sdst[R_ * CAPR];
__device__ float d_att[E_ * H_];
__device__ float d_vt[E_ * C_];
__device__ int   d_cnt[N_];
__device__ int   d_rowPtr[N_ + 1];
__device__ int   d_cursor[N_];
__device__ int   d_bydst[E_];
__device__ int   d_cursorN8[T_];
__device__ int   d_snid[T_ * CAPN];

// ---------------- 0: zero ----------------
__global__ void k_zero() {
    int i = blockIdx.x * blockDim.x + threadIdx.x;
    if (i < N_) { d_cnt[i] = 0; d_cursor[i] = 0; }
    if (i < R_) { d_cursor8[i] = 0; d_cursorN8[i] = 0; }
}

__device__ __forceinline__ void store_wbf(int r, int k, int j, float wv) {
    int chunk = j >> 5, n = j & 31;
    __nv_bfloat16 hi = __float2bfloat16_rn(wv);
    __nv_bfloat16 lo = __float2bfloat16_rn(wv - __bfloat162float(hi));
    size_t base = ((size_t)(r * 12 + chunk) * 2) * 4352 + n * 136 + k;
    d_Wbf[base] = hi;
    d_Wbf[base + 4352] = lo;
}

// ---------------- 1a: setup main (weights + edge scatter + x split) ----------------
__global__ void __launch_bounds__(384) k_setup_main(
        const float* __restrict__ Wk, const float* __restrict__ bk,
        const float* __restrict__ Wq, const float* __restrict__ bq,
        const float* __restrict__ Wv, const float* __restrict__ bv,
        const float* __restrict__ pri, const float* __restrict__ Aatt,
        const float* __restrict__ Amsg,
        const float* __restrict__ x,
        const int* __restrict__ ei, const int* __restrict__ ea) {
    int b = blockIdx.x;
    int j = threadIdx.x;
    if (b < 64) {
        int r = b & 7, kc = b >> 3;
        int k0 = kc * 16;
        if (j < 256) {
            bool isK = j < 128;
            int c = j & 127;
            int h = c >> 4, d2 = c & 15;
            const float* M  = (isK ? Aatt : Amsg) + ((r * 8 + h) * 256) + d2;
            const float* Ws = (isK ? Wk : Wv) + r * 16384 + h * 16;
            for (int k = k0; k < k0 + 16; k++) {
                float s = 0.f;
                #pragma unroll
                for (int d = 0; d < 16; d++) s = fmaf(Ws[k * 128 + d], M[d * 16], s);
                store_wbf(r, k, j, s);
            }
            if (kc == 0) {
                const float* bs = (isK ? bk : bv) + r * 128 + h * 16;
                float s = 0.f;
                #pragma unroll
                for (int d = 0; d < 16; d++) s = fmaf(bs[d], M[d * 16], s);
                d_ball[r][j] = s;
            }
        } else {
            int c = j - 256;
            int h = c >> 4;
            float sc = pri[r * 8 + h] * 0.25f;
            for (int k = k0; k < k0 + 16; k++)
                store_wbf(r, k, j, Wq[r * 16384 + k * 128 + c] * sc);
            if (kc == 0) d_ball[r][j] = bq[r * 128 + c] * sc;
        }
    } else if (b < 747) {
        int e = (b - 64) * 384 + j;
        bool act = e < E_;
        int r = 0, srcv = 0, dstv = 0;
        if (act) { r = ea[e]; srcv = ei[e]; dstv = ei[E_ + e]; }
        unsigned amask = __ballot_sync(0xffffffffu, act);
        if (act) {
            unsigned mask = __match_any_sync(amask, r);
            int lane = j & 31;
            int leader = __ffs(mask) - 1;
            int prefix = __popc(mask & ((1u << lane) - 1));
            int base = 0;
            if (lane == leader) base = atomicAdd(&d_cursor8[r], __popc(mask));
            base = __shfl_sync(mask, base, leader);
            int pos = base + prefix;
            if (pos < CAPR) {
                d_ssrc[r * CAPR + pos] = srcv;
                d_sdst[r * CAPR + pos] = dstv;
            }
            atomicAdd(&d_cnt[dstv], 1);
        }
    } else {
        for (int idx = (b - 747) * 384 + j; idx < N_ * C_ / 4; idx += 128 * 384) {
            float4 v = ((const float4*)x)[idx];
            __nv_bfloat162 ha = __floats2bfloat162_rn(v.x, v.y);
            __nv_bfloat162 hb = __floats2bfloat162_rn(v.z, v.w);
            __nv_bfloat162 la = __floats2bfloat162_rn(v.x - __bfloat162float(ha.x),
                                                      v.y - __bfloat162float(ha.y));
            __nv_bfloat162 lb = __floats2bfloat162_rn(v.z - __bfloat162float(hb.x),
                                                      v.w - __bfloat162float(hb.y));
            uint2 H, L;
            H.x = *(uint32_t*)&ha; H.y = *(uint32_t*)&hb;
            L.x = *(uint32_t*)&la; L.y = *(uint32_t*)&lb;
            ((uint2*)d_xhi)[idx] = H;
            ((uint2*)d_xlo)[idx] = L;
        }
    }
}

// ---------------- 1b: setup out-path (node scatter + Wa split), side stream ----------------
__global__ void __launch_bounds__(384) k_setup_out(
        const float* __restrict__ Wa, const int* __restrict__ tid_) {
    int b = blockIdx.x;
    int j = threadIdx.x;
    if (b < 86) {
        int n = b * 384 + j;
        if (n < N_) {
            int pos = atomicAdd(&d_cursorN8[tid_[n]], 1);
            if (pos < CAPN) d_snid[tid_[n] * CAPN + pos] = n;
        }
    } else {
        int b2 = b - 86;
        int t = b2 & 7, kc = b2 >> 3;
        if (j < 128) {
            int n = j, chunk = n >> 5;
            for (int k = kc * 16; k < kc * 16 + 16; k++) {
                float wv = Wa[t * 16384 + k * 128 + n];
                __nv_bfloat16 hi = __float2bfloat16_rn(wv);
                __nv_bfloat16 lo = __float2bfloat16_rn(wv - __bfloat162float(hi));
                size_t base = ((size_t)(t * 4 + chunk) * 2) * 4352 + (n & 31) * 136 + k;
                d_Wabf[base] = hi;
                d_Wabf[base + 4352] = lo;
            }
        }
    }
}

// ---------------- 2: scan ----------------
__global__ void k_scan() {
    __shared__ int sums[1024];
    int tid = threadIdx.x;
    int base = tid * 32;
    int tot = 0;
    for (int i = 0; i < 32; i++) tot += d_cnt[base + i];
    sums[tid] = tot;
    __syncthreads();
    for (int off = 1; off < 1024; off <<= 1) {
        int v = (tid >= off) ? sums[tid - off] : 0;
        __syncthreads();
        sums[tid] += v;
        __syncthreads();
    }
    int run = sums[tid] - tot;
    for (int i = 0; i < 32; i++) { d_rowPtr[base + i] = run; run += d_cnt[base + i]; }
    if (tid == 1023) d_rowPtr[N_] = run;
}

// ---------------- 3: edge GEMM: mma bf16 3-pass, kt staged in smem, 2 CTA/SM ----------------
__global__ void __launch_bounds__(256, 2) k_edge_gemm() {
    extern __shared__ __align__(16) char dyn[];
    int r = blockIdx.y, i = blockIdx.x;
    int tid = threadIdx.x, wid = tid >> 5, lane = tid & 31;
    int g = lane >> 2, t = lane & 3;

    __shared__ int s_cnt, s_gb, s_src[128], s_dst[128];

    if (tid == 0) {
        int cnt = min(d_cursor8[r], CAPR);
        int gb = 0;
        #pragma unroll
        for (int q = 0; q < R_; q++) { int c = min(d_cursor8[q], CAPR); if (q < r) gb += c; }
        s_cnt = cnt; s_gb = gb;
    }
    __syncthreads();
    int cnt = s_cnt;
    if (i * 128 >= cnt) return;
    int count = min(128, cnt - i * 128);
    int gstart = s_gb + i * 128;
    int pstart = r * CAPR + i * 128;

    if (tid < 128) s_src[tid] = (i * 128 + tid < cnt) ? d_ssrc[pstart + tid] : 0;
    else {
        int m = tid - 128;
        s_dst[m] = (i * 128 + m < cnt) ? d_sdst[pstart + m] : 0;
    }

    uint32_t sB_u32 = smem_u32(dyn);
    float* kt_s = (float*)(dyn + 34816);   // [4 chunks][16 j][256 tid]
    {
        const uint4* w0 = (const uint4*)(d_Wbf + (size_t)(r * 12) * 8704);
        for (int idx = tid; idx < 1088; idx += 256) cp16(sB_u32 + idx * 16, w0 + idx);
        CP_COMMIT();
        CP_WAIT0();
    }
    __syncthreads();

    int r0 = wid * 16 + g, r1 = r0 + 8;

    int i8 = lane & 7, q8 = lane >> 3;
    uint32_t rowL0 = (uint32_t)(((q8 >> 1) * 8 + i8) * 272 + (q8 & 1) * 16);

    uint32_t Ah[8][4], Al[8][4];
    {
        const uint32_t* ph0 = (const uint32_t*)d_xhi + (size_t)s_src[r0] * 64;
        const uint32_t* ph1 = (const uint32_t*)d_xhi + (size_t)s_src[r1] * 64;
        const uint32_t* pl0 = (const uint32_t*)d_xlo + (size_t)s_src[r0] * 64;
        const uint32_t* pl1 = (const uint32_t*)d_xlo + (size_t)s_src[r1] * 64;
        #pragma unroll
        for (int ks = 0; ks < 8; ks++) {
            Ah[ks][0] = ph0[ks * 8 + t];     Ah[ks][1] = ph1[ks * 8 + t];
            Ah[ks][2] = ph0[ks * 8 + t + 4]; Ah[ks][3] = ph1[ks * 8 + t + 4];
            Al[ks][0] = pl0[ks * 8 + t];     Al[ks][1] = pl1[ks * 8 + t];
            Al[ks][2] = pl0[ks * 8 + t + 4]; Al[ks][3] = pl1[ks * 8 + t + 4];
        }
    }

    const float* __restrict__ bb = d_ball[r];
    bool v0 = r0 < count, v1 = r1 < count;
    int slot0 = gstart + r0, slot1 = gstart + r1;

    #pragma unroll
    for (int c = 0; c < 12; c++) {
        int buf = c & 1;
        uint32_t bufbase = sB_u32 + buf * 17408;
        if (c < 11) {
            const uint4* wn = (const uint4*)(d_Wbf + (size_t)(r * 12 + c + 1) * 8704);
            uint32_t dstb = sB_u32 + (buf ^ 1) * 17408;
            for (int idx = tid; idx < 1088; idx += 256) cp16(dstb + idx * 16, wn + idx);
            CP_COMMIT();
        }
        if (c == 8) {
            const uint32_t* ph0 = (const uint32_t*)d_xhi + (size_t)s_dst[r0] * 64;
            const uint32_t* ph1 = (const uint32_t*)d_xhi + (size_t)s_dst[r1] * 64;
            const uint32_t* pl0 = (const uint32_t*)d_xlo + (size_t)s_dst[r0] * 64;
            const uint32_t* pl1 = (const uint32_t*)d_xlo + (size_t)s_dst[r1] * 64;
            #pragma unroll
            for (int ks = 0; ks < 8; ks++) {
                Ah[ks][0] = ph0[ks * 8 + t];     Ah[ks][1] = ph1[ks * 8 + t];
                Ah[ks][2] = ph0[ks * 8 + t + 4]; Ah[ks][3] = ph1[ks * 8 + t + 4];
                Al[ks][0] = pl0[ks * 8 + t];     Al[ks][1] = pl1[ks * 8 + t];
                Al[ks][2] = pl0[ks * 8 + t + 4]; Al[ks][3] = pl1[ks * 8 + t + 4];
            }
        }

        float acc[16];
        #pragma unroll
        for (int j = 0; j < 16; j++) acc[j] = 0.f;

        #pragma unroll
        for (int ks = 0; ks < 8; ks++) {
            uint32_t kof = 32u * ks;
            uint32_t h0[4], h1[4], l0[4], l1[4];
            ldmx4(h0[0], h0[1], h0[2], h0[3], bufbase + rowL0 + kof);
            ldmx4(h1[0], h1[1], h1[2], h1[3], bufbase + rowL0 + 4352 + kof);
            ldmx4(l0[0], l0[1], l0[2], l0[3], bufbase + rowL0 + 8704 + kof);
            ldmx4(l1[0], l1[1], l1[2], l1[3], bufbase + rowL0 + 13056 + kof);
            mma_bf16(&acc[0],  Ah[ks], h0[0], h0[1]);
            mma_bf16(&acc[0],  Al[ks], h0[0], h0[1]);
            mma_bf16(&acc[0],  Ah[ks], l0[0], l0[1]);
            mma_bf16(&acc[4],  Ah[ks], h0[2], h0[3]);
            mma_bf16(&acc[4],  Al[ks], h0[2], h0[3]);
            mma_bf16(&acc[4],  Ah[ks], l0[2], l0[3]);
            mma_bf16(&acc[8],  Ah[ks], h1[0], h1[1]);
            mma_bf16(&acc[8],  Al[ks], h1[0], h1[1]);
            mma_bf16(&acc[8],  Ah[ks], l1[0], l1[1]);
            mma_bf16(&acc[12], Ah[ks], h1[2], h1[3]);
            mma_bf16(&acc[12], Al[ks], h1[2], h1[3]);
            mma_bf16(&acc[12], Ah[ks], l1[2], l1[3]);
        }

        #pragma unroll
        for (int nt = 0; nt < 4; nt++) {
            float bc0 = bb[c * 32 + nt * 8 + 2 * t];
            float bc1 = bb[c * 32 + nt * 8 + 2 * t + 1];
            acc[nt * 4 + 0] += bc0; acc[nt * 4 + 1] += bc1;
            acc[nt * 4 + 2] += bc0; acc[nt * 4 + 3] += bc1;
        }

        if (c < 4) {
            #pragma unroll
            for (int j = 0; j < 16; j++) kt_s[(c * 16 + j) * 256 + tid] = acc[j];
        } else if (c < 8) {
            int cb = (c - 4) * 32;
            #pragma unroll
            for (int nt = 0; nt < 4; nt++) {
                int col = cb + nt * 8 + 2 * t;
                if (v0) __stcs((float2*)&d_vt[(size_t)slot0 * C_ + col],
                               make_float2(acc[nt * 4 + 0], acc[nt * 4 + 1]));
                if (v1) __stcs((float2*)&d_vt[(size_t)slot1 * C_ + col],
                               make_float2(acc[nt * 4 + 2], acc[nt * 4 + 3]));
            }
        } else {
            int cc = c - 8;
            int h0c = cc * 2;
            const float* kb = kt_s + cc * 16 * 256 + tid;
            float p00 = acc[0] * kb[0 * 256] + acc[1] * kb[1 * 256]
                      + acc[4] * kb[4 * 256] + acc[5] * kb[5 * 256];
            float p10 = acc[2] * kb[2 * 256] + acc[3] * kb[3 * 256]
                      + acc[6] * kb[6 * 256] + acc[7] * kb[7 * 256];
            float p01 = acc[8] * kb[8 * 256] + acc[9] * kb[9 * 256]
                      + acc[12] * kb[12 * 256] + acc[13] * kb[13 * 256];
            float p11 = acc[10] * kb[10 * 256] + acc[11] * kb[11 * 256]
                      + acc[14] * kb[14 * 256] + acc[15] * kb[15 * 256];
            p00 += __shfl_xor_sync(0xffffffffu, p00, 1);
            p00 += __shfl_xor_sync(0xffffffffu, p00, 2);
            p10 += __shfl_xor_sync(0xffffffffu, p10, 1);
            p10 += __shfl_xor_sync(0xffffffffu, p10, 2);
            p01 += __shfl_xor_sync(0xffffffffu, p01, 1);
            p01 += __shfl_xor_sync(0xffffffffu, p01, 2);
            p11 += __shfl_xor_sync(0xffffffffu, p11, 1);
            p11 += __shfl_xor_sync(0xffffffffu, p11, 2);
            if (t == 0) {
                if (v0) {
                    d_att[(size_t)slot0 * 8 + h0c] = p00;
                    d_att[(size_t)slot0 * 8 + h0c + 1] = p01;
                }
                if (v1) {
                    d_att[(size_t)slot1 * 8 + h0c] = p10;
                    d_att[(size_t)slot1 * 8 + h0c + 1] = p11;
                }
            }
        }

        if (c < 11) CP_WAIT0();
        __syncthreads();
    }
}

// ---------------- 4: scatter compact slots by dst ----------------
__global__ void k_scatterD() {
    __shared__ int sb[R_ + 1];
    if (threadIdx.x < R_) sb[threadIdx.x + 1] = min(d_cursor8[threadIdx.x], CAPR);
    if (threadIdx.x == 0) sb[0] = 0;
    __syncthreads();
    if (threadIdx.x == 0) {
        #pragma unroll
        for (int q = 1; q <= R_; q++) sb[q] += sb[q - 1];
    }
    __syncthreads();
    int c = blockIdx.x * blockDim.x + threadIdx.x;
    if (c >= sb[R_]) return;
    int r = 0;
    #pragma unroll
    for (int q = 1; q < R_; q++) r += (c >= sb[q]);
    int padded = r * CAPR + (c - sb[r]);
    int dst = d_sdst[padded];
    int pos = d_rowPtr[dst] + atomicAdd(&d_cursor[dst], 1);
    d_bydst[pos] = c;
}

// ---------------- 5: aggregate (no-max softmax; writes x0 as bf16 hi/lo) ----------------
__global__ void k_aggregate() {
    int warp = threadIdx.x >> 5;
    int lane = threadIdx.x & 31;
    int n = blockIdx.x * (blockDim.x >> 5) + warp;
    if (n >= N_) return;
    int s = d_rowPtr[n], eEnd = d_rowPtr[n + 1];
    int deg = eEnd - s;
    if (deg == 0) {
        #pragma unroll
        for (int j = 0; j < 4; j++) {
            d_x0hi[n * C_ + lane + 32 * j] = __float2bfloat16_rn(0.f);
            d_x0lo[n * C_ + lane + 32 * j] = __float2bfloat16_rn(0.f);
        }
        return;
    }
    int slot = lane >> 3, h = lane & 7;
    // softmax is shift-invariant; att magnitudes are O(10) -> exp safely in range
    float den = 0.f;
    for (int b = s; b < eEnd; b += 4) {
        int idx = b + slot;
        if (idx < eEnd) den += expf(d_att[d_bydst[idx] * 8 + h]);
    }
    den += __shfl_xor_sync(0xffffffffu, den, 8);
    den += __shfl_xor_sync(0xffffffffu, den, 16);
    int hb = lane >> 4;
    float rj[4];
    #pragma unroll
    for (int j = 0; j < 4; j++)
        rj[j] = 1.f / __shfl_sync(0xffffffffu, den, hb + 2 * j);
    float acc[4] = {0.f, 0.f, 0.f, 0.f};
    for (int idx = s; idx < eEnd; idx++) {
        int e = d_bydst[idx];
        const float* ar = &d_att[e * 8];
        const float* vr = &d_vt[(size_t)e * C_];
        #pragma unroll
        for (int j = 0; j < 4; j++) {
            float w = expf(ar[hb + 2 * j]) * rj[j];
            acc[j] = fmaf(w, __ldcs(&vr[lane + 32 * j]), acc[j]);
        }
    }
    float inv = 1.f / (float)deg;
    #pragma unroll
    for (int j = 0; j < 4; j++) {
        float val = acc[j] * inv;
        __nv_bfloat16 h2 = __float2bfloat16_rn(val);
        __nv_bfloat16 l2 = __float2bfloat16_rn(val - __bfloat162float(h2));
        d_x0hi[n * C_ + lane + 32 * j] = h2;
        d_x0lo[n * C_ + lane + 32 * j] = l2;
    }
}

// ---------------- 6: out GEMM (mma + ldmatrix + cp.async) + residual + LN ----------------
__global__ void __launch_bounds__(256, 1) k_out(const float* __restrict__ x,
                                                const float* __restrict__ ba,
                                                const float* __restrict__ skipv,
                                                const float* __restrict__ gamma,
                                                const float* __restrict__ beta,
                                                float* __restrict__ out) {
    int t = blockIdx.y, i = blockIdx.x;
    int tid = threadIdx.x, wid = tid >> 5, lane = tid & 31;
    int g = lane >> 2, tq = lane & 3;

    int cntT = min(d_cursorN8[t], CAPN);
    if (i * 128 >= cntT) return;
    int count = min(128, cntT - i * 128);
    int start = t * CAPN + i * 128;

    __shared__ int s_nid[128];
    __shared__ __align__(16) uint4 sB[2][1088];

    if (tid < 128) s_nid[tid] = (i * 128 + tid < cntT) ? d_snid[start + tid] : 0;
    uint32_t sB_u32 = smem_u32(sB);
    {
        const uint4* w0 = (const uint4*)(d_Wabf + (size_t)(t * 4) * 8704);
        for (int idx = tid; idx < 1088; idx += 256) cp16(sB_u32 + idx * 16, w0 + idx);
        CP_COMMIT();
        CP_WAIT0();
    }
    __syncthreads();

    int r0 = wid * 16 + g, r1 = r0 + 8;
    int nid0 = s_nid[r0], nid1 = s_nid[r1];

    int i8 = lane & 7, q8 = lane >> 3;
    uint32_t rowL0 = (uint32_t)(((q8 >> 1) * 8 + i8) * 272 + (q8 & 1) * 16);

    uint32_t Ah[8][4], Al[8][4];
    {
        const uint32_t* ph0 = (const uint32_t*)d_x0hi + (size_t)nid0 * 64;
        const uint32_t* ph1 = (const uint32_t*)d_x0hi + (size_t)nid1 * 64;
        const uint32_t* pl0 = (const uint32_t*)d_x0lo + (size_t)nid0 * 64;
        const uint32_t* pl1 = (const uint32_t*)d_x0lo + (size_t)nid1 * 64;
        #pragma unroll
        for (int ks = 0; ks < 8; ks++) {
            Ah[ks][0] = ph0[ks * 8 + tq];     Ah[ks][1] = ph1[ks * 8 + tq];
            Ah[ks][2] = ph0[ks * 8 + tq + 4]; Ah[ks][3] = ph1[ks * 8 + tq + 4];
            Al[ks][0] = pl0[ks * 8 + tq];     Al[ks][1] = pl1[ks * 8 + tq];
            Al[ks][2] = pl0[ks * 8 + tq + 4]; Al[ks][3] = pl1[ks * 8 + tq + 4];
        }
    }

    float vout[2][32];

    #pragma unroll
    for (int c = 0; c < 4; c++) {
        int buf = c & 1;
        uint32_t bufbase = sB_u32 + buf * 17408;
        if (c < 3) {
            const uint4* wn = (const uint4*)(d_Wabf + (size_t)(t * 4 + c + 1) * 8704);
            uint32_t dstb = sB_u32 + (buf ^ 1) * 17408;
            for (int idx = tid; idx < 1088; idx += 256) cp16(dstb + idx * 16, wn + idx);
            CP_COMMIT();
        }
        float acc[16];
        #pragma unroll
        for (int j = 0; j < 16; j++) acc[j] = 0.f;
        #pragma unroll
        for (int ks = 0; ks < 8; ks++) {
            uint32_t kof = 32u * ks;
            uint32_t h0[4], h1[4], l0[4], l1[4];
            ldmx4(h0[0], h0[1], h0[2], h0[3], bufbase + rowL0 + kof);
            ldmx4(h1[0], h1[1], h1[2], h1[3], bufbase + rowL0 + 4352 + kof);
            ldmx4(l0[0], l0[1], l0[2], l0[3], bufbase + rowL0 + 8704 + kof);
            ldmx4(l1[0], l1[1], l1[2], l1[3], bufbase + rowL0 + 13056 + kof);
            mma_bf16(&acc[0],  Ah[ks], h0[0], h0[1]);
            mma_bf16(&acc[0],  Al[ks], h0[0], h0[1]);
            mma_bf16(&acc[0],  Ah[ks], l0[0], l0[1]);
            mma_bf16(&acc[4],  Ah[ks], h0[2], h0[3]);
            mma_bf16(&acc[4],  Al[ks], h0[2], h0[3]);
            mma_bf16(&acc[4],  Ah[ks], l0[2], l0[3]);
            mma_bf16(&acc[8],  Ah[ks], h1[0], h1[1]);
            mma_bf16(&acc[8],  Al[ks], h1[0], h1[1]);
            mma_bf16(&acc[8],  Ah[ks], l1[0], l1[1]);
            mma_bf16(&acc[12], Ah[ks], h1[2], h1[3]);
            mma_bf16(&acc[12], Al[ks], h1[2], h1[3]);
            mma_bf16(&acc[12], Ah[ks], l1[2], l1[3]);
        }
        #pragma unroll
        for (int nt = 0; nt < 4; nt++) {
            int col = c * 32 + nt * 8 + 2 * tq;
            float bc0 = ba[t * 128 + col];
            float bc1 = ba[t * 128 + col + 1];
            vout[0][c * 8 + nt * 2 + 0] = acc[nt * 4 + 0] + bc0;
            vout[0][c * 8 + nt * 2 + 1] = acc[nt * 4 + 1] + bc1;
            vout[1][c * 8 + nt * 2 + 0] = acc[nt * 4 + 2] + bc0;
            vout[1][c * 8 + nt * 2 + 1] = acc[nt * 4 + 3] + bc1;
        }
        if (c < 3) CP_WAIT0();
        __syncthreads();
    }

    float alpha = 1.f / (1.f + expf(-skipv[t]));
    float onema = 1.f - alpha;

    #pragma unroll
    for (int rr = 0; rr < 2; rr++) {
        int row = (rr == 0) ? r0 : r1;
        int nid = (rr == 0) ? nid0 : nid1;
        bool valid = row < count;
        float s1 = 0.f, s2 = 0.f;
        float v[32];
        #pragma unroll
        for (int c = 0; c < 4; c++)
            #pragma unroll
            for (int nt = 0; nt < 4; nt++) {
                int col = c * 32 + nt * 8 + 2 * tq;
                float2 rx = *(const float2*)(x + (size_t)nid * C_ + col);
                float v0 = alpha * vout[rr][c * 8 + nt * 2 + 0] + onema * rx.x;
                float v1 = alpha * vout[rr][c * 8 + nt * 2 + 1] + onema * rx.y;
                v[c * 8 + nt * 2 + 0] = v0;
                v[c * 8 + nt * 2 + 1] = v1;
                s1 += v0 + v1;
                s2 = fmaf(v0, v0, s2);
                s2 = fmaf(v1, v1, s2);
            }
        s1 += __shfl_xor_sync(0xffffffffu, s1, 1);
        s1 += __shfl_xor_sync(0xffffffffu, s1, 2);
        s2 += __shfl_xor_sync(0xffffffffu, s2, 1);
        s2 += __shfl_xor_sync(0xffffffffu, s2, 2);
        float mu = s1 * (1.f / 128.f);
        float var = s2 * (1.f / 128.f) - mu * mu;
        float rstd = rsqrtf(var + 1e-5f);
        if (valid) {
            #pragma unroll
            for (int c = 0; c < 4; c++)
                #pragma unroll
                for (int nt = 0; nt < 4; nt++) {
                    int col = c * 32 + nt * 8 + 2 * tq;
                    float2 o;
                    o.x = (v[c * 8 + nt * 2 + 0] - mu) * rstd * gamma[t * 128 + col]
                        + beta[t * 128 + col];
                    o.y = (v[c * 8 + nt * 2 + 1] - mu) * rstd * gamma[t * 128 + col + 1]
                        + beta[t * 128 + col + 1];
                    *(float2*)&out[(size_t)nid * C_ + col] = o;
                }
        }
    }
}

// ---------------- launch ----------------
extern "C" void kernel_launch(void* const* d_in, const int* in_sizes, int n_in,
                              void* d_out, int out_size) {
    const float* x      = (const float*)d_in[0];
    const int*   typeId = (const int*)d_in[1];
    const int*   ei     = (const int*)d_in[2];
    const int*   ea     = (const int*)d_in[3];
    const float* Wk     = (const float*)d_in[4];
    const float* bk     = (const float*)d_in[5];
    const float* Wq     = (const float*)d_in[6];
    const float* bq     = (const float*)d_in[7];
    const float* Wv     = (const float*)d_in[8];
    const float* bv     = (const float*)d_in[9];
    const float* Wa     = (const float*)d_in[10];
    const float* ba     = (const float*)d_in[11];
    const float* pri    = (const float*)d_in[12];
    const float* Aatt   = (const float*)d_in[13];
    const float* Amsg   = (const float*)d_in[14];
    const float* skipv  = (const float*)d_in[15];
    const float* gamma  = (const float*)d_in[16];
    const float* beta   = (const float*)d_in[17];
    float* out = (float*)d_out;

    static cudaStream_t s1 = nullptr;
    static cudaEvent_t ev0 = nullptr, ev1 = nullptr, evJoin = nullptr;
    if (!s1) {
        cudaStreamCreateWithFlags(&s1, cudaStreamNonBlocking);
        cudaEventCreateWithFlags(&ev0, cudaEventDisableTiming);
        cudaEventCreateWithFlags(&ev1, cudaEventDisableTiming);
        cudaEventCreateWithFlags(&evJoin, cudaEventDisableTiming);
        cudaFuncSetAttribute(k_edge_gemm, cudaFuncAttributeMaxDynamicSharedMemorySize, EG_DYN);
    }

    k_zero<<<(N_ + 255) / 256, 256>>>();
    cudaEventRecord(ev0, 0);
    cudaStreamWaitEvent(s1, ev0, 0);
    k_setup_out<<<150, 384, 0, s1>>>(Wa, typeId);        // side: node scatter + Wa split
    k_setup_main<<<875, 384>>>(Wk, bk, Wq, bq, Wv, bv, pri, Aatt, Amsg, x, ei, ea);
    cudaEventRecord(ev1, 0);
    cudaStreamWaitEvent(s1, ev1, 0);
    k_scan<<<1, 1024, 0, s1>>>();
    k_scatterD<<<E_ / 256, 256, 0, s1>>>();
    cudaEventRecord(evJoin, s1);
    k_edge_gemm<<<dim3(CAPR / 128, R_), 256, EG_DYN>>>();
    cudaStreamWaitEvent(0, evJoin, 0);
    k_aggregate<<<N_ / 8, 256>>>();
    k_out<<<dim3(CAPN / 128, T_), 256>>>(x, ba, skipv, gamma, beta, out);
}